// round 1
// baseline (speedup 1.0000x reference)
#include <cuda_runtime.h>
#include <math.h>

#define Bb_ 2
#define Ss_ 2048
#define Hh_ 2048
#define NH_ 16
#define NKV_ 4
#define HD_ 128
#define MTOK (Bb_ * Ss_)   // 4096 tokens

// Scratch (allocation-free rule: __device__ globals)
__device__ float g_q[(size_t)MTOK * NH_ * HD_];    // [token][nh*128]
__device__ float g_k[(size_t)MTOK * NKV_ * HD_];   // [token][4*128]
__device__ float g_v[(size_t)MTOK * NKV_ * HD_];
__device__ float g_attn[(size_t)MTOK * NH_ * HD_];

// ---------------------------------------------------------------------------
// C[M,N] = A[M,K] @ B[N,K]^T   (both row-major, K-contiguous)
// 128x128 block tile, BK=16, 256 threads, 8x8 per thread
// ---------------------------------------------------------------------------
__global__ __launch_bounds__(256) void sgemm_nt(
    const float* __restrict__ A, const float* __restrict__ Bm,
    float* __restrict__ C, int M, int N, int K) {
  __shared__ float As[16][132];
  __shared__ float Bs[16][132];
  const int tid = threadIdx.x;
  const int tx = tid & 15, ty = tid >> 4;
  const int bm = blockIdx.y, bn = blockIdx.x;
  const float* Ab = A + (size_t)bm * 128 * K;
  const float* Bp = Bm + (size_t)bn * 128 * K;
  const int lrow = tid >> 2;        // 0..63
  const int lk = (tid & 3) * 4;     // 0,4,8,12

  float acc[8][8];
#pragma unroll
  for (int i = 0; i < 8; i++)
#pragma unroll
    for (int j = 0; j < 8; j++) acc[i][j] = 0.f;

  for (int k0 = 0; k0 < K; k0 += 16) {
#pragma unroll
    for (int i = 0; i < 2; i++) {
      int r = lrow + i * 64;
      float4 a4 = *(const float4*)(Ab + (size_t)r * K + k0 + lk);
      As[lk + 0][r] = a4.x; As[lk + 1][r] = a4.y;
      As[lk + 2][r] = a4.z; As[lk + 3][r] = a4.w;
      float4 b4 = *(const float4*)(Bp + (size_t)r * K + k0 + lk);
      Bs[lk + 0][r] = b4.x; Bs[lk + 1][r] = b4.y;
      Bs[lk + 2][r] = b4.z; Bs[lk + 3][r] = b4.w;
    }
    __syncthreads();
#pragma unroll
    for (int kk = 0; kk < 16; kk++) {
      float ar[8], br[8];
      *(float4*)(ar)     = *(const float4*)&As[kk][ty * 8];
      *(float4*)(ar + 4) = *(const float4*)&As[kk][ty * 8 + 4];
      *(float4*)(br)     = *(const float4*)&Bs[kk][tx * 8];
      *(float4*)(br + 4) = *(const float4*)&Bs[kk][tx * 8 + 4];
#pragma unroll
      for (int i = 0; i < 8; i++)
#pragma unroll
        for (int j = 0; j < 8; j++) acc[i][j] = fmaf(ar[i], br[j], acc[i][j]);
    }
    __syncthreads();
  }

#pragma unroll
  for (int i = 0; i < 8; i++) {
    float* cp = C + (size_t)(bm * 128 + ty * 8 + i) * N + bn * 128 + tx * 8;
    float4 c0 = {acc[i][0], acc[i][1], acc[i][2], acc[i][3]};
    float4 c1 = {acc[i][4], acc[i][5], acc[i][6], acc[i][7]};
    *(float4*)cp = c0;
    *(float4*)(cp + 4) = c1;
  }
}

// ---------------------------------------------------------------------------
// Fused RoPE + RMSNorm, one warp per (token, head), in-place on [token][nh*128]
// ---------------------------------------------------------------------------
__global__ __launch_bounds__(256) void rope_rms(float* __restrict__ x,
                                                const float* __restrict__ w,
                                                int nh, int total_warps) {
  int gw = (blockIdx.x * blockDim.x + threadIdx.x) >> 5;
  if (gw >= total_warps) return;
  int lane = threadIdx.x & 31;
  int token = gw / nh;
  int s = token & (Ss_ - 1);
  float* p = x + (size_t)gw * HD_;

  const float neg_l2theta_over_half = -13.287712379549449f / 64.f;  // -log2(1e4)/64
  float vals[4];
  float ss = 0.f;
#pragma unroll
  for (int hh = 0; hh < 2; hh++) {
    int d = lane + hh * 32;  // 0..63
    float x1 = p[d];
    float x2 = p[d + 64];
    float invf = exp2f((float)d * neg_l2theta_over_half);
    float ang = (float)s * invf;
    float c, sn;
    sincosf(ang, &sn, &c);
    float o1 = x1 * c - x2 * sn;
    float o2 = x2 * c + x1 * sn;
    vals[hh * 2] = o1;
    vals[hh * 2 + 1] = o2;
    ss += o1 * o1 + o2 * o2;
  }
#pragma unroll
  for (int o = 16; o >= 1; o >>= 1) ss += __shfl_xor_sync(0xffffffffu, ss, o);
  float r = rsqrtf(ss * (1.f / 128.f) + 1e-6f);
#pragma unroll
  for (int hh = 0; hh < 2; hh++) {
    int d = lane + hh * 32;
    p[d]      = vals[hh * 2]     * r * w[d];
    p[d + 64] = vals[hh * 2 + 1] * r * w[d + 64];
  }
}

// ---------------------------------------------------------------------------
// Flash attention, causal, GQA (q head h uses kv head h/4)
// 64 q-rows x 64 kv-cols tiles, 256 threads; fp32 everywhere.
// smem: Qs[64][132], Kt[128][68] (transposed), Vs[64][132], Ps[64][68]
// ---------------------------------------------------------------------------
#define FA_SMEM ((64 * 132 + 128 * 68 + 64 * 132 + 64 * 68) * 4)

__global__ __launch_bounds__(256) void flash_attn() {
  extern __shared__ float sm[];
  float* Qs = sm;                    // 64*132
  float* Kt = Qs + 64 * 132;         // 128*68
  float* Vs = Kt + 128 * 68;         // 64*132
  float* Ps = Vs + 64 * 132;         // 64*68

  const int qt = blockIdx.x, h = blockIdx.y, b = blockIdx.z;
  const int kvh = h >> 2;
  const int tid = threadIdx.x, tx = tid & 15, ty = tid >> 4;
  const int qbase = qt * 64;
  const float scale = 0.08838834764831845f;  // 1/sqrt(128)

  // Load Q tile (scaled)
#pragma unroll
  for (int i = 0; i < 8; i++) {
    int e = tid + i * 256;
    int r = e >> 5, c4 = (e & 31) * 4;
    float4 v = *(const float4*)(g_q +
        ((size_t)(b * Ss_ + qbase + r) * (NH_ * HD_) + h * HD_ + c4));
    v.x *= scale; v.y *= scale; v.z *= scale; v.w *= scale;
    *(float4*)&Qs[r * 132 + c4] = v;
  }

  float acc[4][8];
#pragma unroll
  for (int i = 0; i < 4; i++)
#pragma unroll
    for (int j = 0; j < 8; j++) acc[i][j] = 0.f;
  float m[4] = {-INFINITY, -INFINITY, -INFINITY, -INFINITY};
  float l[4] = {0.f, 0.f, 0.f, 0.f};

  for (int kt = 0; kt <= qt; kt++) {
    __syncthreads();  // previous iter's Ps/Vs reads done
    // K, transposed into smem [d][kvcol]; lanes cover rows -> conflict-free STS
#pragma unroll
    for (int i = 0; i < 8; i++) {
      int e = i * 256 + tid;
      int r = e & 63;
      int c4 = (e >> 6) * 4;
      float4 v = *(const float4*)(g_k +
          ((size_t)(b * Ss_ + kt * 64 + r) * (NKV_ * HD_) + kvh * HD_ + c4));
      Kt[(c4 + 0) * 68 + r] = v.x;
      Kt[(c4 + 1) * 68 + r] = v.y;
      Kt[(c4 + 2) * 68 + r] = v.z;
      Kt[(c4 + 3) * 68 + r] = v.w;
    }
    // V row-major, coalesced
#pragma unroll
    for (int i = 0; i < 8; i++) {
      int e = i * 256 + tid;
      int r = e >> 5, c4 = (e & 31) * 4;
      float4 v = *(const float4*)(g_v +
          ((size_t)(b * Ss_ + kt * 64 + r) * (NKV_ * HD_) + kvh * HD_ + c4));
      *(float4*)&Vs[r * 132 + c4] = v;
    }
    __syncthreads();

    // S = Q @ K^T  (thread: rows ty*4..+3, cols tx*4..+3)
    float s4[4][4];
#pragma unroll
    for (int i = 0; i < 4; i++)
#pragma unroll
      for (int j = 0; j < 4; j++) s4[i][j] = 0.f;

#pragma unroll 8
    for (int kk = 0; kk < 128; kk++) {
      float4 kc = *(const float4*)&Kt[kk * 68 + tx * 4];
#pragma unroll
      for (int i = 0; i < 4; i++) {
        float qv = Qs[(ty * 4 + i) * 132 + kk];
        s4[i][0] = fmaf(qv, kc.x, s4[i][0]);
        s4[i][1] = fmaf(qv, kc.y, s4[i][1]);
        s4[i][2] = fmaf(qv, kc.z, s4[i][2]);
        s4[i][3] = fmaf(qv, kc.w, s4[i][3]);
      }
    }

    if (kt == qt) {
#pragma unroll
      for (int i = 0; i < 4; i++)
#pragma unroll
        for (int j = 0; j < 4; j++)
          if (tx * 4 + j > ty * 4 + i) s4[i][j] = -1e30f;
    }

    // online softmax (row groups of 16 threads share a row set)
#pragma unroll
    for (int i = 0; i < 4; i++) {
      float rm = fmaxf(fmaxf(s4[i][0], s4[i][1]), fmaxf(s4[i][2], s4[i][3]));
#pragma unroll
      for (int o = 8; o >= 1; o >>= 1)
        rm = fmaxf(rm, __shfl_xor_sync(0xffffffffu, rm, o));
      float mn = fmaxf(m[i], rm);
      float al = __expf(m[i] - mn);
      float rs = 0.f;
#pragma unroll
      for (int j = 0; j < 4; j++) {
        float p = __expf(s4[i][j] - mn);
        Ps[(ty * 4 + i) * 68 + tx * 4 + j] = p;
        rs += p;
      }
#pragma unroll
      for (int o = 8; o >= 1; o >>= 1)
        rs += __shfl_xor_sync(0xffffffffu, rs, o);
      l[i] = l[i] * al + rs;
      m[i] = mn;
#pragma unroll
      for (int u = 0; u < 8; u++) acc[i][u] *= al;
    }
    __syncthreads();

    // O += P @ V   (thread: rows ty*4..+3, cols tx*8..+7)
#pragma unroll 4
    for (int c = 0; c < 64; c++) {
      float4 v0 = *(const float4*)&Vs[c * 132 + tx * 8];
      float4 v1 = *(const float4*)&Vs[c * 132 + tx * 8 + 4];
#pragma unroll
      for (int i = 0; i < 4; i++) {
        float p = Ps[(ty * 4 + i) * 68 + c];
        acc[i][0] = fmaf(p, v0.x, acc[i][0]);
        acc[i][1] = fmaf(p, v0.y, acc[i][1]);
        acc[i][2] = fmaf(p, v0.z, acc[i][2]);
        acc[i][3] = fmaf(p, v0.w, acc[i][3]);
        acc[i][4] = fmaf(p, v1.x, acc[i][4]);
        acc[i][5] = fmaf(p, v1.y, acc[i][5]);
        acc[i][6] = fmaf(p, v1.z, acc[i][6]);
        acc[i][7] = fmaf(p, v1.w, acc[i][7]);
      }
    }
  }

  // epilogue: O /= l, write to g_attn [token][h*128 + d]
#pragma unroll
  for (int i = 0; i < 4; i++) {
    float inv = 1.0f / l[i];
    size_t token = (size_t)(b * Ss_ + qbase + ty * 4 + i);
    float* op = g_attn + token * (NH_ * HD_) + h * HD_ + tx * 8;
    float4 o0 = {acc[i][0] * inv, acc[i][1] * inv, acc[i][2] * inv, acc[i][3] * inv};
    float4 o1 = {acc[i][4] * inv, acc[i][5] * inv, acc[i][6] * inv, acc[i][7] * inv};
    *(float4*)op = o0;
    *(float4*)(op + 4) = o1;
  }
}

// ---------------------------------------------------------------------------
extern "C" void kernel_launch(void* const* d_in, const int* in_sizes, int n_in,
                              void* d_out, int out_size) {
  const float* hs = (const float*)d_in[0];
  const float* wq = (const float*)d_in[1];
  const float* wk = (const float*)d_in[2];
  const float* wv = (const float*)d_in[3];
  const float* wo = (const float*)d_in[4];
  const float* qw = (const float*)d_in[5];
  const float* kw = (const float*)d_in[6];
  float* out = (float*)d_out;

  void *pq, *pk, *pv, *pa;
  cudaGetSymbolAddress(&pq, g_q);
  cudaGetSymbolAddress(&pk, g_k);
  cudaGetSymbolAddress(&pv, g_v);
  cudaGetSymbolAddress(&pa, g_attn);

  dim3 blk(256);
  // QKV projections
  sgemm_nt<<<dim3(16, 32), blk>>>(hs, wq, (float*)pq, MTOK, NH_ * HD_, Hh_);
  sgemm_nt<<<dim3(4, 32), blk>>>(hs, wk, (float*)pk, MTOK, NKV_ * HD_, Hh_);
  sgemm_nt<<<dim3(4, 32), blk>>>(hs, wv, (float*)pv, MTOK, NKV_ * HD_, Hh_);

  // RoPE + RMSNorm (in place)
  rope_rms<<<(MTOK * NH_) / 8, 256>>>((float*)pq, qw, NH_, MTOK * NH_);
  rope_rms<<<(MTOK * NKV_) / 8, 256>>>((float*)pk, kw, NKV_, MTOK * NKV_);

  // Flash attention
  cudaFuncSetAttribute(flash_attn, cudaFuncAttributeMaxDynamicSharedMemorySize,
                       FA_SMEM);
  flash_attn<<<dim3(Ss_ / 64, NH_, Bb_), blk, FA_SMEM>>>();

  // Output projection -> d_out
  sgemm_nt<<<dim3(16, 32), blk>>>((const float*)pa, wo, out, MTOK, Hh_, Hh_);
}

// round 3
// speedup vs baseline: 1.5390x; 1.5390x over previous
#include <cuda_runtime.h>
#include <cuda_bf16.h>
#include <math.h>
#include <stdint.h>

#define Bb_ 2
#define Ss_ 2048
#define Hh_ 2048
#define NH_ 16
#define NKV_ 4
#define HD_ 128
#define MTOK (Bb_ * Ss_)   // 4096 tokens

// Scratch (allocation-free rule: __device__ globals)
__device__ float g_q[(size_t)MTOK * NH_ * HD_];
__device__ float g_k[(size_t)MTOK * NKV_ * HD_];
__device__ float g_v[(size_t)MTOK * NKV_ * HD_];
__device__ float g_attn[(size_t)MTOK * NH_ * HD_];

// ============================ helpers =======================================
__device__ __forceinline__ uint32_t smem_u32(const void* p) {
  uint32_t a;
  asm("{ .reg .u64 t; cvta.to.shared.u64 t, %1; cvt.u32.u64 %0, t; }"
      : "=r"(a) : "l"(p));
  return a;
}

__device__ __forceinline__ void ldsm4(uint32_t addr, uint32_t r[4]) {
  asm volatile("ldmatrix.sync.aligned.m8n8.x4.shared.b16 {%0,%1,%2,%3}, [%4];"
               : "=r"(r[0]), "=r"(r[1]), "=r"(r[2]), "=r"(r[3]) : "r"(addr));
}

__device__ __forceinline__ void mma16816(float c[4], const uint32_t a[4],
                                         const uint32_t b[2]) {
  asm volatile(
      "mma.sync.aligned.m16n8k16.row.col.f32.bf16.bf16.f32 "
      "{%0,%1,%2,%3}, {%4,%5,%6,%7}, {%8,%9}, {%0,%1,%2,%3};"
      : "+f"(c[0]), "+f"(c[1]), "+f"(c[2]), "+f"(c[3])
      : "r"(a[0]), "r"(a[1]), "r"(a[2]), "r"(a[3]), "r"(b[0]), "r"(b[1]));
}

// split fp32 -> bf16 hi + bf16 lo (residual), packed pairs
__device__ __forceinline__ void cvt_split4(float4 v, uint32_t h[2],
                                           uint32_t l[2]) {
  __nv_bfloat162 h0 = __float22bfloat162_rn(make_float2(v.x, v.y));
  __nv_bfloat162 h1 = __float22bfloat162_rn(make_float2(v.z, v.w));
  float2 r0 = make_float2(v.x - __bfloat162float(h0.x),
                          v.y - __bfloat162float(h0.y));
  float2 r1 = make_float2(v.z - __bfloat162float(h1.x),
                          v.w - __bfloat162float(h1.y));
  __nv_bfloat162 l0 = __float22bfloat162_rn(r0);
  __nv_bfloat162 l1 = __float22bfloat162_rn(r1);
  h[0] = *reinterpret_cast<uint32_t*>(&h0);
  h[1] = *reinterpret_cast<uint32_t*>(&h1);
  l[0] = *reinterpret_cast<uint32_t*>(&l0);
  l[1] = *reinterpret_cast<uint32_t*>(&l1);
}

// ============================ bf16-split GEMM ===============================
// C[M,N] = A[M,K] @ B[N,K]^T, fp32 in/out.
// 128x128 CTA tile, BK=32, 8 warps (warp tile 32x64), double-buffered.
// smem rows padded to 80B (40 bf16) -> conflict-free ldmatrix (5 coprime 8).
#define MAT_B (128 * 80)        // one 128x32 bf16 matrix (padded) = 10240 B
#define STAGE_B (4 * MAT_B)     // Ahi, Alo, Bhi, Blo = 40960 B
#define GSMEM (2 * STAGE_B)     // 81920 B

__global__ __launch_bounds__(256) void gemm_bf16s(
    const float* __restrict__ A, const float* __restrict__ B,
    float* __restrict__ C, const float* __restrict__ B1, float* __restrict__ C1,
    int N, int K) {
  extern __shared__ char sm[];
  if (blockIdx.z == 1) { B = B1; C = C1; }
  const int tid = threadIdx.x, wid = tid >> 5, lane = tid & 31;
  const int bn = blockIdx.x, bm = blockIdx.y;
  const int wm = wid & 3, wn = wid >> 2;   // 4 m-warps x 2 n-warps
  const float* Ab = A + (size_t)(bm * 128) * K;
  const float* Bp = B + (size_t)(bn * 128) * K;
  const uint32_t smb = smem_u32(sm);

  const int lrow = tid >> 1, lhalf = tid & 1;   // loader mapping
  const int i4 = lane >> 3, j8 = lane & 7;      // ldmatrix mapping

  float ac[2][8][4];
#pragma unroll
  for (int mt = 0; mt < 2; mt++)
#pragma unroll
    for (int nt = 0; nt < 8; nt++)
#pragma unroll
      for (int q = 0; q < 4; q++) ac[mt][nt][q] = 0.f;

  float4 pa[4], pb[4];

  auto fetch = [&](int k0) {
    const float* a = Ab + (size_t)lrow * K + k0 + lhalf * 16;
    const float* b = Bp + (size_t)lrow * K + k0 + lhalf * 16;
#pragma unroll
    for (int q = 0; q < 4; q++) {
      pa[q] = *(const float4*)(a + q * 4);
      pb[q] = *(const float4*)(b + q * 4);
    }
  };

  auto store_stage = [&](int s) {
    char* st = sm + s * STAGE_B;
    const uint32_t off = lrow * 80 + lhalf * 32;
#pragma unroll
    for (int q = 0; q < 4; q++) {
      uint32_t h[2], l[2];
      cvt_split4(pa[q], h, l);
      *(uint2*)(st + off + q * 8) = make_uint2(h[0], h[1]);
      *(uint2*)(st + MAT_B + off + q * 8) = make_uint2(l[0], l[1]);
      cvt_split4(pb[q], h, l);
      *(uint2*)(st + 2 * MAT_B + off + q * 8) = make_uint2(h[0], h[1]);
      *(uint2*)(st + 3 * MAT_B + off + q * 8) = make_uint2(l[0], l[1]);
    }
  };

  auto compute = [&](int s) {
    const uint32_t base = smb + s * STAGE_B;
#pragma unroll
    for (int ks = 0; ks < 2; ks++) {
      uint32_t af[2][2][4];  // [split][mtile][4]
      uint32_t bf[2][8][2];  // [split][ntile][2]
#pragma unroll
      for (int sp = 0; sp < 2; sp++)
#pragma unroll
        for (int mt = 0; mt < 2; mt++) {
          uint32_t addr = base + sp * MAT_B +
                          (uint32_t)(wm * 32 + mt * 16 + (i4 & 1) * 8 + j8) * 80 +
                          (uint32_t)((i4 >> 1) * 8 + ks * 16) * 2;
          ldsm4(addr, af[sp][mt]);
        }
#pragma unroll
      for (int sp = 0; sp < 2; sp++)
#pragma unroll
        for (int p = 0; p < 4; p++) {
          uint32_t r[4];
          uint32_t addr = base + (2 + sp) * MAT_B +
                          (uint32_t)(wn * 64 + p * 16 + (i4 >> 1) * 8 + j8) * 80 +
                          (uint32_t)((i4 & 1) * 8 + ks * 16) * 2;
          ldsm4(addr, r);
          bf[sp][2 * p][0] = r[0]; bf[sp][2 * p][1] = r[1];
          bf[sp][2 * p + 1][0] = r[2]; bf[sp][2 * p + 1][1] = r[3];
        }
#pragma unroll
      for (int mt = 0; mt < 2; mt++)
#pragma unroll
        for (int nt = 0; nt < 8; nt++) {
          mma16816(ac[mt][nt], af[0][mt], bf[0][nt]);  // hi*hi
          mma16816(ac[mt][nt], af[0][mt], bf[1][nt]);  // hi*lo
          mma16816(ac[mt][nt], af[1][mt], bf[0][nt]);  // lo*hi
        }
    }
  };

  fetch(0);
  store_stage(0);
  __syncthreads();

  const int KS = K >> 5;
  for (int it = 0; it < KS; it++) {
    const int s = it & 1;
    if (it + 1 < KS) fetch((it + 1) * 32);
    compute(s);
    if (it + 1 < KS) {
      __syncthreads();
      store_stage(s ^ 1);
      __syncthreads();
    }
  }

  // epilogue: regs -> gmem
#pragma unroll
  for (int mt = 0; mt < 2; mt++)
#pragma unroll
    for (int nt = 0; nt < 8; nt++) {
      int row = bm * 128 + wm * 32 + mt * 16 + (lane >> 2);
      int col = bn * 128 + wn * 64 + nt * 8 + (lane & 3) * 2;
      float* c0 = C + (size_t)row * N + col;
      *(float2*)c0 = make_float2(ac[mt][nt][0], ac[mt][nt][1]);
      *(float2*)(c0 + 8 * (size_t)N) = make_float2(ac[mt][nt][2], ac[mt][nt][3]);
    }
}

// ============================ RoPE + RMSNorm ================================
__global__ __launch_bounds__(256) void rope_rms(float* __restrict__ x,
                                                const float* __restrict__ w,
                                                int nh, int total_warps) {
  int gw = (blockIdx.x * blockDim.x + threadIdx.x) >> 5;
  if (gw >= total_warps) return;
  int lane = threadIdx.x & 31;
  int token = gw / nh;
  int s = token & (Ss_ - 1);
  float* p = x + (size_t)gw * HD_;

  const float neg_l2theta_over_half = -13.287712379549449f / 64.f;
  float vals[4];
  float ss = 0.f;
#pragma unroll
  for (int hh = 0; hh < 2; hh++) {
    int d = lane + hh * 32;
    float x1 = p[d];
    float x2 = p[d + 64];
    float invf = exp2f((float)d * neg_l2theta_over_half);
    float ang = (float)s * invf;
    float c, sn;
    sincosf(ang, &sn, &c);
    float o1 = x1 * c - x2 * sn;
    float o2 = x2 * c + x1 * sn;
    vals[hh * 2] = o1;
    vals[hh * 2 + 1] = o2;
    ss += o1 * o1 + o2 * o2;
  }
#pragma unroll
  for (int o = 16; o >= 1; o >>= 1) ss += __shfl_xor_sync(0xffffffffu, ss, o);
  float r = rsqrtf(ss * (1.f / 128.f) + 1e-6f);
#pragma unroll
  for (int hh = 0; hh < 2; hh++) {
    int d = lane + hh * 32;
    p[d]      = vals[hh * 2]     * r * w[d];
    p[d + 64] = vals[hh * 2 + 1] * r * w[d + 64];
  }
}

// ============================ Flash attention (fp32) ========================
#define FA_SMEM ((64 * 132 + 128 * 68 + 64 * 132 + 64 * 68) * 4)

__global__ __launch_bounds__(256) void flash_attn() {
  extern __shared__ float smf[];
  float* Qs = smf;
  float* Kt = Qs + 64 * 132;
  float* Vs = Kt + 128 * 68;
  float* Ps = Vs + 64 * 132;

  const int qt = blockIdx.x, h = blockIdx.y, b = blockIdx.z;
  const int kvh = h >> 2;
  const int tid = threadIdx.x, tx = tid & 15, ty = tid >> 4;
  const int qbase = qt * 64;
  const float scale = 0.08838834764831845f;

#pragma unroll
  for (int i = 0; i < 8; i++) {
    int e = tid + i * 256;
    int r = e >> 5, c4 = (e & 31) * 4;
    float4 v = *(const float4*)(g_q +
        ((size_t)(b * Ss_ + qbase + r) * (NH_ * HD_) + h * HD_ + c4));
    v.x *= scale; v.y *= scale; v.z *= scale; v.w *= scale;
    *(float4*)&Qs[r * 132 + c4] = v;
  }

  float acc[4][8];
#pragma unroll
  for (int i = 0; i < 4; i++)
#pragma unroll
    for (int j = 0; j < 8; j++) acc[i][j] = 0.f;
  float m[4] = {-INFINITY, -INFINITY, -INFINITY, -INFINITY};
  float l[4] = {0.f, 0.f, 0.f, 0.f};

  for (int kt = 0; kt <= qt; kt++) {
    __syncthreads();
#pragma unroll
    for (int i = 0; i < 8; i++) {
      int e = i * 256 + tid;
      int r = e & 63;
      int c4 = (e >> 6) * 4;
      float4 v = *(const float4*)(g_k +
          ((size_t)(b * Ss_ + kt * 64 + r) * (NKV_ * HD_) + kvh * HD_ + c4));
      Kt[(c4 + 0) * 68 + r] = v.x;
      Kt[(c4 + 1) * 68 + r] = v.y;
      Kt[(c4 + 2) * 68 + r] = v.z;
      Kt[(c4 + 3) * 68 + r] = v.w;
    }
#pragma unroll
    for (int i = 0; i < 8; i++) {
      int e = i * 256 + tid;
      int r = e >> 5, c4 = (e & 31) * 4;
      float4 v = *(const float4*)(g_v +
          ((size_t)(b * Ss_ + kt * 64 + r) * (NKV_ * HD_) + kvh * HD_ + c4));
      *(float4*)&Vs[r * 132 + c4] = v;
    }
    __syncthreads();

    float s4[4][4];
#pragma unroll
    for (int i = 0; i < 4; i++)
#pragma unroll
      for (int j = 0; j < 4; j++) s4[i][j] = 0.f;

#pragma unroll 8
    for (int kk = 0; kk < 128; kk++) {
      float4 kc = *(const float4*)&Kt[kk * 68 + tx * 4];
#pragma unroll
      for (int i = 0; i < 4; i++) {
        float qv = Qs[(ty * 4 + i) * 132 + kk];
        s4[i][0] = fmaf(qv, kc.x, s4[i][0]);
        s4[i][1] = fmaf(qv, kc.y, s4[i][1]);
        s4[i][2] = fmaf(qv, kc.z, s4[i][2]);
        s4[i][3] = fmaf(qv, kc.w, s4[i][3]);
      }
    }

    if (kt == qt) {
#pragma unroll
      for (int i = 0; i < 4; i++)
#pragma unroll
        for (int j = 0; j < 4; j++)
          if (tx * 4 + j > ty * 4 + i) s4[i][j] = -1e30f;
    }

#pragma unroll
    for (int i = 0; i < 4; i++) {
      float rm = fmaxf(fmaxf(s4[i][0], s4[i][1]), fmaxf(s4[i][2], s4[i][3]));
#pragma unroll
      for (int o = 8; o >= 1; o >>= 1)
        rm = fmaxf(rm, __shfl_xor_sync(0xffffffffu, rm, o));
      float mn = fmaxf(m[i], rm);
      float al = __expf(m[i] - mn);
      float rs = 0.f;
#pragma unroll
      for (int j = 0; j < 4; j++) {
        float p = __expf(s4[i][j] - mn);
        Ps[(ty * 4 + i) * 68 + tx * 4 + j] = p;
        rs += p;
      }
#pragma unroll
      for (int o = 8; o >= 1; o >>= 1)
        rs += __shfl_xor_sync(0xffffffffu, rs, o);
      l[i] = l[i] * al + rs;
      m[i] = mn;
#pragma unroll
      for (int u = 0; u < 8; u++) acc[i][u] *= al;
    }
    __syncthreads();

#pragma unroll 4
    for (int c = 0; c < 64; c++) {
      float4 v0 = *(const float4*)&Vs[c * 132 + tx * 8];
      float4 v1 = *(const float4*)&Vs[c * 132 + tx * 8 + 4];
#pragma unroll
      for (int i = 0; i < 4; i++) {
        float p = Ps[(ty * 4 + i) * 68 + c];
        acc[i][0] = fmaf(p, v0.x, acc[i][0]);
        acc[i][1] = fmaf(p, v0.y, acc[i][1]);
        acc[i][2] = fmaf(p, v0.z, acc[i][2]);
        acc[i][3] = fmaf(p, v0.w, acc[i][3]);
        acc[i][4] = fmaf(p, v1.x, acc[i][4]);
        acc[i][5] = fmaf(p, v1.y, acc[i][5]);
        acc[i][6] = fmaf(p, v1.z, acc[i][6]);
        acc[i][7] = fmaf(p, v1.w, acc[i][7]);
      }
    }
  }

#pragma unroll
  for (int i = 0; i < 4; i++) {
    float inv = 1.0f / l[i];
    size_t token = (size_t)(b * Ss_ + qbase + ty * 4 + i);
    float* op = g_attn + token * (NH_ * HD_) + h * HD_ + tx * 8;
    float4 o0 = {acc[i][0] * inv, acc[i][1] * inv, acc[i][2] * inv, acc[i][3] * inv};
    float4 o1 = {acc[i][4] * inv, acc[i][5] * inv, acc[i][6] * inv, acc[i][7] * inv};
    *(float4*)op = o0;
    *(float4*)(op + 4) = o1;
  }
}

// ============================ launch ========================================
extern "C" void kernel_launch(void* const* d_in, const int* in_sizes, int n_in,
                              void* d_out, int out_size) {
  const float* hs = (const float*)d_in[0];
  const float* wq = (const float*)d_in[1];
  const float* wk = (const float*)d_in[2];
  const float* wv = (const float*)d_in[3];
  const float* wo = (const float*)d_in[4];
  const float* qw = (const float*)d_in[5];
  const float* kw = (const float*)d_in[6];
  float* out = (float*)d_out;

  void *pq, *pk, *pv, *pa;
  cudaGetSymbolAddress(&pq, g_q);
  cudaGetSymbolAddress(&pk, g_k);
  cudaGetSymbolAddress(&pv, g_v);
  cudaGetSymbolAddress(&pa, g_attn);

  cudaFuncSetAttribute(gemm_bf16s, cudaFuncAttributeMaxDynamicSharedMemorySize,
                       GSMEM);
  cudaFuncSetAttribute(flash_attn, cudaFuncAttributeMaxDynamicSharedMemorySize,
                       FA_SMEM);

  // Q projection
  gemm_bf16s<<<dim3(NH_ * HD_ / 128, MTOK / 128, 1), 256, GSMEM>>>(
      hs, wq, (float*)pq, nullptr, nullptr, NH_ * HD_, Hh_);
  // K and V projections merged (blockIdx.z selects)
  gemm_bf16s<<<dim3(NKV_ * HD_ / 128, MTOK / 128, 2), 256, GSMEM>>>(
      hs, wk, (float*)pk, wv, (float*)pv, NKV_ * HD_, Hh_);

  rope_rms<<<(MTOK * NH_) / 8, 256>>>((float*)pq, qw, NH_, MTOK * NH_);
  rope_rms<<<(MTOK * NKV_) / 8, 256>>>((float*)pk, kw, NKV_, MTOK * NKV_);

  flash_attn<<<dim3(Ss_ / 64, NH_, Bb_), 256, FA_SMEM>>>();

  // Output projection -> d_out
  gemm_bf16s<<<dim3(Hh_ / 128, MTOK / 128, 1), 256, GSMEM>>>(
      (const float*)pa, wo, out, nullptr, nullptr, Hh_, Hh_);
}

// round 4
// speedup vs baseline: 2.3993x; 1.5590x over previous
#include <cuda_runtime.h>
#include <cuda_bf16.h>
#include <math.h>
#include <stdint.h>

#define Bb_ 2
#define Ss_ 2048
#define Hh_ 2048
#define NH_ 16
#define NKV_ 4
#define HD_ 128
#define MTOK (Bb_ * Ss_)   // 4096 tokens

// Scratch (allocation-free rule: __device__ globals)
__device__ float g_q[(size_t)MTOK * NH_ * HD_];
__device__ float g_k[(size_t)MTOK * NKV_ * HD_];
__device__ float g_v[(size_t)MTOK * NKV_ * HD_];
__device__ float g_attn[(size_t)MTOK * NH_ * HD_];

// ============================ helpers =======================================
__device__ __forceinline__ uint32_t smem_u32(const void* p) {
  uint32_t a;
  asm("{ .reg .u64 t; cvta.to.shared.u64 t, %1; cvt.u32.u64 %0, t; }"
      : "=r"(a) : "l"(p));
  return a;
}

__device__ __forceinline__ void ldsm4(uint32_t addr, uint32_t r[4]) {
  asm volatile("ldmatrix.sync.aligned.m8n8.x4.shared.b16 {%0,%1,%2,%3}, [%4];"
               : "=r"(r[0]), "=r"(r[1]), "=r"(r[2]), "=r"(r[3]) : "r"(addr));
}
__device__ __forceinline__ void ldsm4t(uint32_t addr, uint32_t r[4]) {
  asm volatile(
      "ldmatrix.sync.aligned.m8n8.x4.trans.shared.b16 {%0,%1,%2,%3}, [%4];"
      : "=r"(r[0]), "=r"(r[1]), "=r"(r[2]), "=r"(r[3]) : "r"(addr));
}

__device__ __forceinline__ void mma16816(float c[4], const uint32_t a[4],
                                         const uint32_t b[2]) {
  asm volatile(
      "mma.sync.aligned.m16n8k16.row.col.f32.bf16.bf16.f32 "
      "{%0,%1,%2,%3}, {%4,%5,%6,%7}, {%8,%9}, {%0,%1,%2,%3};"
      : "+f"(c[0]), "+f"(c[1]), "+f"(c[2]), "+f"(c[3])
      : "r"(a[0]), "r"(a[1]), "r"(a[2]), "r"(a[3]), "r"(b[0]), "r"(b[1]));
}
__device__ __forceinline__ void mma16816b(float c[4], const uint32_t a[4],
                                          uint32_t b0, uint32_t b1) {
  asm volatile(
      "mma.sync.aligned.m16n8k16.row.col.f32.bf16.bf16.f32 "
      "{%0,%1,%2,%3}, {%4,%5,%6,%7}, {%8,%9}, {%0,%1,%2,%3};"
      : "+f"(c[0]), "+f"(c[1]), "+f"(c[2]), "+f"(c[3])
      : "r"(a[0]), "r"(a[1]), "r"(a[2]), "r"(a[3]), "r"(b0), "r"(b1));
}

// split fp32 -> bf16 hi + bf16 lo (residual), packed pairs
__device__ __forceinline__ void cvt_split4(float4 v, uint32_t h[2],
                                           uint32_t l[2]) {
  __nv_bfloat162 h0 = __float22bfloat162_rn(make_float2(v.x, v.y));
  __nv_bfloat162 h1 = __float22bfloat162_rn(make_float2(v.z, v.w));
  float2 r0 = make_float2(v.x - __bfloat162float(h0.x),
                          v.y - __bfloat162float(h0.y));
  float2 r1 = make_float2(v.z - __bfloat162float(h1.x),
                          v.w - __bfloat162float(h1.y));
  __nv_bfloat162 l0 = __float22bfloat162_rn(r0);
  __nv_bfloat162 l1 = __float22bfloat162_rn(r1);
  h[0] = *reinterpret_cast<uint32_t*>(&h0);
  h[1] = *reinterpret_cast<uint32_t*>(&h1);
  l[0] = *reinterpret_cast<uint32_t*>(&l0);
  l[1] = *reinterpret_cast<uint32_t*>(&l1);
}

__device__ __forceinline__ void pack_split2(float x, float y, uint32_t& h,
                                            uint32_t& l) {
  __nv_bfloat162 hb = __float22bfloat162_rn(make_float2(x, y));
  float2 hf = __bfloat1622float2(hb);
  __nv_bfloat162 lb = __float22bfloat162_rn(make_float2(x - hf.x, y - hf.y));
  h = *reinterpret_cast<uint32_t*>(&hb);
  l = *reinterpret_cast<uint32_t*>(&lb);
}

// ============================ bf16-split GEMM ===============================
#define MAT_B (128 * 80)
#define STAGE_B (4 * MAT_B)
#define GSMEM (2 * STAGE_B)

__global__ __launch_bounds__(256) void gemm_bf16s(
    const float* __restrict__ A, const float* __restrict__ B,
    float* __restrict__ C, const float* __restrict__ B1, float* __restrict__ C1,
    int N, int K) {
  extern __shared__ char sm[];
  if (blockIdx.z == 1) { B = B1; C = C1; }
  const int tid = threadIdx.x, wid = tid >> 5, lane = tid & 31;
  const int bn = blockIdx.x, bm = blockIdx.y;
  const int wm = wid & 3, wn = wid >> 2;
  const float* Ab = A + (size_t)(bm * 128) * K;
  const float* Bp = B + (size_t)(bn * 128) * K;
  const uint32_t smb = smem_u32(sm);

  const int lrow = tid >> 1, lhalf = tid & 1;
  const int i4 = lane >> 3, j8 = lane & 7;

  float ac[2][8][4];
#pragma unroll
  for (int mt = 0; mt < 2; mt++)
#pragma unroll
    for (int nt = 0; nt < 8; nt++)
#pragma unroll
      for (int q = 0; q < 4; q++) ac[mt][nt][q] = 0.f;

  float4 pa[4], pb[4];

  auto fetch = [&](int k0) {
    const float* a = Ab + (size_t)lrow * K + k0 + lhalf * 16;
    const float* b = Bp + (size_t)lrow * K + k0 + lhalf * 16;
#pragma unroll
    for (int q = 0; q < 4; q++) {
      pa[q] = *(const float4*)(a + q * 4);
      pb[q] = *(const float4*)(b + q * 4);
    }
  };

  auto store_stage = [&](int s) {
    char* st = sm + s * STAGE_B;
    const uint32_t off = lrow * 80 + lhalf * 32;
#pragma unroll
    for (int q = 0; q < 4; q++) {
      uint32_t h[2], l[2];
      cvt_split4(pa[q], h, l);
      *(uint2*)(st + off + q * 8) = make_uint2(h[0], h[1]);
      *(uint2*)(st + MAT_B + off + q * 8) = make_uint2(l[0], l[1]);
      cvt_split4(pb[q], h, l);
      *(uint2*)(st + 2 * MAT_B + off + q * 8) = make_uint2(h[0], h[1]);
      *(uint2*)(st + 3 * MAT_B + off + q * 8) = make_uint2(l[0], l[1]);
    }
  };

  auto compute = [&](int s) {
    const uint32_t base = smb + s * STAGE_B;
#pragma unroll
    for (int ks = 0; ks < 2; ks++) {
      uint32_t af[2][2][4];
      uint32_t bf[2][8][2];
#pragma unroll
      for (int sp = 0; sp < 2; sp++)
#pragma unroll
        for (int mt = 0; mt < 2; mt++) {
          uint32_t addr = base + sp * MAT_B +
                          (uint32_t)(wm * 32 + mt * 16 + (i4 & 1) * 8 + j8) * 80 +
                          (uint32_t)((i4 >> 1) * 8 + ks * 16) * 2;
          ldsm4(addr, af[sp][mt]);
        }
#pragma unroll
      for (int sp = 0; sp < 2; sp++)
#pragma unroll
        for (int p = 0; p < 4; p++) {
          uint32_t r[4];
          uint32_t addr = base + (2 + sp) * MAT_B +
                          (uint32_t)(wn * 64 + p * 16 + (i4 >> 1) * 8 + j8) * 80 +
                          (uint32_t)((i4 & 1) * 8 + ks * 16) * 2;
          ldsm4(addr, r);
          bf[sp][2 * p][0] = r[0]; bf[sp][2 * p][1] = r[1];
          bf[sp][2 * p + 1][0] = r[2]; bf[sp][2 * p + 1][1] = r[3];
        }
#pragma unroll
      for (int mt = 0; mt < 2; mt++)
#pragma unroll
        for (int nt = 0; nt < 8; nt++) {
          mma16816(ac[mt][nt], af[0][mt], bf[0][nt]);
          mma16816(ac[mt][nt], af[0][mt], bf[1][nt]);
          mma16816(ac[mt][nt], af[1][mt], bf[0][nt]);
        }
    }
  };

  fetch(0);
  store_stage(0);
  __syncthreads();

  const int KS = K >> 5;
  for (int it = 0; it < KS; it++) {
    const int s = it & 1;
    if (it + 1 < KS) fetch((it + 1) * 32);
    compute(s);
    if (it + 1 < KS) {
      __syncthreads();
      store_stage(s ^ 1);
      __syncthreads();
    }
  }

#pragma unroll
  for (int mt = 0; mt < 2; mt++)
#pragma unroll
    for (int nt = 0; nt < 8; nt++) {
      int row = bm * 128 + wm * 32 + mt * 16 + (lane >> 2);
      int col = bn * 128 + wn * 64 + nt * 8 + (lane & 3) * 2;
      float* c0 = C + (size_t)row * N + col;
      *(float2*)c0 = make_float2(ac[mt][nt][0], ac[mt][nt][1]);
      *(float2*)(c0 + 8 * (size_t)N) = make_float2(ac[mt][nt][2], ac[mt][nt][3]);
    }
}

// ============================ RoPE + RMSNorm ================================
__global__ __launch_bounds__(256) void rope_rms(float* __restrict__ x,
                                                const float* __restrict__ w,
                                                int nh, int total_warps) {
  int gw = (blockIdx.x * blockDim.x + threadIdx.x) >> 5;
  if (gw >= total_warps) return;
  int lane = threadIdx.x & 31;
  int token = gw / nh;
  int s = token & (Ss_ - 1);
  float* p = x + (size_t)gw * HD_;

  const float neg_l2theta_over_half = -13.287712379549449f / 64.f;
  float vals[4];
  float ss = 0.f;
#pragma unroll
  for (int hh = 0; hh < 2; hh++) {
    int d = lane + hh * 32;
    float x1 = p[d];
    float x2 = p[d + 64];
    float invf = exp2f((float)d * neg_l2theta_over_half);
    float ang = (float)s * invf;
    float c, sn;
    sincosf(ang, &sn, &c);
    float o1 = x1 * c - x2 * sn;
    float o2 = x2 * c + x1 * sn;
    vals[hh * 2] = o1;
    vals[hh * 2 + 1] = o2;
    ss += o1 * o1 + o2 * o2;
  }
#pragma unroll
  for (int o = 16; o >= 1; o >>= 1) ss += __shfl_xor_sync(0xffffffffu, ss, o);
  float r = rsqrtf(ss * (1.f / 128.f) + 1e-6f);
#pragma unroll
  for (int hh = 0; hh < 2; hh++) {
    int d = lane + hh * 32;
    p[d]      = vals[hh * 2]     * r * w[d];
    p[d + 64] = vals[hh * 2 + 1] * r * w[d + 64];
  }
}

// ======================= Flash attention (bf16-split mma) ===================
// CTA: 128 q rows (8 warps x 16 rows), kv in 64-row chunks.
// smem rows padded to 272B pitch -> conflict-free ldmatrix.
#define FPITCH 272
#define FQHI 0
#define FQLO (128 * FPITCH)                 // 34816
#define FKHI (2 * 128 * FPITCH)             // 69632
#define FKLO (FKHI + 64 * FPITCH)           // 87040
#define FVHI (FKHI + 2 * 64 * FPITCH)       // 104448
#define FVLO (FVHI + 64 * FPITCH)           // 121856
#define FA2_SMEM (FVLO + 64 * FPITCH)       // 139264

__global__ __launch_bounds__(256) void flash_attn_mma() {
  extern __shared__ char sm[];
  const uint32_t smb = smem_u32(sm);
  const int qt = blockIdx.x, h = blockIdx.y, b = blockIdx.z;
  const int kvh = h >> 2;
  const int tid = threadIdx.x, wid = tid >> 5, lane = tid & 31;
  const int i4 = lane >> 3, j8 = lane & 7;
  const int qb = qt * 128;
  const int qwb = qb + wid * 16;             // warp's first q row (global)
  const float scale = 0.08838834764831845f;  // 1/sqrt(128)

  // ---- prologue: Q -> smem (scaled, split) ----
  {
    const int row = tid >> 1, half = tid & 1;  // 2 threads/row, 64 floats each
    const float* src = g_q + ((size_t)(b * Ss_ + qb + row) * (NH_ * HD_) +
                              h * HD_ + half * 64);
    char* dh = sm + FQHI + row * FPITCH + half * 128;
    char* dl = sm + FQLO + row * FPITCH + half * 128;
#pragma unroll
    for (int q = 0; q < 16; q++) {
      float4 v = *(const float4*)(src + q * 4);
      v.x *= scale; v.y *= scale; v.z *= scale; v.w *= scale;
      uint32_t hh[2], ll[2];
      cvt_split4(v, hh, ll);
      *(uint2*)(dh + q * 8) = make_uint2(hh[0], hh[1]);
      *(uint2*)(dl + q * 8) = make_uint2(ll[0], ll[1]);
    }
  }

  float oa[16][4];
#pragma unroll
  for (int nt = 0; nt < 16; nt++)
#pragma unroll
    for (int q = 0; q < 4; q++) oa[nt][q] = 0.f;
  float m0 = -INFINITY, m1 = -INFINITY, l0 = 0.f, l1 = 0.f;

  // per-thread ldmatrix base offsets
  const uint32_t qa_off = (uint32_t)(wid * 16 + (i4 & 1) * 8 + j8) * FPITCH +
                          (uint32_t)((i4 >> 1) * 8) * 2;
  const uint32_t kb_row = (uint32_t)((i4 >> 1) * 8 + j8);
  const uint32_t kb_koff = (uint32_t)((i4 & 1) * 8) * 2;
  const uint32_t v_kv = (uint32_t)((i4 & 1) * 8 + j8);   // i4=lane>>3: g&1 -> kv+8
  const uint32_t v_d = (uint32_t)((i4 >> 1) * 8);

  // KV loader mapping: 4 threads/row, 32 floats each
  const int krow = tid >> 2, kqtr = tid & 3;

  const int nkv = 2 * qt + 2;
  for (int kvi = 0; kvi < nkv; kvi++) {
    const int kvb = kvi * 64;
    // gmem -> regs
    float4 rk[8], rv[8];
    {
      const size_t gbase = (size_t)(b * Ss_ + kvb + krow) * (NKV_ * HD_) +
                           kvh * HD_ + kqtr * 32;
#pragma unroll
      for (int q = 0; q < 8; q++) {
        rk[q] = *(const float4*)(g_k + gbase + q * 4);
        rv[q] = *(const float4*)(g_v + gbase + q * 4);
      }
    }
    __syncthreads();  // previous iter done reading K/V smem
    {
      char* khd = sm + FKHI + krow * FPITCH + kqtr * 64;
      char* kld = sm + FKLO + krow * FPITCH + kqtr * 64;
      char* vhd = sm + FVHI + krow * FPITCH + kqtr * 64;
      char* vld = sm + FVLO + krow * FPITCH + kqtr * 64;
#pragma unroll
      for (int q = 0; q < 8; q++) {
        uint32_t hh[2], ll[2];
        cvt_split4(rk[q], hh, ll);
        *(uint2*)(khd + q * 8) = make_uint2(hh[0], hh[1]);
        *(uint2*)(kld + q * 8) = make_uint2(ll[0], ll[1]);
        cvt_split4(rv[q], hh, ll);
        *(uint2*)(vhd + q * 8) = make_uint2(hh[0], hh[1]);
        *(uint2*)(vld + q * 8) = make_uint2(ll[0], ll[1]);
      }
    }
    __syncthreads();  // K/V smem ready

    if (kvb > qwb + 15) continue;  // warp fully masked

    // ---- S = Q @ K^T ----
    float s4[8][4];
#pragma unroll
    for (int j = 0; j < 8; j++)
#pragma unroll
      for (int q = 0; q < 4; q++) s4[j][q] = 0.f;

#pragma unroll
    for (int kt = 0; kt < 8; kt++) {
      uint32_t aH[4], aL[4];
      ldsm4(smb + FQHI + qa_off + kt * 32, aH);
      ldsm4(smb + FQLO + qa_off + kt * 32, aL);
#pragma unroll
      for (int p = 0; p < 4; p++) {
        uint32_t rH[4], rL[4];
        uint32_t ka = (uint32_t)(p * 16) * FPITCH + kb_row * FPITCH + kb_koff +
                      (uint32_t)(kt * 32);
        ldsm4(smb + FKHI + ka, rH);
        ldsm4(smb + FKLO + ka, rL);
        mma16816b(s4[2 * p],     aH, rH[0], rH[1]);
        mma16816b(s4[2 * p],     aH, rL[0], rL[1]);
        mma16816b(s4[2 * p],     aL, rH[0], rH[1]);
        mma16816b(s4[2 * p + 1], aH, rH[2], rH[3]);
        mma16816b(s4[2 * p + 1], aH, rL[2], rL[3]);
        mma16816b(s4[2 * p + 1], aL, rH[2], rH[3]);
      }
    }

    // ---- causal mask (diagonal chunks only) ----
    if (kvb + 63 > qwb) {
      const int qr0 = qwb + (lane >> 2), qr1 = qr0 + 8;
      const int kc0 = kvb + (lane & 3) * 2;
#pragma unroll
      for (int j = 0; j < 8; j++) {
        int kv0 = kc0 + j * 8, kv1 = kv0 + 1;
        if (kv0 > qr0) s4[j][0] = -1e30f;
        if (kv1 > qr0) s4[j][1] = -1e30f;
        if (kv0 > qr1) s4[j][2] = -1e30f;
        if (kv1 > qr1) s4[j][3] = -1e30f;
      }
    }

    // ---- online softmax (quad reductions) ----
    float mx0 = -1e30f, mx1 = -1e30f;
#pragma unroll
    for (int j = 0; j < 8; j++) {
      mx0 = fmaxf(mx0, fmaxf(s4[j][0], s4[j][1]));
      mx1 = fmaxf(mx1, fmaxf(s4[j][2], s4[j][3]));
    }
    mx0 = fmaxf(mx0, __shfl_xor_sync(0xffffffffu, mx0, 1));
    mx0 = fmaxf(mx0, __shfl_xor_sync(0xffffffffu, mx0, 2));
    mx1 = fmaxf(mx1, __shfl_xor_sync(0xffffffffu, mx1, 1));
    mx1 = fmaxf(mx1, __shfl_xor_sync(0xffffffffu, mx1, 2));
    float mn0 = fmaxf(m0, mx0), mn1 = fmaxf(m1, mx1);
    float al0 = __expf(m0 - mn0), al1 = __expf(m1 - mn1);
    m0 = mn0; m1 = mn1;
    float sum0 = 0.f, sum1 = 0.f;
#pragma unroll
    for (int j = 0; j < 8; j++) {
      s4[j][0] = __expf(s4[j][0] - mn0);
      s4[j][1] = __expf(s4[j][1] - mn0);
      s4[j][2] = __expf(s4[j][2] - mn1);
      s4[j][3] = __expf(s4[j][3] - mn1);
      sum0 += s4[j][0] + s4[j][1];
      sum1 += s4[j][2] + s4[j][3];
    }
    sum0 += __shfl_xor_sync(0xffffffffu, sum0, 1);
    sum0 += __shfl_xor_sync(0xffffffffu, sum0, 2);
    sum1 += __shfl_xor_sync(0xffffffffu, sum1, 1);
    sum1 += __shfl_xor_sync(0xffffffffu, sum1, 2);
    l0 = l0 * al0 + sum0;
    l1 = l1 * al1 + sum1;
#pragma unroll
    for (int nt = 0; nt < 16; nt++) {
      oa[nt][0] *= al0; oa[nt][1] *= al0;
      oa[nt][2] *= al1; oa[nt][3] *= al1;
    }

    // ---- O += P @ V ----
#pragma unroll
    for (int kt = 0; kt < 4; kt++) {
      uint32_t aPh[4], aPl[4];
      pack_split2(s4[2 * kt][0], s4[2 * kt][1], aPh[0], aPl[0]);
      pack_split2(s4[2 * kt][2], s4[2 * kt][3], aPh[1], aPl[1]);
      pack_split2(s4[2 * kt + 1][0], s4[2 * kt + 1][1], aPh[2], aPl[2]);
      pack_split2(s4[2 * kt + 1][2], s4[2 * kt + 1][3], aPh[3], aPl[3]);
#pragma unroll
      for (int p = 0; p < 8; p++) {
        uint32_t rH[4], rL[4];
        uint32_t va = (uint32_t)(kt * 16 + v_kv) * FPITCH +
                      (uint32_t)(p * 16 + v_d) * 2;
        ldsm4t(smb + FVHI + va, rH);
        ldsm4t(smb + FVLO + va, rL);
        mma16816b(oa[2 * p],     aPh, rH[0], rH[1]);
        mma16816b(oa[2 * p],     aPh, rL[0], rL[1]);
        mma16816b(oa[2 * p],     aPl, rH[0], rH[1]);
        mma16816b(oa[2 * p + 1], aPh, rH[2], rH[3]);
        mma16816b(oa[2 * p + 1], aPh, rL[2], rL[3]);
        mma16816b(oa[2 * p + 1], aPl, rH[2], rH[3]);
      }
    }
  }

  // ---- epilogue ----
  const float inv0 = 1.0f / l0, inv1 = 1.0f / l1;
  const int r0 = qwb + (lane >> 2);
#pragma unroll
  for (int nt = 0; nt < 16; nt++) {
    int col = h * HD_ + nt * 8 + (lane & 3) * 2;
    float* p0 = g_attn + (size_t)(b * Ss_ + r0) * (NH_ * HD_) + col;
    *(float2*)p0 = make_float2(oa[nt][0] * inv0, oa[nt][1] * inv0);
    float* p1 = g_attn + (size_t)(b * Ss_ + r0 + 8) * (NH_ * HD_) + col;
    *(float2*)p1 = make_float2(oa[nt][2] * inv1, oa[nt][3] * inv1);
  }
}

// ============================ launch ========================================
extern "C" void kernel_launch(void* const* d_in, const int* in_sizes, int n_in,
                              void* d_out, int out_size) {
  const float* hs = (const float*)d_in[0];
  const float* wq = (const float*)d_in[1];
  const float* wk = (const float*)d_in[2];
  const float* wv = (const float*)d_in[3];
  const float* wo = (const float*)d_in[4];
  const float* qw = (const float*)d_in[5];
  const float* kw = (const float*)d_in[6];
  float* out = (float*)d_out;

  void *pq, *pk, *pv, *pa;
  cudaGetSymbolAddress(&pq, g_q);
  cudaGetSymbolAddress(&pk, g_k);
  cudaGetSymbolAddress(&pv, g_v);
  cudaGetSymbolAddress(&pa, g_attn);

  cudaFuncSetAttribute(gemm_bf16s, cudaFuncAttributeMaxDynamicSharedMemorySize,
                       GSMEM);
  cudaFuncSetAttribute(flash_attn_mma,
                       cudaFuncAttributeMaxDynamicSharedMemorySize, FA2_SMEM);

  // Q projection
  gemm_bf16s<<<dim3(NH_ * HD_ / 128, MTOK / 128, 1), 256, GSMEM>>>(
      hs, wq, (float*)pq, nullptr, nullptr, NH_ * HD_, Hh_);
  // K and V projections merged
  gemm_bf16s<<<dim3(NKV_ * HD_ / 128, MTOK / 128, 2), 256, GSMEM>>>(
      hs, wk, (float*)pk, wv, (float*)pv, NKV_ * HD_, Hh_);

  rope_rms<<<(MTOK * NH_) / 8, 256>>>((float*)pq, qw, NH_, MTOK * NH_);
  rope_rms<<<(MTOK * NKV_) / 8, 256>>>((float*)pk, kw, NKV_, MTOK * NKV_);

  flash_attn_mma<<<dim3(Ss_ / 128, NH_, Bb_), 256, FA2_SMEM>>>();

  // Output projection -> d_out
  gemm_bf16s<<<dim3(Hh_ / 128, MTOK / 128, 1), 256, GSMEM>>>(
      (const float*)pa, wo, out, nullptr, nullptr, Hh_, Hh_);
}

// round 5
// speedup vs baseline: 2.6193x; 1.0917x over previous
#include <cuda_runtime.h>
#include <cuda_bf16.h>
#include <math.h>
#include <stdint.h>

#define Bb_ 2
#define Ss_ 2048
#define Hh_ 2048
#define NH_ 16
#define NKV_ 4
#define HD_ 128
#define MTOK (Bb_ * Ss_)   // 4096 tokens

// Scratch (allocation-free rule: __device__ globals)
__device__ float g_q[(size_t)MTOK * NH_ * HD_];
__device__ float g_k[(size_t)MTOK * NKV_ * HD_];
__device__ float g_v[(size_t)MTOK * NKV_ * HD_];
// pre-split bf16 operands
__device__ __nv_bfloat16 g_hs_hi[(size_t)MTOK * Hh_];
__device__ __nv_bfloat16 g_hs_lo[(size_t)MTOK * Hh_];
__device__ __nv_bfloat16 g_wq_hi[(size_t)NH_ * HD_ * Hh_];
__device__ __nv_bfloat16 g_wq_lo[(size_t)NH_ * HD_ * Hh_];
__device__ __nv_bfloat16 g_wk_hi[(size_t)NKV_ * HD_ * Hh_];
__device__ __nv_bfloat16 g_wk_lo[(size_t)NKV_ * HD_ * Hh_];
__device__ __nv_bfloat16 g_wv_hi[(size_t)NKV_ * HD_ * Hh_];
__device__ __nv_bfloat16 g_wv_lo[(size_t)NKV_ * HD_ * Hh_];
__device__ __nv_bfloat16 g_wo_hi[(size_t)Hh_ * NH_ * HD_];
__device__ __nv_bfloat16 g_wo_lo[(size_t)Hh_ * NH_ * HD_];
__device__ __nv_bfloat16 g_ahi[(size_t)MTOK * NH_ * HD_];
__device__ __nv_bfloat16 g_alo[(size_t)MTOK * NH_ * HD_];

// ============================ helpers =======================================
__device__ __forceinline__ uint32_t smem_u32(const void* p) {
  uint32_t a;
  asm("{ .reg .u64 t; cvta.to.shared.u64 t, %1; cvt.u32.u64 %0, t; }"
      : "=r"(a) : "l"(p));
  return a;
}
__device__ __forceinline__ void cp16(uint32_t dst, const void* src) {
  asm volatile("cp.async.cg.shared.global [%0], [%1], 16;"
               :: "r"(dst), "l"(src));
}
__device__ __forceinline__ void cp_commit() {
  asm volatile("cp.async.commit_group;" ::: "memory");
}
__device__ __forceinline__ void cp_wait1() {
  asm volatile("cp.async.wait_group 1;" ::: "memory");
}
__device__ __forceinline__ void ldsm4(uint32_t addr, uint32_t r[4]) {
  asm volatile("ldmatrix.sync.aligned.m8n8.x4.shared.b16 {%0,%1,%2,%3}, [%4];"
               : "=r"(r[0]), "=r"(r[1]), "=r"(r[2]), "=r"(r[3]) : "r"(addr));
}
__device__ __forceinline__ void ldsm4t(uint32_t addr, uint32_t r[4]) {
  asm volatile(
      "ldmatrix.sync.aligned.m8n8.x4.trans.shared.b16 {%0,%1,%2,%3}, [%4];"
      : "=r"(r[0]), "=r"(r[1]), "=r"(r[2]), "=r"(r[3]) : "r"(addr));
}
__device__ __forceinline__ void mma16816(float c[4], const uint32_t a[4],
                                         uint32_t b0, uint32_t b1) {
  asm volatile(
      "mma.sync.aligned.m16n8k16.row.col.f32.bf16.bf16.f32 "
      "{%0,%1,%2,%3}, {%4,%5,%6,%7}, {%8,%9}, {%0,%1,%2,%3};"
      : "+f"(c[0]), "+f"(c[1]), "+f"(c[2]), "+f"(c[3])
      : "r"(a[0]), "r"(a[1]), "r"(a[2]), "r"(a[3]), "r"(b0), "r"(b1));
}
__device__ __forceinline__ void cvt_split4(float4 v, uint32_t h[2],
                                           uint32_t l[2]) {
  __nv_bfloat162 h0 = __float22bfloat162_rn(make_float2(v.x, v.y));
  __nv_bfloat162 h1 = __float22bfloat162_rn(make_float2(v.z, v.w));
  float2 r0 = make_float2(v.x - __bfloat162float(h0.x),
                          v.y - __bfloat162float(h0.y));
  float2 r1 = make_float2(v.z - __bfloat162float(h1.x),
                          v.w - __bfloat162float(h1.y));
  __nv_bfloat162 l0 = __float22bfloat162_rn(r0);
  __nv_bfloat162 l1 = __float22bfloat162_rn(r1);
  h[0] = *reinterpret_cast<uint32_t*>(&h0);
  h[1] = *reinterpret_cast<uint32_t*>(&h1);
  l[0] = *reinterpret_cast<uint32_t*>(&l0);
  l[1] = *reinterpret_cast<uint32_t*>(&l1);
}
__device__ __forceinline__ void pack_split2(float x, float y, uint32_t& h,
                                            uint32_t& l) {
  __nv_bfloat162 hb = __float22bfloat162_rn(make_float2(x, y));
  float2 hf = __bfloat1622float2(hb);
  __nv_bfloat162 lb = __float22bfloat162_rn(make_float2(x - hf.x, y - hf.y));
  h = *reinterpret_cast<uint32_t*>(&hb);
  l = *reinterpret_cast<uint32_t*>(&lb);
}

// ============================ split (fp32 -> bf16 hi/lo) ====================
__global__ __launch_bounds__(256) void split_fp32(
    const float* __restrict__ x, __nv_bfloat16* __restrict__ hi,
    __nv_bfloat16* __restrict__ lo, int n4) {
  int i = blockIdx.x * blockDim.x + threadIdx.x;
  if (i >= n4) return;
  float4 v = ((const float4*)x)[i];
  uint32_t h[2], l[2];
  cvt_split4(v, h, l);
  ((uint2*)hi)[i] = make_uint2(h[0], h[1]);
  ((uint2*)lo)[i] = make_uint2(l[0], l[1]);
}

// ================= pure-bf16 split GEMM, cp.async 3-stage ===================
// C[M,N] = (Ahi+Alo)[M,K] @ (Bhi+Blo)[N,K]^T (3-pass), fp32 out.
// CTA tile 128x256, BK=32, 8 warps (2m x 4n, warp tile 64x64).
#define A_MAT (128 * 80)            // 10240 B
#define B_MAT (256 * 80)            // 20480 B
#define STG (2 * A_MAT + 2 * B_MAT) // 61440 B
#define GSM (3 * STG)               // 184320 B

__global__ __launch_bounds__(256, 1) void gemm_bf16p(
    const __nv_bfloat16* __restrict__ Ahi, const __nv_bfloat16* __restrict__ Alo,
    const __nv_bfloat16* Bhi, const __nv_bfloat16* Blo, float* C,
    const __nv_bfloat16* Bhi1, const __nv_bfloat16* Blo1, float* C1,
    int N, int K) {
  extern __shared__ char sm[];
  if (blockIdx.z == 1) { Bhi = Bhi1; Blo = Blo1; C = C1; }
  const uint32_t smb = smem_u32(sm);
  const int tid = threadIdx.x, wid = tid >> 5, lane = tid & 31;
  const int wm = wid & 1, wn = wid >> 1;
  const int bn = blockIdx.x, bm = blockIdx.y;
  const int i4 = lane >> 3, j8 = lane & 7;
  const __nv_bfloat16* Abh = Ahi + (size_t)(bm * 128) * K;
  const __nv_bfloat16* Abl = Alo + (size_t)(bm * 128) * K;
  const __nv_bfloat16* Bbh = Bhi + (size_t)(bn * 256) * K;
  const __nv_bfloat16* Bbl = Blo + (size_t)(bn * 256) * K;

  float ac[4][8][4];
#pragma unroll
  for (int mt = 0; mt < 4; mt++)
#pragma unroll
    for (int nt = 0; nt < 8; nt++)
#pragma unroll
      for (int q = 0; q < 4; q++) ac[mt][nt][q] = 0.f;

  auto issue = [&](int s, int k0) {
    const uint32_t st = smb + s * STG;
#pragma unroll
    for (int i = 0; i < 2; i++) {               // A: 128 rows x 4 chunks
      int e = i * 256 + tid;
      int r = e >> 2, c = e & 3;
      size_t go = (size_t)r * K + k0 + c * 8;
      uint32_t so = (uint32_t)(r * 80 + c * 16);
      cp16(st + so, Abh + go);
      cp16(st + A_MAT + so, Abl + go);
    }
#pragma unroll
    for (int i = 0; i < 4; i++) {               // B: 256 rows x 4 chunks
      int e = i * 256 + tid;
      int r = e >> 2, c = e & 3;
      size_t go = (size_t)r * K + k0 + c * 8;
      uint32_t so = (uint32_t)(r * 80 + c * 16);
      cp16(st + 2 * A_MAT + so, Bbh + go);
      cp16(st + 2 * A_MAT + B_MAT + so, Bbl + go);
    }
  };

  auto compute = [&](int s) {
    const uint32_t base = smb + s * STG;
#pragma unroll
    for (int ks = 0; ks < 2; ks++) {
      uint32_t af[2][4][4];
#pragma unroll
      for (int sp = 0; sp < 2; sp++)
#pragma unroll
        for (int mt = 0; mt < 4; mt++) {
          uint32_t addr = base + sp * A_MAT +
                          (uint32_t)(wm * 64 + mt * 16 + (i4 & 1) * 8 + j8) * 80 +
                          (uint32_t)((i4 >> 1) * 8 + ks * 16) * 2;
          ldsm4(addr, af[sp][mt]);
        }
      uint32_t bf[2][8][2];
#pragma unroll
      for (int sp = 0; sp < 2; sp++)
#pragma unroll
        for (int p = 0; p < 4; p++) {
          uint32_t r[4];
          uint32_t addr = base + 2 * A_MAT + sp * B_MAT +
                          (uint32_t)(wn * 64 + p * 16 + (i4 >> 1) * 8 + j8) * 80 +
                          (uint32_t)((i4 & 1) * 8 + ks * 16) * 2;
          ldsm4(addr, r);
          bf[sp][2 * p][0] = r[0]; bf[sp][2 * p][1] = r[1];
          bf[sp][2 * p + 1][0] = r[2]; bf[sp][2 * p + 1][1] = r[3];
        }
#pragma unroll
      for (int mt = 0; mt < 4; mt++)
#pragma unroll
        for (int nt = 0; nt < 8; nt++) {
          mma16816(ac[mt][nt], af[0][mt], bf[0][nt][0], bf[0][nt][1]);
          mma16816(ac[mt][nt], af[0][mt], bf[1][nt][0], bf[1][nt][1]);
          mma16816(ac[mt][nt], af[1][mt], bf[0][nt][0], bf[0][nt][1]);
        }
    }
  };

  const int KS = K >> 5;   // 64
  issue(0, 0); cp_commit();
  issue(1, 32); cp_commit();

  for (int it = 0; it < KS; it++) {
    const int s = it % 3;
    cp_wait1();
    __syncthreads();
    if (it + 2 < KS) issue((it + 2) % 3, (it + 2) * 32);
    cp_commit();
    compute(s);
  }

  // epilogue
#pragma unroll
  for (int mt = 0; mt < 4; mt++)
#pragma unroll
    for (int nt = 0; nt < 8; nt++) {
      int row = bm * 128 + wm * 64 + mt * 16 + (lane >> 2);
      int col = bn * 256 + wn * 64 + nt * 8 + (lane & 3) * 2;
      float* c0 = C + (size_t)row * N + col;
      *(float2*)c0 = make_float2(ac[mt][nt][0], ac[mt][nt][1]);
      *(float2*)(c0 + 8 * (size_t)N) = make_float2(ac[mt][nt][2], ac[mt][nt][3]);
    }
}

// ============================ RoPE + RMSNorm ================================
__global__ __launch_bounds__(256) void rope_rms(float* __restrict__ x,
                                                const float* __restrict__ w,
                                                int nh, int total_warps) {
  int gw = (blockIdx.x * blockDim.x + threadIdx.x) >> 5;
  if (gw >= total_warps) return;
  int lane = threadIdx.x & 31;
  int token = gw / nh;
  int s = token & (Ss_ - 1);
  float* p = x + (size_t)gw * HD_;

  const float neg_l2theta_over_half = -13.287712379549449f / 64.f;
  float vals[4];
  float ss = 0.f;
#pragma unroll
  for (int hh = 0; hh < 2; hh++) {
    int d = lane + hh * 32;
    float x1 = p[d];
    float x2 = p[d + 64];
    float invf = exp2f((float)d * neg_l2theta_over_half);
    float ang = (float)s * invf;
    float c, sn;
    sincosf(ang, &sn, &c);
    float o1 = x1 * c - x2 * sn;
    float o2 = x2 * c + x1 * sn;
    vals[hh * 2] = o1;
    vals[hh * 2 + 1] = o2;
    ss += o1 * o1 + o2 * o2;
  }
#pragma unroll
  for (int o = 16; o >= 1; o >>= 1) ss += __shfl_xor_sync(0xffffffffu, ss, o);
  float r = rsqrtf(ss * (1.f / 128.f) + 1e-6f);
#pragma unroll
  for (int hh = 0; hh < 2; hh++) {
    int d = lane + hh * 32;
    p[d]      = vals[hh * 2]     * r * w[d];
    p[d + 64] = vals[hh * 2 + 1] * r * w[d + 64];
  }
}

// ======================= Flash attention (bf16-split mma) ===================
#define FPITCH 272
#define FQHI 0
#define FQLO (128 * FPITCH)
#define FKHI (2 * 128 * FPITCH)
#define FKLO (FKHI + 64 * FPITCH)
#define FVHI (FKHI + 2 * 64 * FPITCH)
#define FVLO (FVHI + 64 * FPITCH)
#define FA2_SMEM (FVLO + 64 * FPITCH)

__global__ __launch_bounds__(256) void flash_attn_mma() {
  extern __shared__ char sm[];
  const uint32_t smb = smem_u32(sm);
  const int qt = blockIdx.x, h = blockIdx.y, b = blockIdx.z;
  const int kvh = h >> 2;
  const int tid = threadIdx.x, wid = tid >> 5, lane = tid & 31;
  const int i4 = lane >> 3, j8 = lane & 7;
  const int qb = qt * 128;
  const int qwb = qb + wid * 16;
  const float scale = 0.08838834764831845f;

  {
    const int row = tid >> 1, half = tid & 1;
    const float* src = g_q + ((size_t)(b * Ss_ + qb + row) * (NH_ * HD_) +
                              h * HD_ + half * 64);
    char* dh = sm + FQHI + row * FPITCH + half * 128;
    char* dl = sm + FQLO + row * FPITCH + half * 128;
#pragma unroll
    for (int q = 0; q < 16; q++) {
      float4 v = *(const float4*)(src + q * 4);
      v.x *= scale; v.y *= scale; v.z *= scale; v.w *= scale;
      uint32_t hh[2], ll[2];
      cvt_split4(v, hh, ll);
      *(uint2*)(dh + q * 8) = make_uint2(hh[0], hh[1]);
      *(uint2*)(dl + q * 8) = make_uint2(ll[0], ll[1]);
    }
  }

  float oa[16][4];
#pragma unroll
  for (int nt = 0; nt < 16; nt++)
#pragma unroll
    for (int q = 0; q < 4; q++) oa[nt][q] = 0.f;
  float m0 = -INFINITY, m1 = -INFINITY, l0 = 0.f, l1 = 0.f;

  const uint32_t qa_off = (uint32_t)(wid * 16 + (i4 & 1) * 8 + j8) * FPITCH +
                          (uint32_t)((i4 >> 1) * 8) * 2;
  const uint32_t kb_row = (uint32_t)((i4 >> 1) * 8 + j8);
  const uint32_t kb_koff = (uint32_t)((i4 & 1) * 8) * 2;
  const uint32_t v_kv = (uint32_t)((i4 & 1) * 8 + j8);
  const uint32_t v_d = (uint32_t)((i4 >> 1) * 8);

  const int krow = tid >> 2, kqtr = tid & 3;

  const int nkv = 2 * qt + 2;
  for (int kvi = 0; kvi < nkv; kvi++) {
    const int kvb = kvi * 64;
    float4 rk[8], rv[8];
    {
      const size_t gbase = (size_t)(b * Ss_ + kvb + krow) * (NKV_ * HD_) +
                           kvh * HD_ + kqtr * 32;
#pragma unroll
      for (int q = 0; q < 8; q++) {
        rk[q] = *(const float4*)(g_k + gbase + q * 4);
        rv[q] = *(const float4*)(g_v + gbase + q * 4);
      }
    }
    __syncthreads();
    {
      char* khd = sm + FKHI + krow * FPITCH + kqtr * 64;
      char* kld = sm + FKLO + krow * FPITCH + kqtr * 64;
      char* vhd = sm + FVHI + krow * FPITCH + kqtr * 64;
      char* vld = sm + FVLO + krow * FPITCH + kqtr * 64;
#pragma unroll
      for (int q = 0; q < 8; q++) {
        uint32_t hh[2], ll[2];
        cvt_split4(rk[q], hh, ll);
        *(uint2*)(khd + q * 8) = make_uint2(hh[0], hh[1]);
        *(uint2*)(kld + q * 8) = make_uint2(ll[0], ll[1]);
        cvt_split4(rv[q], hh, ll);
        *(uint2*)(vhd + q * 8) = make_uint2(hh[0], hh[1]);
        *(uint2*)(vld + q * 8) = make_uint2(ll[0], ll[1]);
      }
    }
    __syncthreads();

    if (kvb > qwb + 15) continue;

    float s4[8][4];
#pragma unroll
    for (int j = 0; j < 8; j++)
#pragma unroll
      for (int q = 0; q < 4; q++) s4[j][q] = 0.f;

#pragma unroll
    for (int kt = 0; kt < 8; kt++) {
      uint32_t aH[4], aL[4];
      ldsm4(smb + FQHI + qa_off + kt * 32, aH);
      ldsm4(smb + FQLO + qa_off + kt * 32, aL);
#pragma unroll
      for (int p = 0; p < 4; p++) {
        uint32_t rH[4], rL[4];
        uint32_t ka = (uint32_t)(p * 16) * FPITCH + kb_row * FPITCH + kb_koff +
                      (uint32_t)(kt * 32);
        ldsm4(smb + FKHI + ka, rH);
        ldsm4(smb + FKLO + ka, rL);
        mma16816(s4[2 * p],     aH, rH[0], rH[1]);
        mma16816(s4[2 * p],     aH, rL[0], rL[1]);
        mma16816(s4[2 * p],     aL, rH[0], rH[1]);
        mma16816(s4[2 * p + 1], aH, rH[2], rH[3]);
        mma16816(s4[2 * p + 1], aH, rL[2], rL[3]);
        mma16816(s4[2 * p + 1], aL, rH[2], rH[3]);
      }
    }

    if (kvb + 63 > qwb) {
      const int qr0 = qwb + (lane >> 2), qr1 = qr0 + 8;
      const int kc0 = kvb + (lane & 3) * 2;
#pragma unroll
      for (int j = 0; j < 8; j++) {
        int kv0 = kc0 + j * 8, kv1 = kv0 + 1;
        if (kv0 > qr0) s4[j][0] = -1e30f;
        if (kv1 > qr0) s4[j][1] = -1e30f;
        if (kv0 > qr1) s4[j][2] = -1e30f;
        if (kv1 > qr1) s4[j][3] = -1e30f;
      }
    }

    float mx0 = -1e30f, mx1 = -1e30f;
#pragma unroll
    for (int j = 0; j < 8; j++) {
      mx0 = fmaxf(mx0, fmaxf(s4[j][0], s4[j][1]));
      mx1 = fmaxf(mx1, fmaxf(s4[j][2], s4[j][3]));
    }
    mx0 = fmaxf(mx0, __shfl_xor_sync(0xffffffffu, mx0, 1));
    mx0 = fmaxf(mx0, __shfl_xor_sync(0xffffffffu, mx0, 2));
    mx1 = fmaxf(mx1, __shfl_xor_sync(0xffffffffu, mx1, 1));
    mx1 = fmaxf(mx1, __shfl_xor_sync(0xffffffffu, mx1, 2));
    float mn0 = fmaxf(m0, mx0), mn1 = fmaxf(m1, mx1);
    float al0 = __expf(m0 - mn0), al1 = __expf(m1 - mn1);
    m0 = mn0; m1 = mn1;
    float sum0 = 0.f, sum1 = 0.f;
#pragma unroll
    for (int j = 0; j < 8; j++) {
      s4[j][0] = __expf(s4[j][0] - mn0);
      s4[j][1] = __expf(s4[j][1] - mn0);
      s4[j][2] = __expf(s4[j][2] - mn1);
      s4[j][3] = __expf(s4[j][3] - mn1);
      sum0 += s4[j][0] + s4[j][1];
      sum1 += s4[j][2] + s4[j][3];
    }
    sum0 += __shfl_xor_sync(0xffffffffu, sum0, 1);
    sum0 += __shfl_xor_sync(0xffffffffu, sum0, 2);
    sum1 += __shfl_xor_sync(0xffffffffu, sum1, 1);
    sum1 += __shfl_xor_sync(0xffffffffu, sum1, 2);
    l0 = l0 * al0 + sum0;
    l1 = l1 * al1 + sum1;
#pragma unroll
    for (int nt = 0; nt < 16; nt++) {
      oa[nt][0] *= al0; oa[nt][1] *= al0;
      oa[nt][2] *= al1; oa[nt][3] *= al1;
    }

#pragma unroll
    for (int kt = 0; kt < 4; kt++) {
      uint32_t aPh[4], aPl[4];
      pack_split2(s4[2 * kt][0], s4[2 * kt][1], aPh[0], aPl[0]);
      pack_split2(s4[2 * kt][2], s4[2 * kt][3], aPh[1], aPl[1]);
      pack_split2(s4[2 * kt + 1][0], s4[2 * kt + 1][1], aPh[2], aPl[2]);
      pack_split2(s4[2 * kt + 1][2], s4[2 * kt + 1][3], aPh[3], aPl[3]);
#pragma unroll
      for (int p = 0; p < 8; p++) {
        uint32_t rH[4], rL[4];
        uint32_t va = (uint32_t)(kt * 16 + v_kv) * FPITCH +
                      (uint32_t)(p * 16 + v_d) * 2;
        ldsm4t(smb + FVHI + va, rH);
        ldsm4t(smb + FVLO + va, rL);
        mma16816(oa[2 * p],     aPh, rH[0], rH[1]);
        mma16816(oa[2 * p],     aPh, rL[0], rL[1]);
        mma16816(oa[2 * p],     aPl, rH[0], rH[1]);
        mma16816(oa[2 * p + 1], aPh, rH[2], rH[3]);
        mma16816(oa[2 * p + 1], aPh, rL[2], rL[3]);
        mma16816(oa[2 * p + 1], aPl, rH[2], rH[3]);
      }
    }
  }

  // epilogue: split-write attention output as bf16 hi/lo
  const float inv0 = 1.0f / l0, inv1 = 1.0f / l1;
  const int r0 = qwb + (lane >> 2);
#pragma unroll
  for (int nt = 0; nt < 16; nt++) {
    int col = h * HD_ + nt * 8 + (lane & 3) * 2;
    size_t idx0 = (size_t)(b * Ss_ + r0) * (NH_ * HD_) + col;
    size_t idx1 = (size_t)(b * Ss_ + r0 + 8) * (NH_ * HD_) + col;
    uint32_t h0, lo0, h1, lo1;
    pack_split2(oa[nt][0] * inv0, oa[nt][1] * inv0, h0, lo0);
    pack_split2(oa[nt][2] * inv1, oa[nt][3] * inv1, h1, lo1);
    *(uint32_t*)(g_ahi + idx0) = h0;
    *(uint32_t*)(g_alo + idx0) = lo0;
    *(uint32_t*)(g_ahi + idx1) = h1;
    *(uint32_t*)(g_alo + idx1) = lo1;
  }
}

// ============================ launch ========================================
extern "C" void kernel_launch(void* const* d_in, const int* in_sizes, int n_in,
                              void* d_out, int out_size) {
  const float* hs = (const float*)d_in[0];
  const float* wq = (const float*)d_in[1];
  const float* wk = (const float*)d_in[2];
  const float* wv = (const float*)d_in[3];
  const float* wo = (const float*)d_in[4];
  const float* qw = (const float*)d_in[5];
  const float* kw = (const float*)d_in[6];
  float* out = (float*)d_out;

  void *pq, *pk, *pv;
  void *hsh, *hsl, *wqh, *wql, *wkh, *wkl, *wvh, *wvl, *woh, *wol, *ah, *al;
  cudaGetSymbolAddress(&pq, g_q);
  cudaGetSymbolAddress(&pk, g_k);
  cudaGetSymbolAddress(&pv, g_v);
  cudaGetSymbolAddress(&hsh, g_hs_hi); cudaGetSymbolAddress(&hsl, g_hs_lo);
  cudaGetSymbolAddress(&wqh, g_wq_hi); cudaGetSymbolAddress(&wql, g_wq_lo);
  cudaGetSymbolAddress(&wkh, g_wk_hi); cudaGetSymbolAddress(&wkl, g_wk_lo);
  cudaGetSymbolAddress(&wvh, g_wv_hi); cudaGetSymbolAddress(&wvl, g_wv_lo);
  cudaGetSymbolAddress(&woh, g_wo_hi); cudaGetSymbolAddress(&wol, g_wo_lo);
  cudaGetSymbolAddress(&ah, g_ahi);    cudaGetSymbolAddress(&al, g_alo);

  cudaFuncSetAttribute(gemm_bf16p, cudaFuncAttributeMaxDynamicSharedMemorySize,
                       GSM);
  cudaFuncSetAttribute(flash_attn_mma,
                       cudaFuncAttributeMaxDynamicSharedMemorySize, FA2_SMEM);

  // pre-split inputs
  {
    int n4;
    n4 = MTOK * Hh_ / 4;
    split_fp32<<<(n4 + 255) / 256, 256>>>(hs, (__nv_bfloat16*)hsh,
                                          (__nv_bfloat16*)hsl, n4);
    n4 = NH_ * HD_ * Hh_ / 4;
    split_fp32<<<(n4 + 255) / 256, 256>>>(wq, (__nv_bfloat16*)wqh,
                                          (__nv_bfloat16*)wql, n4);
    n4 = NKV_ * HD_ * Hh_ / 4;
    split_fp32<<<(n4 + 255) / 256, 256>>>(wk, (__nv_bfloat16*)wkh,
                                          (__nv_bfloat16*)wkl, n4);
    split_fp32<<<(n4 + 255) / 256, 256>>>(wv, (__nv_bfloat16*)wvh,
                                          (__nv_bfloat16*)wvl, n4);
    n4 = Hh_ * NH_ * HD_ / 4;
    split_fp32<<<(n4 + 255) / 256, 256>>>(wo, (__nv_bfloat16*)woh,
                                          (__nv_bfloat16*)wol, n4);
  }

  // Q projection: [4096, 2048]
  gemm_bf16p<<<dim3(NH_ * HD_ / 256, MTOK / 128, 1), 256, GSM>>>(
      (const __nv_bfloat16*)hsh, (const __nv_bfloat16*)hsl,
      (const __nv_bfloat16*)wqh, (const __nv_bfloat16*)wql, (float*)pq,
      nullptr, nullptr, nullptr, NH_ * HD_, Hh_);
  // K and V projections merged: [4096, 512] each
  gemm_bf16p<<<dim3(NKV_ * HD_ / 256, MTOK / 128, 2), 256, GSM>>>(
      (const __nv_bfloat16*)hsh, (const __nv_bfloat16*)hsl,
      (const __nv_bfloat16*)wkh, (const __nv_bfloat16*)wkl, (float*)pk,
      (const __nv_bfloat16*)wvh, (const __nv_bfloat16*)wvl, (float*)pv,
      NKV_ * HD_, Hh_);

  rope_rms<<<(MTOK * NH_) / 8, 256>>>((float*)pq, qw, NH_, MTOK * NH_);
  rope_rms<<<(MTOK * NKV_) / 8, 256>>>((float*)pk, kw, NKV_, MTOK * NKV_);

  flash_attn_mma<<<dim3(Ss_ / 128, NH_, Bb_), 256, FA2_SMEM>>>();

  // Output projection -> d_out
  gemm_bf16p<<<dim3(Hh_ / 256, MTOK / 128, 1), 256, GSM>>>(
      (const __nv_bfloat16*)ah, (const __nv_bfloat16*)al,
      (const __nv_bfloat16*)woh, (const __nv_bfloat16*)wol, out,
      nullptr, nullptr, nullptr, Hh_, Hh_);
}

// round 6
// speedup vs baseline: 2.6797x; 1.0230x over previous
#include <cuda_runtime.h>
#include <cuda_bf16.h>
#include <math.h>
#include <stdint.h>

#define Bb_ 2
#define Ss_ 2048
#define Hh_ 2048
#define NH_ 16
#define NKV_ 4
#define HD_ 128
#define MTOK (Bb_ * Ss_)   // 4096 tokens

// Scratch (allocation-free rule: __device__ globals)
__device__ float g_q[(size_t)MTOK * NH_ * HD_];
__device__ float g_k[(size_t)MTOK * NKV_ * HD_];
__device__ float g_v[(size_t)MTOK * NKV_ * HD_];
// pre-split bf16 operands
__device__ __nv_bfloat16 g_hs_hi[(size_t)MTOK * Hh_];
__device__ __nv_bfloat16 g_hs_lo[(size_t)MTOK * Hh_];
__device__ __nv_bfloat16 g_wq_hi[(size_t)NH_ * HD_ * Hh_];
__device__ __nv_bfloat16 g_wq_lo[(size_t)NH_ * HD_ * Hh_];
__device__ __nv_bfloat16 g_wk_hi[(size_t)NKV_ * HD_ * Hh_];
__device__ __nv_bfloat16 g_wk_lo[(size_t)NKV_ * HD_ * Hh_];
__device__ __nv_bfloat16 g_wv_hi[(size_t)NKV_ * HD_ * Hh_];
__device__ __nv_bfloat16 g_wv_lo[(size_t)NKV_ * HD_ * Hh_];
__device__ __nv_bfloat16 g_wo_hi[(size_t)Hh_ * NH_ * HD_];
__device__ __nv_bfloat16 g_wo_lo[(size_t)Hh_ * NH_ * HD_];
__device__ __nv_bfloat16 g_ahi[(size_t)MTOK * NH_ * HD_];
__device__ __nv_bfloat16 g_alo[(size_t)MTOK * NH_ * HD_];

// ============================ helpers =======================================
__device__ __forceinline__ uint32_t smem_u32(const void* p) {
  uint32_t a;
  asm("{ .reg .u64 t; cvta.to.shared.u64 t, %1; cvt.u32.u64 %0, t; }"
      : "=r"(a) : "l"(p));
  return a;
}
__device__ __forceinline__ void cp16(uint32_t dst, const void* src) {
  asm volatile("cp.async.cg.shared.global [%0], [%1], 16;"
               :: "r"(dst), "l"(src));
}
__device__ __forceinline__ void cp_commit() {
  asm volatile("cp.async.commit_group;" ::: "memory");
}
__device__ __forceinline__ void cp_wait1() {
  asm volatile("cp.async.wait_group 1;" ::: "memory");
}
__device__ __forceinline__ void ldsm4(uint32_t addr, uint32_t r[4]) {
  asm volatile("ldmatrix.sync.aligned.m8n8.x4.shared.b16 {%0,%1,%2,%3}, [%4];"
               : "=r"(r[0]), "=r"(r[1]), "=r"(r[2]), "=r"(r[3]) : "r"(addr));
}
__device__ __forceinline__ void ldsm4t(uint32_t addr, uint32_t r[4]) {
  asm volatile(
      "ldmatrix.sync.aligned.m8n8.x4.trans.shared.b16 {%0,%1,%2,%3}, [%4];"
      : "=r"(r[0]), "=r"(r[1]), "=r"(r[2]), "=r"(r[3]) : "r"(addr));
}
__device__ __forceinline__ void mma16816(float c[4], const uint32_t a[4],
                                         uint32_t b0, uint32_t b1) {
  asm volatile(
      "mma.sync.aligned.m16n8k16.row.col.f32.bf16.bf16.f32 "
      "{%0,%1,%2,%3}, {%4,%5,%6,%7}, {%8,%9}, {%0,%1,%2,%3};"
      : "+f"(c[0]), "+f"(c[1]), "+f"(c[2]), "+f"(c[3])
      : "r"(a[0]), "r"(a[1]), "r"(a[2]), "r"(a[3]), "r"(b0), "r"(b1));
}
__device__ __forceinline__ void cvt_split4(float4 v, uint32_t h[2],
                                           uint32_t l[2]) {
  __nv_bfloat162 h0 = __float22bfloat162_rn(make_float2(v.x, v.y));
  __nv_bfloat162 h1 = __float22bfloat162_rn(make_float2(v.z, v.w));
  float2 r0 = make_float2(v.x - __bfloat162float(h0.x),
                          v.y - __bfloat162float(h0.y));
  float2 r1 = make_float2(v.z - __bfloat162float(h1.x),
                          v.w - __bfloat162float(h1.y));
  __nv_bfloat162 l0 = __float22bfloat162_rn(r0);
  __nv_bfloat162 l1 = __float22bfloat162_rn(r1);
  h[0] = *reinterpret_cast<uint32_t*>(&h0);
  h[1] = *reinterpret_cast<uint32_t*>(&h1);
  l[0] = *reinterpret_cast<uint32_t*>(&l0);
  l[1] = *reinterpret_cast<uint32_t*>(&l1);
}
__device__ __forceinline__ void pack_split2(float x, float y, uint32_t& h,
                                            uint32_t& l) {
  __nv_bfloat162 hb = __float22bfloat162_rn(make_float2(x, y));
  float2 hf = __bfloat1622float2(hb);
  __nv_bfloat162 lb = __float22bfloat162_rn(make_float2(x - hf.x, y - hf.y));
  h = *reinterpret_cast<uint32_t*>(&hb);
  l = *reinterpret_cast<uint32_t*>(&lb);
}

// ============================ split (fp32 -> bf16 hi/lo) ====================
__global__ __launch_bounds__(256) void split_fp32(
    const float* __restrict__ x, __nv_bfloat16* __restrict__ hi,
    __nv_bfloat16* __restrict__ lo, int n4) {
  int i = blockIdx.x * blockDim.x + threadIdx.x;
  if (i >= n4) return;
  float4 v = ((const float4*)x)[i];
  uint32_t h[2], l[2];
  cvt_split4(v, h, l);
  ((uint2*)hi)[i] = make_uint2(h[0], h[1]);
  ((uint2*)lo)[i] = make_uint2(l[0], l[1]);
}

// ================= pure-bf16 split GEMM, 512 thr, cp.async 3-stage ==========
// CTA tile 128x256, BK=32, 16 warps (2m x 8n, warp tile 64x32).
// mode 0: fused QKV (A = hs, bn<8 -> Q, 8..9 -> K, 10..11 -> V)
// mode 1: O proj (A = attn hi/lo, B = wo, C = outC, N = 2048)
#define A_MAT (128 * 80)            // 10240 B
#define B_MAT (256 * 80)            // 20480 B
#define STG (2 * A_MAT + 2 * B_MAT) // 61440 B
#define GSM (3 * STG)               // 184320 B
#define KDIM 2048

__global__ __launch_bounds__(512, 1) void gemm512(int mode, float* outC) {
  extern __shared__ char sm[];
  const uint32_t smb = smem_u32(sm);
  const int tid = threadIdx.x, wid = tid >> 5, lane = tid & 31;
  const int wm = wid & 1, wn = wid >> 1;
  const int bn = blockIdx.x, bm = blockIdx.y;
  const int i4 = lane >> 3, j8 = lane & 7;

  const __nv_bfloat16 *Abh, *Abl, *Bbh, *Bbl;
  float* C;
  int N, colbase;
  if (mode == 0) {
    Abh = g_hs_hi + (size_t)(bm * 128) * KDIM;
    Abl = g_hs_lo + (size_t)(bm * 128) * KDIM;
    if (bn < 8) {
      Bbh = g_wq_hi + (size_t)(bn * 256) * KDIM;
      Bbl = g_wq_lo + (size_t)(bn * 256) * KDIM;
      C = g_q; N = 2048; colbase = bn * 256;
    } else if (bn < 10) {
      Bbh = g_wk_hi + (size_t)((bn - 8) * 256) * KDIM;
      Bbl = g_wk_lo + (size_t)((bn - 8) * 256) * KDIM;
      C = g_k; N = 512; colbase = (bn - 8) * 256;
    } else {
      Bbh = g_wv_hi + (size_t)((bn - 10) * 256) * KDIM;
      Bbl = g_wv_lo + (size_t)((bn - 10) * 256) * KDIM;
      C = g_v; N = 512; colbase = (bn - 10) * 256;
    }
  } else {
    Abh = g_ahi + (size_t)(bm * 128) * KDIM;
    Abl = g_alo + (size_t)(bm * 128) * KDIM;
    Bbh = g_wo_hi + (size_t)(bn * 256) * KDIM;
    Bbl = g_wo_lo + (size_t)(bn * 256) * KDIM;
    C = outC; N = 2048; colbase = bn * 256;
  }

  float ac[4][4][4];
#pragma unroll
  for (int mt = 0; mt < 4; mt++)
#pragma unroll
    for (int nt = 0; nt < 4; nt++)
#pragma unroll
      for (int q = 0; q < 4; q++) ac[mt][nt][q] = 0.f;

  auto issue = [&](int s, int k0) {
    const uint32_t st = smb + s * STG;
    {  // A: 128 rows x 4 chunks = 512 lines; 1 per thread (hi + lo)
      int r = tid >> 2, c = tid & 3;
      size_t go = (size_t)r * KDIM + k0 + c * 8;
      uint32_t so = (uint32_t)(r * 80 + c * 16);
      cp16(st + so, Abh + go);
      cp16(st + A_MAT + so, Abl + go);
    }
#pragma unroll
    for (int i = 0; i < 2; i++) {  // B: 256 rows x 4 chunks
      int e = i * 512 + tid;
      int r = e >> 2, c = e & 3;
      size_t go = (size_t)r * KDIM + k0 + c * 8;
      uint32_t so = (uint32_t)(r * 80 + c * 16);
      cp16(st + 2 * A_MAT + so, Bbh + go);
      cp16(st + 2 * A_MAT + B_MAT + so, Bbl + go);
    }
  };

  auto compute = [&](int s) {
    const uint32_t base = smb + s * STG;
#pragma unroll
    for (int ks = 0; ks < 2; ks++) {
      uint32_t af[2][4][4];
#pragma unroll
      for (int sp = 0; sp < 2; sp++)
#pragma unroll
        for (int mt = 0; mt < 4; mt++) {
          uint32_t addr = base + sp * A_MAT +
                          (uint32_t)(wm * 64 + mt * 16 + (i4 & 1) * 8 + j8) * 80 +
                          (uint32_t)((i4 >> 1) * 8 + ks * 16) * 2;
          ldsm4(addr, af[sp][mt]);
        }
      uint32_t bf[2][4][2];
#pragma unroll
      for (int sp = 0; sp < 2; sp++)
#pragma unroll
        for (int p = 0; p < 2; p++) {
          uint32_t r[4];
          uint32_t addr = base + 2 * A_MAT + sp * B_MAT +
                          (uint32_t)(wn * 32 + p * 16 + (i4 >> 1) * 8 + j8) * 80 +
                          (uint32_t)((i4 & 1) * 8 + ks * 16) * 2;
          ldsm4(addr, r);
          bf[sp][2 * p][0] = r[0]; bf[sp][2 * p][1] = r[1];
          bf[sp][2 * p + 1][0] = r[2]; bf[sp][2 * p + 1][1] = r[3];
        }
#pragma unroll
      for (int mt = 0; mt < 4; mt++)
#pragma unroll
        for (int nt = 0; nt < 4; nt++) {
          mma16816(ac[mt][nt], af[0][mt], bf[0][nt][0], bf[0][nt][1]);
          mma16816(ac[mt][nt], af[0][mt], bf[1][nt][0], bf[1][nt][1]);
          mma16816(ac[mt][nt], af[1][mt], bf[0][nt][0], bf[0][nt][1]);
        }
    }
  };

  const int KS = KDIM >> 5;  // 64
  issue(0, 0); cp_commit();
  issue(1, 32); cp_commit();

  for (int it = 0; it < KS; it++) {
    const int s = it % 3;
    cp_wait1();
    __syncthreads();
    if (it + 2 < KS) issue((it + 2) % 3, (it + 2) * 32);
    cp_commit();
    compute(s);
  }

  // epilogue
#pragma unroll
  for (int mt = 0; mt < 4; mt++)
#pragma unroll
    for (int nt = 0; nt < 4; nt++) {
      int row = bm * 128 + wm * 64 + mt * 16 + (lane >> 2);
      int col = colbase + wn * 32 + nt * 8 + (lane & 3) * 2;
      float* c0 = C + (size_t)row * N + col;
      *(float2*)c0 = make_float2(ac[mt][nt][0], ac[mt][nt][1]);
      *(float2*)(c0 + 8 * (size_t)N) = make_float2(ac[mt][nt][2], ac[mt][nt][3]);
    }
}

// ============================ RoPE + RMSNorm ================================
__global__ __launch_bounds__(256) void rope_rms(float* __restrict__ x,
                                                const float* __restrict__ w,
                                                int nh, int total_warps) {
  int gw = (blockIdx.x * blockDim.x + threadIdx.x) >> 5;
  if (gw >= total_warps) return;
  int lane = threadIdx.x & 31;
  int token = gw / nh;
  int s = token & (Ss_ - 1);
  float* p = x + (size_t)gw * HD_;

  const float neg_l2theta_over_half = -13.287712379549449f / 64.f;
  float vals[4];
  float ss = 0.f;
#pragma unroll
  for (int hh = 0; hh < 2; hh++) {
    int d = lane + hh * 32;
    float x1 = p[d];
    float x2 = p[d + 64];
    float invf = exp2f((float)d * neg_l2theta_over_half);
    float ang = (float)s * invf;
    float c, sn;
    sincosf(ang, &sn, &c);
    float o1 = x1 * c - x2 * sn;
    float o2 = x2 * c + x1 * sn;
    vals[hh * 2] = o1;
    vals[hh * 2 + 1] = o2;
    ss += o1 * o1 + o2 * o2;
  }
#pragma unroll
  for (int o = 16; o >= 1; o >>= 1) ss += __shfl_xor_sync(0xffffffffu, ss, o);
  float r = rsqrtf(ss * (1.f / 128.f) + 1e-6f);
#pragma unroll
  for (int hh = 0; hh < 2; hh++) {
    int d = lane + hh * 32;
    p[d]      = vals[hh * 2]     * r * w[d];
    p[d + 64] = vals[hh * 2 + 1] * r * w[d + 64];
  }
}

// ======================= Flash attention (bf16-split mma) ===================
#define FPITCH 272
#define FQHI 0
#define FQLO (128 * FPITCH)
#define FKHI (2 * 128 * FPITCH)
#define FKLO (FKHI + 64 * FPITCH)
#define FVHI (FKHI + 2 * 64 * FPITCH)
#define FVLO (FVHI + 64 * FPITCH)
#define FA2_SMEM (FVLO + 64 * FPITCH)

__global__ __launch_bounds__(256) void flash_attn_mma() {
  extern __shared__ char sm[];
  const uint32_t smb = smem_u32(sm);
  const int qt = blockIdx.x, h = blockIdx.y, b = blockIdx.z;
  const int kvh = h >> 2;
  const int tid = threadIdx.x, wid = tid >> 5, lane = tid & 31;
  const int i4 = lane >> 3, j8 = lane & 7;
  const int qb = qt * 128;
  const int qwb = qb + wid * 16;
  const float scale = 0.08838834764831845f;

  {
    const int row = tid >> 1, half = tid & 1;
    const float* src = g_q + ((size_t)(b * Ss_ + qb + row) * (NH_ * HD_) +
                              h * HD_ + half * 64);
    char* dh = sm + FQHI + row * FPITCH + half * 128;
    char* dl = sm + FQLO + row * FPITCH + half * 128;
#pragma unroll
    for (int q = 0; q < 16; q++) {
      float4 v = *(const float4*)(src + q * 4);
      v.x *= scale; v.y *= scale; v.z *= scale; v.w *= scale;
      uint32_t hh[2], ll[2];
      cvt_split4(v, hh, ll);
      *(uint2*)(dh + q * 8) = make_uint2(hh[0], hh[1]);
      *(uint2*)(dl + q * 8) = make_uint2(ll[0], ll[1]);
    }
  }

  float oa[16][4];
#pragma unroll
  for (int nt = 0; nt < 16; nt++)
#pragma unroll
    for (int q = 0; q < 4; q++) oa[nt][q] = 0.f;
  float m0 = -INFINITY, m1 = -INFINITY, l0 = 0.f, l1 = 0.f;

  const uint32_t qa_off = (uint32_t)(wid * 16 + (i4 & 1) * 8 + j8) * FPITCH +
                          (uint32_t)((i4 >> 1) * 8) * 2;
  const uint32_t kb_row = (uint32_t)((i4 >> 1) * 8 + j8);
  const uint32_t kb_koff = (uint32_t)((i4 & 1) * 8) * 2;
  const uint32_t v_kv = (uint32_t)((i4 & 1) * 8 + j8);
  const uint32_t v_d = (uint32_t)((i4 >> 1) * 8);

  const int krow = tid >> 2, kqtr = tid & 3;

  const int nkv = 2 * qt + 2;
  for (int kvi = 0; kvi < nkv; kvi++) {
    const int kvb = kvi * 64;
    float4 rk[8], rv[8];
    {
      const size_t gbase = (size_t)(b * Ss_ + kvb + krow) * (NKV_ * HD_) +
                           kvh * HD_ + kqtr * 32;
#pragma unroll
      for (int q = 0; q < 8; q++) {
        rk[q] = *(const float4*)(g_k + gbase + q * 4);
        rv[q] = *(const float4*)(g_v + gbase + q * 4);
      }
    }
    __syncthreads();
    {
      char* khd = sm + FKHI + krow * FPITCH + kqtr * 64;
      char* kld = sm + FKLO + krow * FPITCH + kqtr * 64;
      char* vhd = sm + FVHI + krow * FPITCH + kqtr * 64;
      char* vld = sm + FVLO + krow * FPITCH + kqtr * 64;
#pragma unroll
      for (int q = 0; q < 8; q++) {
        uint32_t hh[2], ll[2];
        cvt_split4(rk[q], hh, ll);
        *(uint2*)(khd + q * 8) = make_uint2(hh[0], hh[1]);
        *(uint2*)(kld + q * 8) = make_uint2(ll[0], ll[1]);
        cvt_split4(rv[q], hh, ll);
        *(uint2*)(vhd + q * 8) = make_uint2(hh[0], hh[1]);
        *(uint2*)(vld + q * 8) = make_uint2(ll[0], ll[1]);
      }
    }
    __syncthreads();

    if (kvb > qwb + 15) continue;

    float s4[8][4];
#pragma unroll
    for (int j = 0; j < 8; j++)
#pragma unroll
      for (int q = 0; q < 4; q++) s4[j][q] = 0.f;

#pragma unroll
    for (int kt = 0; kt < 8; kt++) {
      uint32_t aH[4], aL[4];
      ldsm4(smb + FQHI + qa_off + kt * 32, aH);
      ldsm4(smb + FQLO + qa_off + kt * 32, aL);
#pragma unroll
      for (int p = 0; p < 4; p++) {
        uint32_t rH[4], rL[4];
        uint32_t ka = (uint32_t)(p * 16) * FPITCH + kb_row * FPITCH + kb_koff +
                      (uint32_t)(kt * 32);
        ldsm4(smb + FKHI + ka, rH);
        ldsm4(smb + FKLO + ka, rL);
        mma16816(s4[2 * p],     aH, rH[0], rH[1]);
        mma16816(s4[2 * p],     aH, rL[0], rL[1]);
        mma16816(s4[2 * p],     aL, rH[0], rH[1]);
        mma16816(s4[2 * p + 1], aH, rH[2], rH[3]);
        mma16816(s4[2 * p + 1], aH, rL[2], rL[3]);
        mma16816(s4[2 * p + 1], aL, rH[2], rH[3]);
      }
    }

    if (kvb + 63 > qwb) {
      const int qr0 = qwb + (lane >> 2), qr1 = qr0 + 8;
      const int kc0 = kvb + (lane & 3) * 2;
#pragma unroll
      for (int j = 0; j < 8; j++) {
        int kv0 = kc0 + j * 8, kv1 = kv0 + 1;
        if (kv0 > qr0) s4[j][0] = -1e30f;
        if (kv1 > qr0) s4[j][1] = -1e30f;
        if (kv0 > qr1) s4[j][2] = -1e30f;
        if (kv1 > qr1) s4[j][3] = -1e30f;
      }
    }

    float mx0 = -1e30f, mx1 = -1e30f;
#pragma unroll
    for (int j = 0; j < 8; j++) {
      mx0 = fmaxf(mx0, fmaxf(s4[j][0], s4[j][1]));
      mx1 = fmaxf(mx1, fmaxf(s4[j][2], s4[j][3]));
    }
    mx0 = fmaxf(mx0, __shfl_xor_sync(0xffffffffu, mx0, 1));
    mx0 = fmaxf(mx0, __shfl_xor_sync(0xffffffffu, mx0, 2));
    mx1 = fmaxf(mx1, __shfl_xor_sync(0xffffffffu, mx1, 1));
    mx1 = fmaxf(mx1, __shfl_xor_sync(0xffffffffu, mx1, 2));
    float mn0 = fmaxf(m0, mx0), mn1 = fmaxf(m1, mx1);
    float al0 = __expf(m0 - mn0), al1 = __expf(m1 - mn1);
    m0 = mn0; m1 = mn1;
    float sum0 = 0.f, sum1 = 0.f;
#pragma unroll
    for (int j = 0; j < 8; j++) {
      s4[j][0] = __expf(s4[j][0] - mn0);
      s4[j][1] = __expf(s4[j][1] - mn0);
      s4[j][2] = __expf(s4[j][2] - mn1);
      s4[j][3] = __expf(s4[j][3] - mn1);
      sum0 += s4[j][0] + s4[j][1];
      sum1 += s4[j][2] + s4[j][3];
    }
    sum0 += __shfl_xor_sync(0xffffffffu, sum0, 1);
    sum0 += __shfl_xor_sync(0xffffffffu, sum0, 2);
    sum1 += __shfl_xor_sync(0xffffffffu, sum1, 1);
    sum1 += __shfl_xor_sync(0xffffffffu, sum1, 2);
    l0 = l0 * al0 + sum0;
    l1 = l1 * al1 + sum1;
#pragma unroll
    for (int nt = 0; nt < 16; nt++) {
      oa[nt][0] *= al0; oa[nt][1] *= al0;
      oa[nt][2] *= al1; oa[nt][3] *= al1;
    }

#pragma unroll
    for (int kt = 0; kt < 4; kt++) {
      uint32_t aPh[4], aPl[4];
      pack_split2(s4[2 * kt][0], s4[2 * kt][1], aPh[0], aPl[0]);
      pack_split2(s4[2 * kt][2], s4[2 * kt][3], aPh[1], aPl[1]);
      pack_split2(s4[2 * kt + 1][0], s4[2 * kt + 1][1], aPh[2], aPl[2]);
      pack_split2(s4[2 * kt + 1][2], s4[2 * kt + 1][3], aPh[3], aPl[3]);
#pragma unroll
      for (int p = 0; p < 8; p++) {
        uint32_t rH[4], rL[4];
        uint32_t va = (uint32_t)(kt * 16 + v_kv) * FPITCH +
                      (uint32_t)(p * 16 + v_d) * 2;
        ldsm4t(smb + FVHI + va, rH);
        ldsm4t(smb + FVLO + va, rL);
        mma16816(oa[2 * p],     aPh, rH[0], rH[1]);
        mma16816(oa[2 * p],     aPh, rL[0], rL[1]);
        mma16816(oa[2 * p],     aPl, rH[0], rH[1]);
        mma16816(oa[2 * p + 1], aPh, rH[2], rH[3]);
        mma16816(oa[2 * p + 1], aPh, rL[2], rL[3]);
        mma16816(oa[2 * p + 1], aPl, rH[2], rH[3]);
      }
    }
  }

  // epilogue: split-write attention output as bf16 hi/lo
  const float inv0 = 1.0f / l0, inv1 = 1.0f / l1;
  const int r0 = qwb + (lane >> 2);
#pragma unroll
  for (int nt = 0; nt < 16; nt++) {
    int col = h * HD_ + nt * 8 + (lane & 3) * 2;
    size_t idx0 = (size_t)(b * Ss_ + r0) * (NH_ * HD_) + col;
    size_t idx1 = (size_t)(b * Ss_ + r0 + 8) * (NH_ * HD_) + col;
    uint32_t h0, lo0, h1, lo1;
    pack_split2(oa[nt][0] * inv0, oa[nt][1] * inv0, h0, lo0);
    pack_split2(oa[nt][2] * inv1, oa[nt][3] * inv1, h1, lo1);
    *(uint32_t*)(g_ahi + idx0) = h0;
    *(uint32_t*)(g_alo + idx0) = lo0;
    *(uint32_t*)(g_ahi + idx1) = h1;
    *(uint32_t*)(g_alo + idx1) = lo1;
  }
}

// ============================ launch ========================================
extern "C" void kernel_launch(void* const* d_in, const int* in_sizes, int n_in,
                              void* d_out, int out_size) {
  const float* hs = (const float*)d_in[0];
  const float* wq = (const float*)d_in[1];
  const float* wk = (const float*)d_in[2];
  const float* wv = (const float*)d_in[3];
  const float* wo = (const float*)d_in[4];
  const float* qw = (const float*)d_in[5];
  const float* kw = (const float*)d_in[6];
  float* out = (float*)d_out;

  void *pq, *pk;
  void *hsh, *hsl, *wqh, *wql, *wkh, *wkl, *wvh, *wvl, *woh, *wol;
  cudaGetSymbolAddress(&pq, g_q);
  cudaGetSymbolAddress(&pk, g_k);
  cudaGetSymbolAddress(&hsh, g_hs_hi); cudaGetSymbolAddress(&hsl, g_hs_lo);
  cudaGetSymbolAddress(&wqh, g_wq_hi); cudaGetSymbolAddress(&wql, g_wq_lo);
  cudaGetSymbolAddress(&wkh, g_wk_hi); cudaGetSymbolAddress(&wkl, g_wk_lo);
  cudaGetSymbolAddress(&wvh, g_wv_hi); cudaGetSymbolAddress(&wvl, g_wv_lo);
  cudaGetSymbolAddress(&woh, g_wo_hi); cudaGetSymbolAddress(&wol, g_wo_lo);

  cudaFuncSetAttribute(gemm512, cudaFuncAttributeMaxDynamicSharedMemorySize,
                       GSM);
  cudaFuncSetAttribute(flash_attn_mma,
                       cudaFuncAttributeMaxDynamicSharedMemorySize, FA2_SMEM);

  // pre-split inputs
  {
    int n4;
    n4 = MTOK * Hh_ / 4;
    split_fp32<<<(n4 + 255) / 256, 256>>>(hs, (__nv_bfloat16*)hsh,
                                          (__nv_bfloat16*)hsl, n4);
    n4 = NH_ * HD_ * Hh_ / 4;
    split_fp32<<<(n4 + 255) / 256, 256>>>(wq, (__nv_bfloat16*)wqh,
                                          (__nv_bfloat16*)wql, n4);
    n4 = NKV_ * HD_ * Hh_ / 4;
    split_fp32<<<(n4 + 255) / 256, 256>>>(wk, (__nv_bfloat16*)wkh,
                                          (__nv_bfloat16*)wkl, n4);
    split_fp32<<<(n4 + 255) / 256, 256>>>(wv, (__nv_bfloat16*)wvh,
                                          (__nv_bfloat16*)wvl, n4);
    n4 = Hh_ * NH_ * HD_ / 4;
    split_fp32<<<(n4 + 255) / 256, 256>>>(wo, (__nv_bfloat16*)woh,
                                          (__nv_bfloat16*)wol, n4);
  }

  // Fused Q+K+V projections: 12 n-tiles (Q:8, K:2, V:2) x 32 m-tiles
  gemm512<<<dim3(12, MTOK / 128), 512, GSM>>>(0, nullptr);

  rope_rms<<<(MTOK * NH_) / 8, 256>>>((float*)pq, qw, NH_, MTOK * NH_);
  rope_rms<<<(MTOK * NKV_) / 8, 256>>>((float*)pk, kw, NKV_, MTOK * NKV_);

  flash_attn_mma<<<dim3(Ss_ / 128, NH_, Bb_), 256, FA2_SMEM>>>();

  // Output projection -> d_out
  gemm512<<<dim3(Hh_ / 256, MTOK / 128), 512, GSM>>>(1, out);
}

// round 7
// speedup vs baseline: 3.1079x; 1.1598x over previous
#include <cuda_runtime.h>
#include <cuda_bf16.h>
#include <cuda_fp16.h>
#include <math.h>
#include <stdint.h>

#define Bb_ 2
#define Ss_ 2048
#define Hh_ 2048
#define NH_ 16
#define NKV_ 4
#define HD_ 128
#define MTOK (Bb_ * Ss_)   // 4096 tokens

// Scratch (allocation-free rule: __device__ globals)
__device__ float g_q[(size_t)MTOK * NH_ * HD_];    // fp32 pre-rope Q
__device__ float g_k[(size_t)MTOK * NKV_ * HD_];   // fp32 pre-rope K
// pre-split bf16 GEMM operands
__device__ __nv_bfloat16 g_hs_hi[(size_t)MTOK * Hh_];
__device__ __nv_bfloat16 g_hs_lo[(size_t)MTOK * Hh_];
__device__ __nv_bfloat16 g_wq_hi[(size_t)NH_ * HD_ * Hh_];
__device__ __nv_bfloat16 g_wq_lo[(size_t)NH_ * HD_ * Hh_];
__device__ __nv_bfloat16 g_wk_hi[(size_t)NKV_ * HD_ * Hh_];
__device__ __nv_bfloat16 g_wk_lo[(size_t)NKV_ * HD_ * Hh_];
__device__ __nv_bfloat16 g_wv_hi[(size_t)NKV_ * HD_ * Hh_];
__device__ __nv_bfloat16 g_wv_lo[(size_t)NKV_ * HD_ * Hh_];
// attention inputs, pre-split bf16
__device__ __nv_bfloat16 g_qhi[(size_t)MTOK * NH_ * HD_];
__device__ __nv_bfloat16 g_qlo[(size_t)MTOK * NH_ * HD_];
__device__ __nv_bfloat16 g_khi[(size_t)MTOK * NKV_ * HD_];
__device__ __nv_bfloat16 g_klo[(size_t)MTOK * NKV_ * HD_];
__device__ __nv_bfloat16 g_vhi[(size_t)MTOK * NKV_ * HD_];
__device__ __nv_bfloat16 g_vlo[(size_t)MTOK * NKV_ * HD_];
// O-proj operands (fp16 2-pass)
__device__ __half g_wo16[(size_t)Hh_ * NH_ * HD_];
__device__ __half g_ahi[(size_t)MTOK * NH_ * HD_];
__device__ __half g_alo[(size_t)MTOK * NH_ * HD_];

// ============================ helpers =======================================
__device__ __forceinline__ uint32_t smem_u32(const void* p) {
  uint32_t a;
  asm("{ .reg .u64 t; cvta.to.shared.u64 t, %1; cvt.u32.u64 %0, t; }"
      : "=r"(a) : "l"(p));
  return a;
}
__device__ __forceinline__ void cp16(uint32_t dst, const void* src) {
  asm volatile("cp.async.cg.shared.global [%0], [%1], 16;"
               :: "r"(dst), "l"(src));
}
__device__ __forceinline__ void cp_commit() {
  asm volatile("cp.async.commit_group;" ::: "memory");
}
__device__ __forceinline__ void cp_wait1() {
  asm volatile("cp.async.wait_group 1;" ::: "memory");
}
__device__ __forceinline__ void ldsm4(uint32_t addr, uint32_t r[4]) {
  asm volatile("ldmatrix.sync.aligned.m8n8.x4.shared.b16 {%0,%1,%2,%3}, [%4];"
               : "=r"(r[0]), "=r"(r[1]), "=r"(r[2]), "=r"(r[3]) : "r"(addr));
}
__device__ __forceinline__ void ldsm4t(uint32_t addr, uint32_t r[4]) {
  asm volatile(
      "ldmatrix.sync.aligned.m8n8.x4.trans.shared.b16 {%0,%1,%2,%3}, [%4];"
      : "=r"(r[0]), "=r"(r[1]), "=r"(r[2]), "=r"(r[3]) : "r"(addr));
}
__device__ __forceinline__ void mma16816(float c[4], const uint32_t a[4],
                                         uint32_t b0, uint32_t b1) {
  asm volatile(
      "mma.sync.aligned.m16n8k16.row.col.f32.bf16.bf16.f32 "
      "{%0,%1,%2,%3}, {%4,%5,%6,%7}, {%8,%9}, {%0,%1,%2,%3};"
      : "+f"(c[0]), "+f"(c[1]), "+f"(c[2]), "+f"(c[3])
      : "r"(a[0]), "r"(a[1]), "r"(a[2]), "r"(a[3]), "r"(b0), "r"(b1));
}
__device__ __forceinline__ void mmaf16(float c[4], const uint32_t a[4],
                                       uint32_t b0, uint32_t b1) {
  asm volatile(
      "mma.sync.aligned.m16n8k16.row.col.f32.f16.f16.f32 "
      "{%0,%1,%2,%3}, {%4,%5,%6,%7}, {%8,%9}, {%0,%1,%2,%3};"
      : "+f"(c[0]), "+f"(c[1]), "+f"(c[2]), "+f"(c[3])
      : "r"(a[0]), "r"(a[1]), "r"(a[2]), "r"(a[3]), "r"(b0), "r"(b1));
}
__device__ __forceinline__ void cvt_split4(float4 v, uint32_t h[2],
                                           uint32_t l[2]) {
  __nv_bfloat162 h0 = __float22bfloat162_rn(make_float2(v.x, v.y));
  __nv_bfloat162 h1 = __float22bfloat162_rn(make_float2(v.z, v.w));
  float2 r0 = make_float2(v.x - __bfloat162float(h0.x),
                          v.y - __bfloat162float(h0.y));
  float2 r1 = make_float2(v.z - __bfloat162float(h1.x),
                          v.w - __bfloat162float(h1.y));
  __nv_bfloat162 l0 = __float22bfloat162_rn(r0);
  __nv_bfloat162 l1 = __float22bfloat162_rn(r1);
  h[0] = *reinterpret_cast<uint32_t*>(&h0);
  h[1] = *reinterpret_cast<uint32_t*>(&h1);
  l[0] = *reinterpret_cast<uint32_t*>(&l0);
  l[1] = *reinterpret_cast<uint32_t*>(&l1);
}
__device__ __forceinline__ void pack_split2(float x, float y, uint32_t& h,
                                            uint32_t& l) {
  __nv_bfloat162 hb = __float22bfloat162_rn(make_float2(x, y));
  float2 hf = __bfloat1622float2(hb);
  __nv_bfloat162 lb = __float22bfloat162_rn(make_float2(x - hf.x, y - hf.y));
  h = *reinterpret_cast<uint32_t*>(&hb);
  l = *reinterpret_cast<uint32_t*>(&lb);
}
__device__ __forceinline__ void pack_h2(float x, float y, uint32_t& h,
                                        uint32_t& l) {
  __half2 hb = __float22half2_rn(make_float2(x, y));
  float2 hf = __half22float2(hb);
  __half2 lb = __float22half2_rn(make_float2(x - hf.x, y - hf.y));
  h = *reinterpret_cast<uint32_t*>(&hb);
  l = *reinterpret_cast<uint32_t*>(&lb);
}

// ============================ split kernels =================================
__global__ __launch_bounds__(256) void split_fp32(
    const float* __restrict__ x, __nv_bfloat16* __restrict__ hi,
    __nv_bfloat16* __restrict__ lo, int n4) {
  int i = blockIdx.x * blockDim.x + threadIdx.x;
  if (i >= n4) return;
  float4 v = ((const float4*)x)[i];
  uint32_t h[2], l[2];
  cvt_split4(v, h, l);
  ((uint2*)hi)[i] = make_uint2(h[0], h[1]);
  ((uint2*)lo)[i] = make_uint2(l[0], l[1]);
}

__global__ __launch_bounds__(256) void round_fp16(
    const float* __restrict__ x, __half* __restrict__ y, int n4) {
  int i = blockIdx.x * blockDim.x + threadIdx.x;
  if (i >= n4) return;
  float4 v = ((const float4*)x)[i];
  __half2 a = __float22half2_rn(make_float2(v.x, v.y));
  __half2 b = __float22half2_rn(make_float2(v.z, v.w));
  ((uint2*)y)[i] = make_uint2(*reinterpret_cast<uint32_t*>(&a),
                              *reinterpret_cast<uint32_t*>(&b));
}

// ================= fused QKV GEMM, bf16 3-pass, cp.async 3-stage ============
// CTA tile 128x256, BK=32, 16 warps (2m x 8n, warp tile 64x32).
// bn<8 -> Q (fp32 out), 8..9 -> K (fp32 out), 10..11 -> V (bf16 split out)
#define A_MAT (128 * 80)            // 10240 B
#define B_MAT (256 * 80)            // 20480 B
#define STG (2 * A_MAT + 2 * B_MAT) // 61440 B
#define GSM (3 * STG)               // 184320 B
#define KDIM 2048

__global__ __launch_bounds__(512, 1) void gemm_qkv() {
  extern __shared__ char sm[];
  const uint32_t smb = smem_u32(sm);
  const int tid = threadIdx.x, wid = tid >> 5, lane = tid & 31;
  const int wm = wid & 1, wn = wid >> 1;
  const int bn = blockIdx.x, bm = blockIdx.y;
  const int i4 = lane >> 3, j8 = lane & 7;

  const __nv_bfloat16 *Bbh, *Bbl;
  int colbase, dest;  // dest: 0=Q fp32, 1=K fp32, 2=V split
  if (bn < 8) {
    Bbh = g_wq_hi + (size_t)(bn * 256) * KDIM;
    Bbl = g_wq_lo + (size_t)(bn * 256) * KDIM;
    colbase = bn * 256; dest = 0;
  } else if (bn < 10) {
    Bbh = g_wk_hi + (size_t)((bn - 8) * 256) * KDIM;
    Bbl = g_wk_lo + (size_t)((bn - 8) * 256) * KDIM;
    colbase = (bn - 8) * 256; dest = 1;
  } else {
    Bbh = g_wv_hi + (size_t)((bn - 10) * 256) * KDIM;
    Bbl = g_wv_lo + (size_t)((bn - 10) * 256) * KDIM;
    colbase = (bn - 10) * 256; dest = 2;
  }
  const __nv_bfloat16* Abh = g_hs_hi + (size_t)(bm * 128) * KDIM;
  const __nv_bfloat16* Abl = g_hs_lo + (size_t)(bm * 128) * KDIM;

  float ac[4][4][4];
#pragma unroll
  for (int mt = 0; mt < 4; mt++)
#pragma unroll
    for (int nt = 0; nt < 4; nt++)
#pragma unroll
      for (int q = 0; q < 4; q++) ac[mt][nt][q] = 0.f;

  auto issue = [&](int s, int k0) {
    const uint32_t st = smb + s * STG;
    {
      int r = tid >> 2, c = tid & 3;
      size_t go = (size_t)r * KDIM + k0 + c * 8;
      uint32_t so = (uint32_t)(r * 80 + c * 16);
      cp16(st + so, Abh + go);
      cp16(st + A_MAT + so, Abl + go);
    }
#pragma unroll
    for (int i = 0; i < 2; i++) {
      int e = i * 512 + tid;
      int r = e >> 2, c = e & 3;
      size_t go = (size_t)r * KDIM + k0 + c * 8;
      uint32_t so = (uint32_t)(r * 80 + c * 16);
      cp16(st + 2 * A_MAT + so, Bbh + go);
      cp16(st + 2 * A_MAT + B_MAT + so, Bbl + go);
    }
  };

  auto compute = [&](int s) {
    const uint32_t base = smb + s * STG;
#pragma unroll
    for (int ks = 0; ks < 2; ks++) {
      uint32_t af[2][4][4];
#pragma unroll
      for (int sp = 0; sp < 2; sp++)
#pragma unroll
        for (int mt = 0; mt < 4; mt++) {
          uint32_t addr = base + sp * A_MAT +
                          (uint32_t)(wm * 64 + mt * 16 + (i4 & 1) * 8 + j8) * 80 +
                          (uint32_t)((i4 >> 1) * 8 + ks * 16) * 2;
          ldsm4(addr, af[sp][mt]);
        }
      uint32_t bf[2][4][2];
#pragma unroll
      for (int sp = 0; sp < 2; sp++)
#pragma unroll
        for (int p = 0; p < 2; p++) {
          uint32_t r[4];
          uint32_t addr = base + 2 * A_MAT + sp * B_MAT +
                          (uint32_t)(wn * 32 + p * 16 + (i4 >> 1) * 8 + j8) * 80 +
                          (uint32_t)((i4 & 1) * 8 + ks * 16) * 2;
          ldsm4(addr, r);
          bf[sp][2 * p][0] = r[0]; bf[sp][2 * p][1] = r[1];
          bf[sp][2 * p + 1][0] = r[2]; bf[sp][2 * p + 1][1] = r[3];
        }
#pragma unroll
      for (int mt = 0; mt < 4; mt++)
#pragma unroll
        for (int nt = 0; nt < 4; nt++) {
          mma16816(ac[mt][nt], af[0][mt], bf[0][nt][0], bf[0][nt][1]);
          mma16816(ac[mt][nt], af[0][mt], bf[1][nt][0], bf[1][nt][1]);
          mma16816(ac[mt][nt], af[1][mt], bf[0][nt][0], bf[0][nt][1]);
        }
    }
  };

  const int KS = KDIM >> 5;  // 64
  issue(0, 0); cp_commit();
  issue(1, 32); cp_commit();

  for (int it = 0; it < KS; it++) {
    const int s = it % 3;
    cp_wait1();
    __syncthreads();
    if (it + 2 < KS) issue((it + 2) % 3, (it + 2) * 32);
    cp_commit();
    compute(s);
  }

  // epilogue
#pragma unroll
  for (int mt = 0; mt < 4; mt++)
#pragma unroll
    for (int nt = 0; nt < 4; nt++) {
      int row = bm * 128 + wm * 64 + mt * 16 + (lane >> 2);
      int col = colbase + wn * 32 + nt * 8 + (lane & 3) * 2;
      if (dest == 0) {
        float* c0 = g_q + (size_t)row * 2048 + col;
        *(float2*)c0 = make_float2(ac[mt][nt][0], ac[mt][nt][1]);
        *(float2*)(c0 + 8 * 2048) = make_float2(ac[mt][nt][2], ac[mt][nt][3]);
      } else if (dest == 1) {
        float* c0 = g_k + (size_t)row * 512 + col;
        *(float2*)c0 = make_float2(ac[mt][nt][0], ac[mt][nt][1]);
        *(float2*)(c0 + 8 * 512) = make_float2(ac[mt][nt][2], ac[mt][nt][3]);
      } else {
        size_t i0 = (size_t)row * 512 + col;
        size_t i1 = i0 + 8 * 512;
        uint32_t h0, l0, h1, l1;
        pack_split2(ac[mt][nt][0], ac[mt][nt][1], h0, l0);
        pack_split2(ac[mt][nt][2], ac[mt][nt][3], h1, l1);
        *(uint32_t*)(g_vhi + i0) = h0;
        *(uint32_t*)(g_vlo + i0) = l0;
        *(uint32_t*)(g_vhi + i1) = h1;
        *(uint32_t*)(g_vlo + i1) = l1;
      }
    }
}

// ============== O-proj GEMM, fp16 2-pass (A exact split, B single) ==========
#define OA_MAT (128 * 80)             // 10240
#define OB_MAT (256 * 80)             // 20480
#define OSTG (2 * OA_MAT + OB_MAT)    // 40960
#define OSM (3 * OSTG)                // 122880

__global__ __launch_bounds__(512, 1) void gemm_oproj(float* __restrict__ out) {
  extern __shared__ char sm[];
  const uint32_t smb = smem_u32(sm);
  const int tid = threadIdx.x, wid = tid >> 5, lane = tid & 31;
  const int wm = wid & 1, wn = wid >> 1;
  const int bn = blockIdx.x, bm = blockIdx.y;
  const int i4 = lane >> 3, j8 = lane & 7;
  const __half* Abh = g_ahi + (size_t)(bm * 128) * KDIM;
  const __half* Abl = g_alo + (size_t)(bm * 128) * KDIM;
  const __half* Bb = g_wo16 + (size_t)(bn * 256) * KDIM;

  float ac[4][4][4];
#pragma unroll
  for (int mt = 0; mt < 4; mt++)
#pragma unroll
    for (int nt = 0; nt < 4; nt++)
#pragma unroll
      for (int q = 0; q < 4; q++) ac[mt][nt][q] = 0.f;

  auto issue = [&](int s, int k0) {
    const uint32_t st = smb + s * OSTG;
    {
      int r = tid >> 2, c = tid & 3;
      size_t go = (size_t)r * KDIM + k0 + c * 8;
      uint32_t so = (uint32_t)(r * 80 + c * 16);
      cp16(st + so, Abh + go);
      cp16(st + OA_MAT + so, Abl + go);
    }
#pragma unroll
    for (int i = 0; i < 2; i++) {
      int e = i * 512 + tid;
      int r = e >> 2, c = e & 3;
      size_t go = (size_t)r * KDIM + k0 + c * 8;
      uint32_t so = (uint32_t)(r * 80 + c * 16);
      cp16(st + 2 * OA_MAT + so, Bb + go);
    }
  };

  auto compute = [&](int s) {
    const uint32_t base = smb + s * OSTG;
#pragma unroll
    for (int ks = 0; ks < 2; ks++) {
      uint32_t af[2][4][4];
#pragma unroll
      for (int sp = 0; sp < 2; sp++)
#pragma unroll
        for (int mt = 0; mt < 4; mt++) {
          uint32_t addr = base + sp * OA_MAT +
                          (uint32_t)(wm * 64 + mt * 16 + (i4 & 1) * 8 + j8) * 80 +
                          (uint32_t)((i4 >> 1) * 8 + ks * 16) * 2;
          ldsm4(addr, af[sp][mt]);
        }
      uint32_t bf[4][2];
#pragma unroll
      for (int p = 0; p < 2; p++) {
        uint32_t r[4];
        uint32_t addr = base + 2 * OA_MAT +
                        (uint32_t)(wn * 32 + p * 16 + (i4 >> 1) * 8 + j8) * 80 +
                        (uint32_t)((i4 & 1) * 8 + ks * 16) * 2;
        ldsm4(addr, r);
        bf[2 * p][0] = r[0]; bf[2 * p][1] = r[1];
        bf[2 * p + 1][0] = r[2]; bf[2 * p + 1][1] = r[3];
      }
#pragma unroll
      for (int mt = 0; mt < 4; mt++)
#pragma unroll
        for (int nt = 0; nt < 4; nt++) {
          mmaf16(ac[mt][nt], af[0][mt], bf[nt][0], bf[nt][1]);
          mmaf16(ac[mt][nt], af[1][mt], bf[nt][0], bf[nt][1]);
        }
    }
  };

  const int KS = KDIM >> 5;
  issue(0, 0); cp_commit();
  issue(1, 32); cp_commit();

  for (int it = 0; it < KS; it++) {
    const int s = it % 3;
    cp_wait1();
    __syncthreads();
    if (it + 2 < KS) issue((it + 2) % 3, (it + 2) * 32);
    cp_commit();
    compute(s);
  }

#pragma unroll
  for (int mt = 0; mt < 4; mt++)
#pragma unroll
    for (int nt = 0; nt < 4; nt++) {
      int row = bm * 128 + wm * 64 + mt * 16 + (lane >> 2);
      int col = bn * 256 + wn * 32 + nt * 8 + (lane & 3) * 2;
      float* c0 = out + (size_t)row * 2048 + col;
      *(float2*)c0 = make_float2(ac[mt][nt][0], ac[mt][nt][1]);
      *(float2*)(c0 + 8 * 2048) = make_float2(ac[mt][nt][2], ac[mt][nt][3]);
    }
}

// =================== RoPE + RMSNorm -> bf16 hi/lo split =====================
__global__ __launch_bounds__(256) void rope_rms_split(
    const float* __restrict__ x, const float* __restrict__ w,
    __nv_bfloat16* __restrict__ hi, __nv_bfloat16* __restrict__ lo,
    int nh, int total_warps, float osc) {
  int gw = (blockIdx.x * blockDim.x + threadIdx.x) >> 5;
  if (gw >= total_warps) return;
  int lane = threadIdx.x & 31;
  int token = gw / nh;
  int s = token & (Ss_ - 1);
  const float* p = x + (size_t)gw * HD_;

  const float neg_l2theta_over_half = -13.287712379549449f / 64.f;
  float vals[4];
  float ss = 0.f;
#pragma unroll
  for (int hh = 0; hh < 2; hh++) {
    int d = lane + hh * 32;
    float x1 = p[d];
    float x2 = p[d + 64];
    float invf = exp2f((float)d * neg_l2theta_over_half);
    float ang = (float)s * invf;
    float c, sn;
    sincosf(ang, &sn, &c);
    float o1 = x1 * c - x2 * sn;
    float o2 = x2 * c + x1 * sn;
    vals[hh * 2] = o1;
    vals[hh * 2 + 1] = o2;
    ss += o1 * o1 + o2 * o2;
  }
#pragma unroll
  for (int o = 16; o >= 1; o >>= 1) ss += __shfl_xor_sync(0xffffffffu, ss, o);
  float r = rsqrtf(ss * (1.f / 128.f) + 1e-6f) * osc;
#pragma unroll
  for (int hh = 0; hh < 2; hh++) {
    int d = lane + hh * 32;
    float v0 = vals[hh * 2] * r * w[d];
    float v1 = vals[hh * 2 + 1] * r * w[d + 64];
    size_t base = (size_t)gw * HD_;
    __nv_bfloat16 b0 = __float2bfloat16(v0);
    __nv_bfloat16 b1 = __float2bfloat16(v1);
    hi[base + d] = b0;
    lo[base + d] = __float2bfloat16(v0 - __bfloat162float(b0));
    hi[base + d + 64] = b1;
    lo[base + d + 64] = __float2bfloat16(v1 - __bfloat162float(b1));
  }
}

// ======================= Flash attention (bf16-split mma) ===================
#define FPITCH 272
#define FQHI 0
#define FQLO (128 * FPITCH)
#define FKHI (2 * 128 * FPITCH)
#define FKLO (FKHI + 64 * FPITCH)
#define FVHI (FKHI + 2 * 64 * FPITCH)
#define FVLO (FVHI + 64 * FPITCH)
#define FA2_SMEM (FVLO + 64 * FPITCH)

__global__ __launch_bounds__(256) void flash_attn_mma() {
  extern __shared__ char sm[];
  const uint32_t smb = smem_u32(sm);
  const int qt = blockIdx.x, h = blockIdx.y, b = blockIdx.z;
  const int kvh = h >> 2;
  const int tid = threadIdx.x, wid = tid >> 5, lane = tid & 31;
  const int i4 = lane >> 3, j8 = lane & 7;
  const int qb = qt * 128;
  const int qwb = qb + wid * 16;

  // ---- prologue: Q (pre-split, pre-scaled) -> smem ----
  {
    const int row = tid >> 1, half = tid & 1;
    const size_t gof = (size_t)(b * Ss_ + qb + row) * (NH_ * HD_) + h * HD_ +
                       half * 64;
    const uint4* sh = (const uint4*)(g_qhi + gof);
    const uint4* sl = (const uint4*)(g_qlo + gof);
    char* dh = sm + FQHI + row * FPITCH + half * 128;
    char* dl = sm + FQLO + row * FPITCH + half * 128;
#pragma unroll
    for (int q = 0; q < 8; q++) {
      *(uint4*)(dh + q * 16) = sh[q];
      *(uint4*)(dl + q * 16) = sl[q];
    }
  }

  float oa[16][4];
#pragma unroll
  for (int nt = 0; nt < 16; nt++)
#pragma unroll
    for (int q = 0; q < 4; q++) oa[nt][q] = 0.f;
  float m0 = -INFINITY, m1 = -INFINITY, l0 = 0.f, l1 = 0.f;

  const uint32_t qa_off = (uint32_t)(wid * 16 + (i4 & 1) * 8 + j8) * FPITCH +
                          (uint32_t)((i4 >> 1) * 8) * 2;
  const uint32_t kb_row = (uint32_t)((i4 >> 1) * 8 + j8);
  const uint32_t kb_koff = (uint32_t)((i4 & 1) * 8) * 2;
  const uint32_t v_kv = (uint32_t)((i4 & 1) * 8 + j8);
  const uint32_t v_d = (uint32_t)((i4 >> 1) * 8);

  const int krow = tid >> 2, kqtr = tid & 3;

  const int nkv = 2 * qt + 2;
  for (int kvi = 0; kvi < nkv; kvi++) {
    const int kvb = kvi * 64;
    uint4 rkh[4], rkl[4], rvh[4], rvl[4];
    {
      const size_t gb = (size_t)(b * Ss_ + kvb + krow) * (NKV_ * HD_) +
                        kvh * HD_ + kqtr * 32;
#pragma unroll
      for (int q = 0; q < 4; q++) {
        rkh[q] = ((const uint4*)(g_khi + gb))[q];
        rkl[q] = ((const uint4*)(g_klo + gb))[q];
        rvh[q] = ((const uint4*)(g_vhi + gb))[q];
        rvl[q] = ((const uint4*)(g_vlo + gb))[q];
      }
    }
    __syncthreads();
    {
      char* khd = sm + FKHI + krow * FPITCH + kqtr * 64;
      char* kld = sm + FKLO + krow * FPITCH + kqtr * 64;
      char* vhd = sm + FVHI + krow * FPITCH + kqtr * 64;
      char* vld = sm + FVLO + krow * FPITCH + kqtr * 64;
#pragma unroll
      for (int q = 0; q < 4; q++) {
        *(uint4*)(khd + q * 16) = rkh[q];
        *(uint4*)(kld + q * 16) = rkl[q];
        *(uint4*)(vhd + q * 16) = rvh[q];
        *(uint4*)(vld + q * 16) = rvl[q];
      }
    }
    __syncthreads();

    if (kvb > qwb + 15) continue;

    float s4[8][4];
#pragma unroll
    for (int j = 0; j < 8; j++)
#pragma unroll
      for (int q = 0; q < 4; q++) s4[j][q] = 0.f;

#pragma unroll
    for (int kt = 0; kt < 8; kt++) {
      uint32_t aH[4], aL[4];
      ldsm4(smb + FQHI + qa_off + kt * 32, aH);
      ldsm4(smb + FQLO + qa_off + kt * 32, aL);
#pragma unroll
      for (int p = 0; p < 4; p++) {
        uint32_t rH[4], rL[4];
        uint32_t ka = (uint32_t)(p * 16) * FPITCH + kb_row * FPITCH + kb_koff +
                      (uint32_t)(kt * 32);
        ldsm4(smb + FKHI + ka, rH);
        ldsm4(smb + FKLO + ka, rL);
        mma16816(s4[2 * p],     aH, rH[0], rH[1]);
        mma16816(s4[2 * p],     aH, rL[0], rL[1]);
        mma16816(s4[2 * p],     aL, rH[0], rH[1]);
        mma16816(s4[2 * p + 1], aH, rH[2], rH[3]);
        mma16816(s4[2 * p + 1], aH, rL[2], rL[3]);
        mma16816(s4[2 * p + 1], aL, rH[2], rH[3]);
      }
    }

    if (kvb + 63 > qwb) {
      const int qr0 = qwb + (lane >> 2), qr1 = qr0 + 8;
      const int kc0 = kvb + (lane & 3) * 2;
#pragma unroll
      for (int j = 0; j < 8; j++) {
        int kv0 = kc0 + j * 8, kv1 = kv0 + 1;
        if (kv0 > qr0) s4[j][0] = -1e30f;
        if (kv1 > qr0) s4[j][1] = -1e30f;
        if (kv0 > qr1) s4[j][2] = -1e30f;
        if (kv1 > qr1) s4[j][3] = -1e30f;
      }
    }

    float mx0 = -1e30f, mx1 = -1e30f;
#pragma unroll
    for (int j = 0; j < 8; j++) {
      mx0 = fmaxf(mx0, fmaxf(s4[j][0], s4[j][1]));
      mx1 = fmaxf(mx1, fmaxf(s4[j][2], s4[j][3]));
    }
    mx0 = fmaxf(mx0, __shfl_xor_sync(0xffffffffu, mx0, 1));
    mx0 = fmaxf(mx0, __shfl_xor_sync(0xffffffffu, mx0, 2));
    mx1 = fmaxf(mx1, __shfl_xor_sync(0xffffffffu, mx1, 1));
    mx1 = fmaxf(mx1, __shfl_xor_sync(0xffffffffu, mx1, 2));
    float mn0 = fmaxf(m0, mx0), mn1 = fmaxf(m1, mx1);
    float al0 = __expf(m0 - mn0), al1 = __expf(m1 - mn1);
    m0 = mn0; m1 = mn1;
    float sum0 = 0.f, sum1 = 0.f;
#pragma unroll
    for (int j = 0; j < 8; j++) {
      s4[j][0] = __expf(s4[j][0] - mn0);
      s4[j][1] = __expf(s4[j][1] - mn0);
      s4[j][2] = __expf(s4[j][2] - mn1);
      s4[j][3] = __expf(s4[j][3] - mn1);
      sum0 += s4[j][0] + s4[j][1];
      sum1 += s4[j][2] + s4[j][3];
    }
    sum0 += __shfl_xor_sync(0xffffffffu, sum0, 1);
    sum0 += __shfl_xor_sync(0xffffffffu, sum0, 2);
    sum1 += __shfl_xor_sync(0xffffffffu, sum1, 1);
    sum1 += __shfl_xor_sync(0xffffffffu, sum1, 2);
    l0 = l0 * al0 + sum0;
    l1 = l1 * al1 + sum1;
#pragma unroll
    for (int nt = 0; nt < 16; nt++) {
      oa[nt][0] *= al0; oa[nt][1] *= al0;
      oa[nt][2] *= al1; oa[nt][3] *= al1;
    }

#pragma unroll
    for (int kt = 0; kt < 4; kt++) {
      uint32_t aPh[4], aPl[4];
      pack_split2(s4[2 * kt][0], s4[2 * kt][1], aPh[0], aPl[0]);
      pack_split2(s4[2 * kt][2], s4[2 * kt][3], aPh[1], aPl[1]);
      pack_split2(s4[2 * kt + 1][0], s4[2 * kt + 1][1], aPh[2], aPl[2]);
      pack_split2(s4[2 * kt + 1][2], s4[2 * kt + 1][3], aPh[3], aPl[3]);
#pragma unroll
      for (int p = 0; p < 8; p++) {
        uint32_t rH[4], rL[4];
        uint32_t va = (uint32_t)(kt * 16 + v_kv) * FPITCH +
                      (uint32_t)(p * 16 + v_d) * 2;
        ldsm4t(smb + FVHI + va, rH);
        ldsm4t(smb + FVLO + va, rL);
        mma16816(oa[2 * p],     aPh, rH[0], rH[1]);
        mma16816(oa[2 * p],     aPh, rL[0], rL[1]);
        mma16816(oa[2 * p],     aPl, rH[0], rH[1]);
        mma16816(oa[2 * p + 1], aPh, rH[2], rH[3]);
        mma16816(oa[2 * p + 1], aPh, rL[2], rL[3]);
        mma16816(oa[2 * p + 1], aPl, rH[2], rH[3]);
      }
    }
  }

  // epilogue: split-write attention output as fp16 hi/lo (exact split)
  const float inv0 = 1.0f / l0, inv1 = 1.0f / l1;
  const int r0 = qwb + (lane >> 2);
#pragma unroll
  for (int nt = 0; nt < 16; nt++) {
    int col = h * HD_ + nt * 8 + (lane & 3) * 2;
    size_t idx0 = (size_t)(b * Ss_ + r0) * (NH_ * HD_) + col;
    size_t idx1 = (size_t)(b * Ss_ + r0 + 8) * (NH_ * HD_) + col;
    uint32_t h0, lo0, h1, lo1;
    pack_h2(oa[nt][0] * inv0, oa[nt][1] * inv0, h0, lo0);
    pack_h2(oa[nt][2] * inv1, oa[nt][3] * inv1, h1, lo1);
    *(uint32_t*)(g_ahi + idx0) = h0;
    *(uint32_t*)(g_alo + idx0) = lo0;
    *(uint32_t*)(g_ahi + idx1) = h1;
    *(uint32_t*)(g_alo + idx1) = lo1;
  }
}

// ============================ launch ========================================
extern "C" void kernel_launch(void* const* d_in, const int* in_sizes, int n_in,
                              void* d_out, int out_size) {
  const float* hs = (const float*)d_in[0];
  const float* wq = (const float*)d_in[1];
  const float* wk = (const float*)d_in[2];
  const float* wv = (const float*)d_in[3];
  const float* wo = (const float*)d_in[4];
  const float* qw = (const float*)d_in[5];
  const float* kw = (const float*)d_in[6];
  float* out = (float*)d_out;

  void *pq, *pk, *pqh, *pql, *pkh, *pkl;
  void *hsh, *hsl, *wqh, *wql, *wkh, *wkl, *wvh, *wvl, *pwo;
  cudaGetSymbolAddress(&pq, g_q);
  cudaGetSymbolAddress(&pk, g_k);
  cudaGetSymbolAddress(&pqh, g_qhi); cudaGetSymbolAddress(&pql, g_qlo);
  cudaGetSymbolAddress(&pkh, g_khi); cudaGetSymbolAddress(&pkl, g_klo);
  cudaGetSymbolAddress(&hsh, g_hs_hi); cudaGetSymbolAddress(&hsl, g_hs_lo);
  cudaGetSymbolAddress(&wqh, g_wq_hi); cudaGetSymbolAddress(&wql, g_wq_lo);
  cudaGetSymbolAddress(&wkh, g_wk_hi); cudaGetSymbolAddress(&wkl, g_wk_lo);
  cudaGetSymbolAddress(&wvh, g_wv_hi); cudaGetSymbolAddress(&wvl, g_wv_lo);
  cudaGetSymbolAddress(&pwo, g_wo16);

  cudaFuncSetAttribute(gemm_qkv, cudaFuncAttributeMaxDynamicSharedMemorySize,
                       GSM);
  cudaFuncSetAttribute(gemm_oproj, cudaFuncAttributeMaxDynamicSharedMemorySize,
                       OSM);
  cudaFuncSetAttribute(flash_attn_mma,
                       cudaFuncAttributeMaxDynamicSharedMemorySize, FA2_SMEM);

  // pre-split / pre-round inputs
  {
    int n4;
    n4 = MTOK * Hh_ / 4;
    split_fp32<<<(n4 + 255) / 256, 256>>>(hs, (__nv_bfloat16*)hsh,
                                          (__nv_bfloat16*)hsl, n4);
    n4 = NH_ * HD_ * Hh_ / 4;
    split_fp32<<<(n4 + 255) / 256, 256>>>(wq, (__nv_bfloat16*)wqh,
                                          (__nv_bfloat16*)wql, n4);
    n4 = NKV_ * HD_ * Hh_ / 4;
    split_fp32<<<(n4 + 255) / 256, 256>>>(wk, (__nv_bfloat16*)wkh,
                                          (__nv_bfloat16*)wkl, n4);
    split_fp32<<<(n4 + 255) / 256, 256>>>(wv, (__nv_bfloat16*)wvh,
                                          (__nv_bfloat16*)wvl, n4);
    n4 = Hh_ * NH_ * HD_ / 4;
    round_fp16<<<(n4 + 255) / 256, 256>>>(wo, (__half*)pwo, n4);
  }

  // Fused Q+K+V projections
  gemm_qkv<<<dim3(12, MTOK / 128), 512, GSM>>>();

  // RoPE + RMSNorm + split (q scaled by 1/sqrt(HD))
  rope_rms_split<<<(MTOK * NH_) / 8, 256>>>(
      (const float*)pq, qw, (__nv_bfloat16*)pqh, (__nv_bfloat16*)pql, NH_,
      MTOK * NH_, 0.08838834764831845f);
  rope_rms_split<<<(MTOK * NKV_) / 8, 256>>>(
      (const float*)pk, kw, (__nv_bfloat16*)pkh, (__nv_bfloat16*)pkl, NKV_,
      MTOK * NKV_, 1.0f);

  flash_attn_mma<<<dim3(Ss_ / 128, NH_, Bb_), 256, FA2_SMEM>>>();

  // Output projection (fp16 2-pass) -> d_out
  gemm_oproj<<<dim3(Hh_ / 256, MTOK / 128), 512, OSM>>>(out);
}

// round 8
// speedup vs baseline: 3.9455x; 1.2695x over previous
#include <cuda_runtime.h>
#include <cuda_bf16.h>
#include <cuda_fp16.h>
#include <math.h>
#include <stdint.h>

#define Bb_ 2
#define Ss_ 2048
#define Hh_ 2048
#define NH_ 16
#define NKV_ 4
#define HD_ 128
#define MTOK (Bb_ * Ss_)   // 4096 tokens

// Scratch (allocation-free rule: __device__ globals)
__device__ float g_q[(size_t)MTOK * NH_ * HD_];    // fp32 pre-rope Q
__device__ float g_k[(size_t)MTOK * NKV_ * HD_];   // fp32 pre-rope K
// fp16 GEMM operands
__device__ __half g_hs_hi[(size_t)MTOK * Hh_];
__device__ __half g_hs_lo[(size_t)MTOK * Hh_];
__device__ __half g_wq16[(size_t)NH_ * HD_ * Hh_];
__device__ __half g_wk16[(size_t)NKV_ * HD_ * Hh_];
__device__ __half g_wv16[(size_t)NKV_ * HD_ * Hh_];
// attention inputs (fp16)
__device__ __half g_q16h[(size_t)MTOK * NH_ * HD_];
__device__ __half g_q16l[(size_t)MTOK * NH_ * HD_];
__device__ __half g_k16[(size_t)MTOK * NKV_ * HD_];
__device__ __half g_v16[(size_t)MTOK * NKV_ * HD_];
// O-proj operands (fp16 2-pass)
__device__ __half g_wo16[(size_t)Hh_ * NH_ * HD_];
__device__ __half g_ahi[(size_t)MTOK * NH_ * HD_];
__device__ __half g_alo[(size_t)MTOK * NH_ * HD_];

// ============================ helpers =======================================
__device__ __forceinline__ uint32_t smem_u32(const void* p) {
  uint32_t a;
  asm("{ .reg .u64 t; cvta.to.shared.u64 t, %1; cvt.u32.u64 %0, t; }"
      : "=r"(a) : "l"(p));
  return a;
}
__device__ __forceinline__ void cp16(uint32_t dst, const void* src) {
  asm volatile("cp.async.cg.shared.global [%0], [%1], 16;"
               :: "r"(dst), "l"(src));
}
__device__ __forceinline__ void cp_commit() {
  asm volatile("cp.async.commit_group;" ::: "memory");
}
__device__ __forceinline__ void cp_wait1() {
  asm volatile("cp.async.wait_group 1;" ::: "memory");
}
__device__ __forceinline__ void ldsm4(uint32_t addr, uint32_t r[4]) {
  asm volatile("ldmatrix.sync.aligned.m8n8.x4.shared.b16 {%0,%1,%2,%3}, [%4];"
               : "=r"(r[0]), "=r"(r[1]), "=r"(r[2]), "=r"(r[3]) : "r"(addr));
}
__device__ __forceinline__ void ldsm4t(uint32_t addr, uint32_t r[4]) {
  asm volatile(
      "ldmatrix.sync.aligned.m8n8.x4.trans.shared.b16 {%0,%1,%2,%3}, [%4];"
      : "=r"(r[0]), "=r"(r[1]), "=r"(r[2]), "=r"(r[3]) : "r"(addr));
}
__device__ __forceinline__ void mmaf16(float c[4], const uint32_t a[4],
                                       uint32_t b0, uint32_t b1) {
  asm volatile(
      "mma.sync.aligned.m16n8k16.row.col.f32.f16.f16.f32 "
      "{%0,%1,%2,%3}, {%4,%5,%6,%7}, {%8,%9}, {%0,%1,%2,%3};"
      : "+f"(c[0]), "+f"(c[1]), "+f"(c[2]), "+f"(c[3])
      : "r"(a[0]), "r"(a[1]), "r"(a[2]), "r"(a[3]), "r"(b0), "r"(b1));
}
__device__ __forceinline__ void pack_h2(float x, float y, uint32_t& h,
                                        uint32_t& l) {
  __half2 hb = __float22half2_rn(make_float2(x, y));
  float2 hf = __half22float2(hb);
  __half2 lb = __float22half2_rn(make_float2(x - hf.x, y - hf.y));
  h = *reinterpret_cast<uint32_t*>(&hb);
  l = *reinterpret_cast<uint32_t*>(&lb);
}

// ============================ prep kernels ==================================
// exact fp16 split
__global__ __launch_bounds__(256) void split_fp16(
    const float* __restrict__ x, __half* __restrict__ hi,
    __half* __restrict__ lo, int n4) {
  int i = blockIdx.x * blockDim.x + threadIdx.x;
  if (i >= n4) return;
  float4 v = ((const float4*)x)[i];
  uint32_t h0, l0, h1, l1;
  pack_h2(v.x, v.y, h0, l0);
  pack_h2(v.z, v.w, h1, l1);
  ((uint2*)hi)[i] = make_uint2(h0, h1);
  ((uint2*)lo)[i] = make_uint2(l0, l1);
}

__global__ __launch_bounds__(256) void round_fp16(
    const float* __restrict__ x, __half* __restrict__ y, int n4) {
  int i = blockIdx.x * blockDim.x + threadIdx.x;
  if (i >= n4) return;
  float4 v = ((const float4*)x)[i];
  __half2 a = __float22half2_rn(make_float2(v.x, v.y));
  __half2 b = __float22half2_rn(make_float2(v.z, v.w));
  ((uint2*)y)[i] = make_uint2(*reinterpret_cast<uint32_t*>(&a),
                              *reinterpret_cast<uint32_t*>(&b));
}

// ======== fp16 2-pass GEMM (A exact split, B single), cp.async 3-stage ======
// CTA tile 128x256, BK=32, 16 warps (2m x 8n, warp tile 64x32).
#define A_MAT (128 * 80)            // 10240 B
#define B_MAT (256 * 80)            // 20480 B
#define STG (2 * A_MAT + B_MAT)     // 40960 B
#define GSM (3 * STG)               // 122880 B
#define KDIM 2048

// mode 0: fused QKV (bn<8 Q fp32, 8..9 K fp32, 10..11 V fp16)
// mode 1: O proj (A = g_ahi/g_alo, B = g_wo16, C = outC fp32)
__global__ __launch_bounds__(512, 1) void gemm_f16(int mode, float* outC) {
  extern __shared__ char sm[];
  const uint32_t smb = smem_u32(sm);
  const int tid = threadIdx.x, wid = tid >> 5, lane = tid & 31;
  const int wm = wid & 1, wn = wid >> 1;
  const int bn = blockIdx.x, bm = blockIdx.y;
  const int i4 = lane >> 3, j8 = lane & 7;

  const __half *Abh, *Abl, *Bb;
  int colbase, dest;  // 0=Q fp32, 1=K fp32, 2=V fp16, 3=out fp32
  if (mode == 0) {
    Abh = g_hs_hi + (size_t)(bm * 128) * KDIM;
    Abl = g_hs_lo + (size_t)(bm * 128) * KDIM;
    if (bn < 8) {
      Bb = g_wq16 + (size_t)(bn * 256) * KDIM;
      colbase = bn * 256; dest = 0;
    } else if (bn < 10) {
      Bb = g_wk16 + (size_t)((bn - 8) * 256) * KDIM;
      colbase = (bn - 8) * 256; dest = 1;
    } else {
      Bb = g_wv16 + (size_t)((bn - 10) * 256) * KDIM;
      colbase = (bn - 10) * 256; dest = 2;
    }
  } else {
    Abh = g_ahi + (size_t)(bm * 128) * KDIM;
    Abl = g_alo + (size_t)(bm * 128) * KDIM;
    Bb = g_wo16 + (size_t)(bn * 256) * KDIM;
    colbase = bn * 256; dest = 3;
  }

  float ac[4][4][4];
#pragma unroll
  for (int mt = 0; mt < 4; mt++)
#pragma unroll
    for (int nt = 0; nt < 4; nt++)
#pragma unroll
      for (int q = 0; q < 4; q++) ac[mt][nt][q] = 0.f;

  auto issue = [&](int s, int k0) {
    const uint32_t st = smb + s * STG;
    {
      int r = tid >> 2, c = tid & 3;
      size_t go = (size_t)r * KDIM + k0 + c * 8;
      uint32_t so = (uint32_t)(r * 80 + c * 16);
      cp16(st + so, Abh + go);
      cp16(st + A_MAT + so, Abl + go);
    }
#pragma unroll
    for (int i = 0; i < 2; i++) {
      int e = i * 512 + tid;
      int r = e >> 2, c = e & 3;
      size_t go = (size_t)r * KDIM + k0 + c * 8;
      uint32_t so = (uint32_t)(r * 80 + c * 16);
      cp16(st + 2 * A_MAT + so, Bb + go);
    }
  };

  auto compute = [&](int s) {
    const uint32_t base = smb + s * STG;
#pragma unroll
    for (int ks = 0; ks < 2; ks++) {
      uint32_t af[2][4][4];
#pragma unroll
      for (int sp = 0; sp < 2; sp++)
#pragma unroll
        for (int mt = 0; mt < 4; mt++) {
          uint32_t addr = base + sp * A_MAT +
                          (uint32_t)(wm * 64 + mt * 16 + (i4 & 1) * 8 + j8) * 80 +
                          (uint32_t)((i4 >> 1) * 8 + ks * 16) * 2;
          ldsm4(addr, af[sp][mt]);
        }
      uint32_t bf[4][2];
#pragma unroll
      for (int p = 0; p < 2; p++) {
        uint32_t r[4];
        uint32_t addr = base + 2 * A_MAT +
                        (uint32_t)(wn * 32 + p * 16 + (i4 >> 1) * 8 + j8) * 80 +
                        (uint32_t)((i4 & 1) * 8 + ks * 16) * 2;
        ldsm4(addr, r);
        bf[2 * p][0] = r[0]; bf[2 * p][1] = r[1];
        bf[2 * p + 1][0] = r[2]; bf[2 * p + 1][1] = r[3];
      }
#pragma unroll
      for (int mt = 0; mt < 4; mt++)
#pragma unroll
        for (int nt = 0; nt < 4; nt++) {
          mmaf16(ac[mt][nt], af[0][mt], bf[nt][0], bf[nt][1]);
          mmaf16(ac[mt][nt], af[1][mt], bf[nt][0], bf[nt][1]);
        }
    }
  };

  const int KS = KDIM >> 5;  // 64
  issue(0, 0); cp_commit();
  issue(1, 32); cp_commit();

  for (int it = 0; it < KS; it++) {
    const int s = it % 3;
    cp_wait1();
    __syncthreads();
    if (it + 2 < KS) issue((it + 2) % 3, (it + 2) * 32);
    cp_commit();
    compute(s);
  }

  // epilogue
#pragma unroll
  for (int mt = 0; mt < 4; mt++)
#pragma unroll
    for (int nt = 0; nt < 4; nt++) {
      int row = bm * 128 + wm * 64 + mt * 16 + (lane >> 2);
      int col = colbase + wn * 32 + nt * 8 + (lane & 3) * 2;
      if (dest == 0) {
        float* c0 = g_q + (size_t)row * 2048 + col;
        *(float2*)c0 = make_float2(ac[mt][nt][0], ac[mt][nt][1]);
        *(float2*)(c0 + 8 * 2048) = make_float2(ac[mt][nt][2], ac[mt][nt][3]);
      } else if (dest == 1) {
        float* c0 = g_k + (size_t)row * 512 + col;
        *(float2*)c0 = make_float2(ac[mt][nt][0], ac[mt][nt][1]);
        *(float2*)(c0 + 8 * 512) = make_float2(ac[mt][nt][2], ac[mt][nt][3]);
      } else if (dest == 2) {
        size_t i0 = (size_t)row * 512 + col;
        size_t i1 = i0 + 8 * 512;
        __half2 v0 = __float22half2_rn(make_float2(ac[mt][nt][0], ac[mt][nt][1]));
        __half2 v1 = __float22half2_rn(make_float2(ac[mt][nt][2], ac[mt][nt][3]));
        *(__half2*)(g_v16 + i0) = v0;
        *(__half2*)(g_v16 + i1) = v1;
      } else {
        float* c0 = outC + (size_t)row * 2048 + col;
        *(float2*)c0 = make_float2(ac[mt][nt][0], ac[mt][nt][1]);
        *(float2*)(c0 + 8 * 2048) = make_float2(ac[mt][nt][2], ac[mt][nt][3]);
      }
    }
}

// =================== RoPE + RMSNorm -> fp16 out =============================
// write_lo=1: exact fp16 split (hi+lo). write_lo=0: single fp16 round.
__global__ __launch_bounds__(256) void rope_rms_f16(
    const float* __restrict__ x, const float* __restrict__ w,
    __half* __restrict__ hi, __half* __restrict__ lo,
    int nh, int total_warps, float osc, int write_lo) {
  int gw = (blockIdx.x * blockDim.x + threadIdx.x) >> 5;
  if (gw >= total_warps) return;
  int lane = threadIdx.x & 31;
  int token = gw / nh;
  int s = token & (Ss_ - 1);
  const float* p = x + (size_t)gw * HD_;

  const float neg_l2theta_over_half = -13.287712379549449f / 64.f;
  float vals[4];
  float ss = 0.f;
#pragma unroll
  for (int hh = 0; hh < 2; hh++) {
    int d = lane + hh * 32;
    float x1 = p[d];
    float x2 = p[d + 64];
    float invf = exp2f((float)d * neg_l2theta_over_half);
    float ang = (float)s * invf;
    float c, sn;
    sincosf(ang, &sn, &c);
    float o1 = x1 * c - x2 * sn;
    float o2 = x2 * c + x1 * sn;
    vals[hh * 2] = o1;
    vals[hh * 2 + 1] = o2;
    ss += o1 * o1 + o2 * o2;
  }
#pragma unroll
  for (int o = 16; o >= 1; o >>= 1) ss += __shfl_xor_sync(0xffffffffu, ss, o);
  float r = rsqrtf(ss * (1.f / 128.f) + 1e-6f) * osc;
#pragma unroll
  for (int hh = 0; hh < 2; hh++) {
    int d = lane + hh * 32;
    float v0 = vals[hh * 2] * r * w[d];
    float v1 = vals[hh * 2 + 1] * r * w[d + 64];
    size_t base = (size_t)gw * HD_;
    __half h0 = __float2half_rn(v0);
    __half h1 = __float2half_rn(v1);
    hi[base + d] = h0;
    hi[base + d + 64] = h1;
    if (write_lo) {
      lo[base + d] = __float2half_rn(v0 - __half2float(h0));
      lo[base + d + 64] = __float2half_rn(v1 - __half2float(h1));
    }
  }
}

// ================ Flash attention (fp16 2-pass mma) =========================
// smem: Qhi[128], Qlo[128], K[64], V[64] rows, pitch 272.
#define FPITCH 272
#define FQHI 0
#define FQLO (128 * FPITCH)
#define FK (2 * 128 * FPITCH)             // 69632
#define FV (FK + 64 * FPITCH)             // 87040
#define FA2_SMEM (FV + 64 * FPITCH)       // 104448

__global__ __launch_bounds__(256) void flash_attn_f16() {
  extern __shared__ char sm[];
  const uint32_t smb = smem_u32(sm);
  const int qt = blockIdx.x, h = blockIdx.y, b = blockIdx.z;
  const int kvh = h >> 2;
  const int tid = threadIdx.x, wid = tid >> 5, lane = tid & 31;
  const int i4 = lane >> 3, j8 = lane & 7;
  const int qb = qt * 128;
  const int qwb = qb + wid * 16;

  // ---- prologue: Q (pre-split, pre-scaled fp16) -> smem ----
  {
    const int row = tid >> 1, half = tid & 1;
    const size_t gof = (size_t)(b * Ss_ + qb + row) * (NH_ * HD_) + h * HD_ +
                       half * 64;
    const uint4* sh = (const uint4*)(g_q16h + gof);
    const uint4* sl = (const uint4*)(g_q16l + gof);
    char* dh = sm + FQHI + row * FPITCH + half * 128;
    char* dl = sm + FQLO + row * FPITCH + half * 128;
#pragma unroll
    for (int q = 0; q < 8; q++) {
      *(uint4*)(dh + q * 16) = sh[q];
      *(uint4*)(dl + q * 16) = sl[q];
    }
  }

  float oa[16][4];
#pragma unroll
  for (int nt = 0; nt < 16; nt++)
#pragma unroll
    for (int q = 0; q < 4; q++) oa[nt][q] = 0.f;
  float m0 = -INFINITY, m1 = -INFINITY, l0 = 0.f, l1 = 0.f;

  const uint32_t qa_off = (uint32_t)(wid * 16 + (i4 & 1) * 8 + j8) * FPITCH +
                          (uint32_t)((i4 >> 1) * 8) * 2;
  const uint32_t kb_row = (uint32_t)((i4 >> 1) * 8 + j8);
  const uint32_t kb_koff = (uint32_t)((i4 & 1) * 8) * 2;
  const uint32_t v_kv = (uint32_t)((i4 & 1) * 8 + j8);
  const uint32_t v_d = (uint32_t)((i4 >> 1) * 8);

  const int krow = tid >> 2, kqtr = tid & 3;

  const int nkv = 2 * qt + 2;
  for (int kvi = 0; kvi < nkv; kvi++) {
    const int kvb = kvi * 64;
    uint4 rk[4], rv[4];
    {
      const size_t gb = (size_t)(b * Ss_ + kvb + krow) * (NKV_ * HD_) +
                        kvh * HD_ + kqtr * 32;
#pragma unroll
      for (int q = 0; q < 4; q++) {
        rk[q] = ((const uint4*)(g_k16 + gb))[q];
        rv[q] = ((const uint4*)(g_v16 + gb))[q];
      }
    }
    __syncthreads();
    {
      char* kd = sm + FK + krow * FPITCH + kqtr * 64;
      char* vd = sm + FV + krow * FPITCH + kqtr * 64;
#pragma unroll
      for (int q = 0; q < 4; q++) {
        *(uint4*)(kd + q * 16) = rk[q];
        *(uint4*)(vd + q * 16) = rv[q];
      }
    }
    __syncthreads();

    if (kvb > qwb + 15) continue;

    float s4[8][4];
#pragma unroll
    for (int j = 0; j < 8; j++)
#pragma unroll
      for (int q = 0; q < 4; q++) s4[j][q] = 0.f;

#pragma unroll
    for (int kt = 0; kt < 8; kt++) {
      uint32_t aH[4], aL[4];
      ldsm4(smb + FQHI + qa_off + kt * 32, aH);
      ldsm4(smb + FQLO + qa_off + kt * 32, aL);
#pragma unroll
      for (int p = 0; p < 4; p++) {
        uint32_t rK[4];
        uint32_t ka = (uint32_t)(p * 16) * FPITCH + kb_row * FPITCH + kb_koff +
                      (uint32_t)(kt * 32);
        ldsm4(smb + FK + ka, rK);
        mmaf16(s4[2 * p],     aH, rK[0], rK[1]);
        mmaf16(s4[2 * p],     aL, rK[0], rK[1]);
        mmaf16(s4[2 * p + 1], aH, rK[2], rK[3]);
        mmaf16(s4[2 * p + 1], aL, rK[2], rK[3]);
      }
    }

    if (kvb + 63 > qwb) {
      const int qr0 = qwb + (lane >> 2), qr1 = qr0 + 8;
      const int kc0 = kvb + (lane & 3) * 2;
#pragma unroll
      for (int j = 0; j < 8; j++) {
        int kv0 = kc0 + j * 8, kv1 = kv0 + 1;
        if (kv0 > qr0) s4[j][0] = -1e30f;
        if (kv1 > qr0) s4[j][1] = -1e30f;
        if (kv0 > qr1) s4[j][2] = -1e30f;
        if (kv1 > qr1) s4[j][3] = -1e30f;
      }
    }

    float mx0 = -1e30f, mx1 = -1e30f;
#pragma unroll
    for (int j = 0; j < 8; j++) {
      mx0 = fmaxf(mx0, fmaxf(s4[j][0], s4[j][1]));
      mx1 = fmaxf(mx1, fmaxf(s4[j][2], s4[j][3]));
    }
    mx0 = fmaxf(mx0, __shfl_xor_sync(0xffffffffu, mx0, 1));
    mx0 = fmaxf(mx0, __shfl_xor_sync(0xffffffffu, mx0, 2));
    mx1 = fmaxf(mx1, __shfl_xor_sync(0xffffffffu, mx1, 1));
    mx1 = fmaxf(mx1, __shfl_xor_sync(0xffffffffu, mx1, 2));
    float mn0 = fmaxf(m0, mx0), mn1 = fmaxf(m1, mx1);
    float al0 = __expf(m0 - mn0), al1 = __expf(m1 - mn1);
    m0 = mn0; m1 = mn1;
    float sum0 = 0.f, sum1 = 0.f;
#pragma unroll
    for (int j = 0; j < 8; j++) {
      s4[j][0] = __expf(s4[j][0] - mn0);
      s4[j][1] = __expf(s4[j][1] - mn0);
      s4[j][2] = __expf(s4[j][2] - mn1);
      s4[j][3] = __expf(s4[j][3] - mn1);
      sum0 += s4[j][0] + s4[j][1];
      sum1 += s4[j][2] + s4[j][3];
    }
    sum0 += __shfl_xor_sync(0xffffffffu, sum0, 1);
    sum0 += __shfl_xor_sync(0xffffffffu, sum0, 2);
    sum1 += __shfl_xor_sync(0xffffffffu, sum1, 1);
    sum1 += __shfl_xor_sync(0xffffffffu, sum1, 2);
    l0 = l0 * al0 + sum0;
    l1 = l1 * al1 + sum1;
#pragma unroll
    for (int nt = 0; nt < 16; nt++) {
      oa[nt][0] *= al0; oa[nt][1] *= al0;
      oa[nt][2] *= al1; oa[nt][3] *= al1;
    }

    // P split (exact fp16 hi/lo), V single
#pragma unroll
    for (int kt = 0; kt < 4; kt++) {
      uint32_t aPh[4], aPl[4];
      pack_h2(s4[2 * kt][0], s4[2 * kt][1], aPh[0], aPl[0]);
      pack_h2(s4[2 * kt][2], s4[2 * kt][3], aPh[1], aPl[1]);
      pack_h2(s4[2 * kt + 1][0], s4[2 * kt + 1][1], aPh[2], aPl[2]);
      pack_h2(s4[2 * kt + 1][2], s4[2 * kt + 1][3], aPh[3], aPl[3]);
#pragma unroll
      for (int p = 0; p < 8; p++) {
        uint32_t rV[4];
        uint32_t va = (uint32_t)(kt * 16 + v_kv) * FPITCH +
                      (uint32_t)(p * 16 + v_d) * 2;
        ldsm4t(smb + FV + va, rV);
        mmaf16(oa[2 * p],     aPh, rV[0], rV[1]);
        mmaf16(oa[2 * p],     aPl, rV[0], rV[1]);
        mmaf16(oa[2 * p + 1], aPh, rV[2], rV[3]);
        mmaf16(oa[2 * p + 1], aPl, rV[2], rV[3]);
      }
    }
  }

  // epilogue: split-write attention output as fp16 hi/lo (exact split)
  const float inv0 = 1.0f / l0, inv1 = 1.0f / l1;
  const int r0 = qwb + (lane >> 2);
#pragma unroll
  for (int nt = 0; nt < 16; nt++) {
    int col = h * HD_ + nt * 8 + (lane & 3) * 2;
    size_t idx0 = (size_t)(b * Ss_ + r0) * (NH_ * HD_) + col;
    size_t idx1 = (size_t)(b * Ss_ + r0 + 8) * (NH_ * HD_) + col;
    uint32_t h0, lo0, h1, lo1;
    pack_h2(oa[nt][0] * inv0, oa[nt][1] * inv0, h0, lo0);
    pack_h2(oa[nt][2] * inv1, oa[nt][3] * inv1, h1, lo1);
    *(uint32_t*)(g_ahi + idx0) = h0;
    *(uint32_t*)(g_alo + idx0) = lo0;
    *(uint32_t*)(g_ahi + idx1) = h1;
    *(uint32_t*)(g_alo + idx1) = lo1;
  }
}

// ============================ launch ========================================
extern "C" void kernel_launch(void* const* d_in, const int* in_sizes, int n_in,
                              void* d_out, int out_size) {
  const float* hs = (const float*)d_in[0];
  const float* wq = (const float*)d_in[1];
  const float* wk = (const float*)d_in[2];
  const float* wv = (const float*)d_in[3];
  const float* wo = (const float*)d_in[4];
  const float* qw = (const float*)d_in[5];
  const float* kw = (const float*)d_in[6];
  float* out = (float*)d_out;

  void *pq, *pk, *pqh, *pql, *pk16;
  void *hsh, *hsl, *pwq, *pwk, *pwv, *pwo;
  cudaGetSymbolAddress(&pq, g_q);
  cudaGetSymbolAddress(&pk, g_k);
  cudaGetSymbolAddress(&pqh, g_q16h);
  cudaGetSymbolAddress(&pql, g_q16l);
  cudaGetSymbolAddress(&pk16, g_k16);
  cudaGetSymbolAddress(&hsh, g_hs_hi);
  cudaGetSymbolAddress(&hsl, g_hs_lo);
  cudaGetSymbolAddress(&pwq, g_wq16);
  cudaGetSymbolAddress(&pwk, g_wk16);
  cudaGetSymbolAddress(&pwv, g_wv16);
  cudaGetSymbolAddress(&pwo, g_wo16);

  cudaFuncSetAttribute(gemm_f16, cudaFuncAttributeMaxDynamicSharedMemorySize,
                       GSM);
  cudaFuncSetAttribute(flash_attn_f16,
                       cudaFuncAttributeMaxDynamicSharedMemorySize, FA2_SMEM);

  // prep: exact split of hs, fp16 round of weights
  {
    int n4;
    n4 = MTOK * Hh_ / 4;
    split_fp16<<<(n4 + 255) / 256, 256>>>(hs, (__half*)hsh, (__half*)hsl, n4);
    n4 = NH_ * HD_ * Hh_ / 4;
    round_fp16<<<(n4 + 255) / 256, 256>>>(wq, (__half*)pwq, n4);
    n4 = NKV_ * HD_ * Hh_ / 4;
    round_fp16<<<(n4 + 255) / 256, 256>>>(wk, (__half*)pwk, n4);
    round_fp16<<<(n4 + 255) / 256, 256>>>(wv, (__half*)pwv, n4);
    n4 = Hh_ * NH_ * HD_ / 4;
    round_fp16<<<(n4 + 255) / 256, 256>>>(wo, (__half*)pwo, n4);
  }

  // Fused Q+K+V projections (fp16 2-pass)
  gemm_f16<<<dim3(12, MTOK / 128), 512, GSM>>>(0, nullptr);

  // RoPE + RMSNorm (q: exact fp16 split, pre-scaled; k: single fp16)
  rope_rms_f16<<<(MTOK * NH_) / 8, 256>>>(
      (const float*)pq, qw, (__half*)pqh, (__half*)pql, NH_, MTOK * NH_,
      0.08838834764831845f, 1);
  rope_rms_f16<<<(MTOK * NKV_) / 8, 256>>>(
      (const float*)pk, kw, (__half*)pk16, nullptr, NKV_, MTOK * NKV_, 1.0f, 0);

  flash_attn_f16<<<dim3(Ss_ / 128, NH_, Bb_), 256, FA2_SMEM>>>();

  // Output projection (fp16 2-pass) -> d_out
  gemm_f16<<<dim3(Hh_ / 256, MTOK / 128), 512, GSM>>>(1, out);
}

// round 9
// speedup vs baseline: 5.2327x; 1.3263x over previous
#include <cuda_runtime.h>
#include <cuda_fp16.h>
#include <math.h>
#include <stdint.h>

#define Bb_ 2
#define Ss_ 2048
#define Hh_ 2048
#define NH_ 16
#define NKV_ 4
#define HD_ 128
#define MTOK (Bb_ * Ss_)   // 4096 tokens

// Scratch (allocation-free rule: __device__ globals)
__device__ float g_q[(size_t)MTOK * NH_ * HD_];    // fp32 pre-rope Q
__device__ float g_k[(size_t)MTOK * NKV_ * HD_];   // fp32 pre-rope K
// fp16 GEMM operands (single-rounded)
__device__ __half g_hs16[(size_t)MTOK * Hh_];
__device__ __half g_wq16[(size_t)NH_ * HD_ * Hh_];
__device__ __half g_wk16[(size_t)NKV_ * HD_ * Hh_];
__device__ __half g_wv16[(size_t)NKV_ * HD_ * Hh_];
// attention inputs (fp16)
__device__ __half g_q16h[(size_t)MTOK * NH_ * HD_];
__device__ __half g_q16l[(size_t)MTOK * NH_ * HD_];
__device__ __half g_k16[(size_t)MTOK * NKV_ * HD_];
__device__ __half g_v16[(size_t)MTOK * NKV_ * HD_];
// O-proj operands (fp16 1-pass)
__device__ __half g_wo16[(size_t)Hh_ * NH_ * HD_];
__device__ __half g_a16[(size_t)MTOK * NH_ * HD_];

// ============================ helpers =======================================
__device__ __forceinline__ uint32_t smem_u32(const void* p) {
  uint32_t a;
  asm("{ .reg .u64 t; cvta.to.shared.u64 t, %1; cvt.u32.u64 %0, t; }"
      : "=r"(a) : "l"(p));
  return a;
}
__device__ __forceinline__ void cp16(uint32_t dst, const void* src) {
  asm volatile("cp.async.cg.shared.global [%0], [%1], 16;"
               :: "r"(dst), "l"(src));
}
__device__ __forceinline__ void cp_commit() {
  asm volatile("cp.async.commit_group;" ::: "memory");
}
__device__ __forceinline__ void cp_wait1() {
  asm volatile("cp.async.wait_group 1;" ::: "memory");
}
__device__ __forceinline__ void ldsm4(uint32_t addr, uint32_t r[4]) {
  asm volatile("ldmatrix.sync.aligned.m8n8.x4.shared.b16 {%0,%1,%2,%3}, [%4];"
               : "=r"(r[0]), "=r"(r[1]), "=r"(r[2]), "=r"(r[3]) : "r"(addr));
}
__device__ __forceinline__ void ldsm4t(uint32_t addr, uint32_t r[4]) {
  asm volatile(
      "ldmatrix.sync.aligned.m8n8.x4.trans.shared.b16 {%0,%1,%2,%3}, [%4];"
      : "=r"(r[0]), "=r"(r[1]), "=r"(r[2]), "=r"(r[3]) : "r"(addr));
}
__device__ __forceinline__ void mmaf16(float c[4], const uint32_t a[4],
                                       uint32_t b0, uint32_t b1) {
  asm volatile(
      "mma.sync.aligned.m16n8k16.row.col.f32.f16.f16.f32 "
      "{%0,%1,%2,%3}, {%4,%5,%6,%7}, {%8,%9}, {%0,%1,%2,%3};"
      : "+f"(c[0]), "+f"(c[1]), "+f"(c[2]), "+f"(c[3])
      : "r"(a[0]), "r"(a[1]), "r"(a[2]), "r"(a[3]), "r"(b0), "r"(b1));
}
__device__ __forceinline__ void pack_h2(float x, float y, uint32_t& h,
                                        uint32_t& l) {
  __half2 hb = __float22half2_rn(make_float2(x, y));
  float2 hf = __half22float2(hb);
  __half2 lb = __float22half2_rn(make_float2(x - hf.x, y - hf.y));
  h = *reinterpret_cast<uint32_t*>(&hb);
  l = *reinterpret_cast<uint32_t*>(&lb);
}

// ============================ prep kernel ===================================
__global__ __launch_bounds__(256) void round_fp16(
    const float* __restrict__ x, __half* __restrict__ y, int n4) {
  int i = blockIdx.x * blockDim.x + threadIdx.x;
  if (i >= n4) return;
  float4 v = ((const float4*)x)[i];
  __half2 a = __float22half2_rn(make_float2(v.x, v.y));
  __half2 b = __float22half2_rn(make_float2(v.z, v.w));
  ((uint2*)y)[i] = make_uint2(*reinterpret_cast<uint32_t*>(&a),
                              *reinterpret_cast<uint32_t*>(&b));
}

// ============ fp16 1-pass GEMM, cp.async 3-stage, 512 threads ===============
// CTA tile 128x256, BK=32, 16 warps (2m x 8n, warp tile 64x32).
#define A_MAT (128 * 80)            // 10240 B
#define B_MAT (256 * 80)            // 20480 B
#define STG (A_MAT + B_MAT)         // 30720 B
#define GSM (3 * STG)               // 92160 B
#define KDIM 2048

// mode 0: fused QKV (bn<8 Q fp32, 8..9 K fp32, 10..11 V fp16)
// mode 1: O proj (A = g_a16, B = g_wo16, C = outC fp32)
__global__ __launch_bounds__(512, 1) void gemm_f16(int mode, float* outC) {
  extern __shared__ char sm[];
  const uint32_t smb = smem_u32(sm);
  const int tid = threadIdx.x, wid = tid >> 5, lane = tid & 31;
  const int wm = wid & 1, wn = wid >> 1;
  const int bn = blockIdx.x, bm = blockIdx.y;
  const int i4 = lane >> 3, j8 = lane & 7;

  const __half *Ab, *Bb;
  int colbase, dest;  // 0=Q fp32, 1=K fp32, 2=V fp16, 3=out fp32
  if (mode == 0) {
    Ab = g_hs16 + (size_t)(bm * 128) * KDIM;
    if (bn < 8) {
      Bb = g_wq16 + (size_t)(bn * 256) * KDIM;
      colbase = bn * 256; dest = 0;
    } else if (bn < 10) {
      Bb = g_wk16 + (size_t)((bn - 8) * 256) * KDIM;
      colbase = (bn - 8) * 256; dest = 1;
    } else {
      Bb = g_wv16 + (size_t)((bn - 10) * 256) * KDIM;
      colbase = (bn - 10) * 256; dest = 2;
    }
  } else {
    Ab = g_a16 + (size_t)(bm * 128) * KDIM;
    Bb = g_wo16 + (size_t)(bn * 256) * KDIM;
    colbase = bn * 256; dest = 3;
  }

  float ac[4][4][4];
#pragma unroll
  for (int mt = 0; mt < 4; mt++)
#pragma unroll
    for (int nt = 0; nt < 4; nt++)
#pragma unroll
      for (int q = 0; q < 4; q++) ac[mt][nt][q] = 0.f;

  auto issue = [&](int s, int k0) {
    const uint32_t st = smb + s * STG;
    {
      int r = tid >> 2, c = tid & 3;
      size_t go = (size_t)r * KDIM + k0 + c * 8;
      uint32_t so = (uint32_t)(r * 80 + c * 16);
      cp16(st + so, Ab + go);
    }
#pragma unroll
    for (int i = 0; i < 2; i++) {
      int e = i * 512 + tid;
      int r = e >> 2, c = e & 3;
      size_t go = (size_t)r * KDIM + k0 + c * 8;
      uint32_t so = (uint32_t)(r * 80 + c * 16);
      cp16(st + A_MAT + so, Bb + go);
    }
  };

  auto compute = [&](int s) {
    const uint32_t base = smb + s * STG;
#pragma unroll
    for (int ks = 0; ks < 2; ks++) {
      uint32_t af[4][4];
#pragma unroll
      for (int mt = 0; mt < 4; mt++) {
        uint32_t addr = base +
                        (uint32_t)(wm * 64 + mt * 16 + (i4 & 1) * 8 + j8) * 80 +
                        (uint32_t)((i4 >> 1) * 8 + ks * 16) * 2;
        ldsm4(addr, af[mt]);
      }
      uint32_t bf[4][2];
#pragma unroll
      for (int p = 0; p < 2; p++) {
        uint32_t r[4];
        uint32_t addr = base + A_MAT +
                        (uint32_t)(wn * 32 + p * 16 + (i4 >> 1) * 8 + j8) * 80 +
                        (uint32_t)((i4 & 1) * 8 + ks * 16) * 2;
        ldsm4(addr, r);
        bf[2 * p][0] = r[0]; bf[2 * p][1] = r[1];
        bf[2 * p + 1][0] = r[2]; bf[2 * p + 1][1] = r[3];
      }
#pragma unroll
      for (int mt = 0; mt < 4; mt++)
#pragma unroll
        for (int nt = 0; nt < 4; nt++)
          mmaf16(ac[mt][nt], af[mt], bf[nt][0], bf[nt][1]);
    }
  };

  const int KS = KDIM >> 5;  // 64
  issue(0, 0); cp_commit();
  issue(1, 32); cp_commit();

  for (int it = 0; it < KS; it++) {
    const int s = it % 3;
    cp_wait1();
    __syncthreads();
    if (it + 2 < KS) issue((it + 2) % 3, (it + 2) * 32);
    cp_commit();
    compute(s);
  }

  // epilogue
#pragma unroll
  for (int mt = 0; mt < 4; mt++)
#pragma unroll
    for (int nt = 0; nt < 4; nt++) {
      int row = bm * 128 + wm * 64 + mt * 16 + (lane >> 2);
      int col = colbase + wn * 32 + nt * 8 + (lane & 3) * 2;
      if (dest == 0) {
        float* c0 = g_q + (size_t)row * 2048 + col;
        *(float2*)c0 = make_float2(ac[mt][nt][0], ac[mt][nt][1]);
        *(float2*)(c0 + 8 * 2048) = make_float2(ac[mt][nt][2], ac[mt][nt][3]);
      } else if (dest == 1) {
        float* c0 = g_k + (size_t)row * 512 + col;
        *(float2*)c0 = make_float2(ac[mt][nt][0], ac[mt][nt][1]);
        *(float2*)(c0 + 8 * 512) = make_float2(ac[mt][nt][2], ac[mt][nt][3]);
      } else if (dest == 2) {
        size_t i0 = (size_t)row * 512 + col;
        size_t i1 = i0 + 8 * 512;
        __half2 v0 = __float22half2_rn(make_float2(ac[mt][nt][0], ac[mt][nt][1]));
        __half2 v1 = __float22half2_rn(make_float2(ac[mt][nt][2], ac[mt][nt][3]));
        *(__half2*)(g_v16 + i0) = v0;
        *(__half2*)(g_v16 + i1) = v1;
      } else {
        float* c0 = outC + (size_t)row * 2048 + col;
        *(float2*)c0 = make_float2(ac[mt][nt][0], ac[mt][nt][1]);
        *(float2*)(c0 + 8 * 2048) = make_float2(ac[mt][nt][2], ac[mt][nt][3]);
      }
    }
}

// =================== RoPE + RMSNorm -> fp16 out =============================
__global__ __launch_bounds__(256) void rope_rms_f16(
    const float* __restrict__ x, const float* __restrict__ w,
    __half* __restrict__ hi, __half* __restrict__ lo,
    int nh, int total_warps, float osc, int write_lo) {
  int gw = (blockIdx.x * blockDim.x + threadIdx.x) >> 5;
  if (gw >= total_warps) return;
  int lane = threadIdx.x & 31;
  int token = gw / nh;
  int s = token & (Ss_ - 1);
  const float* p = x + (size_t)gw * HD_;

  const float neg_l2theta_over_half = -13.287712379549449f / 64.f;
  float vals[4];
  float ss = 0.f;
#pragma unroll
  for (int hh = 0; hh < 2; hh++) {
    int d = lane + hh * 32;
    float x1 = p[d];
    float x2 = p[d + 64];
    float invf = exp2f((float)d * neg_l2theta_over_half);
    float ang = (float)s * invf;
    float c, sn;
    sincosf(ang, &sn, &c);
    float o1 = x1 * c - x2 * sn;
    float o2 = x2 * c + x1 * sn;
    vals[hh * 2] = o1;
    vals[hh * 2 + 1] = o2;
    ss += o1 * o1 + o2 * o2;
  }
#pragma unroll
  for (int o = 16; o >= 1; o >>= 1) ss += __shfl_xor_sync(0xffffffffu, ss, o);
  float r = rsqrtf(ss * (1.f / 128.f) + 1e-6f) * osc;
#pragma unroll
  for (int hh = 0; hh < 2; hh++) {
    int d = lane + hh * 32;
    float v0 = vals[hh * 2] * r * w[d];
    float v1 = vals[hh * 2 + 1] * r * w[d + 64];
    size_t base = (size_t)gw * HD_;
    __half h0 = __float2half_rn(v0);
    __half h1 = __float2half_rn(v1);
    hi[base + d] = h0;
    hi[base + d + 64] = h1;
    if (write_lo) {
      lo[base + d] = __float2half_rn(v0 - __half2float(h0));
      lo[base + d + 64] = __float2half_rn(v1 - __half2float(h1));
    }
  }
}

// ================ Flash attention (fp16 2-pass mma) =========================
#define FPITCH 272
#define FQHI 0
#define FQLO (128 * FPITCH)
#define FK (2 * 128 * FPITCH)             // 69632
#define FV (FK + 64 * FPITCH)             // 87040
#define FA2_SMEM (FV + 64 * FPITCH)       // 104448

__global__ __launch_bounds__(256) void flash_attn_f16() {
  extern __shared__ char sm[];
  const uint32_t smb = smem_u32(sm);
  const int qt = blockIdx.x, h = blockIdx.y, b = blockIdx.z;
  const int kvh = h >> 2;
  const int tid = threadIdx.x, wid = tid >> 5, lane = tid & 31;
  const int i4 = lane >> 3, j8 = lane & 7;
  const int qb = qt * 128;
  const int qwb = qb + wid * 16;

  // ---- prologue: Q (pre-split, pre-scaled fp16) -> smem ----
  {
    const int row = tid >> 1, half = tid & 1;
    const size_t gof = (size_t)(b * Ss_ + qb + row) * (NH_ * HD_) + h * HD_ +
                       half * 64;
    const uint4* sh = (const uint4*)(g_q16h + gof);
    const uint4* sl = (const uint4*)(g_q16l + gof);
    char* dh = sm + FQHI + row * FPITCH + half * 128;
    char* dl = sm + FQLO + row * FPITCH + half * 128;
#pragma unroll
    for (int q = 0; q < 8; q++) {
      *(uint4*)(dh + q * 16) = sh[q];
      *(uint4*)(dl + q * 16) = sl[q];
    }
  }

  float oa[16][4];
#pragma unroll
  for (int nt = 0; nt < 16; nt++)
#pragma unroll
    for (int q = 0; q < 4; q++) oa[nt][q] = 0.f;
  float m0 = -INFINITY, m1 = -INFINITY, l0 = 0.f, l1 = 0.f;

  const uint32_t qa_off = (uint32_t)(wid * 16 + (i4 & 1) * 8 + j8) * FPITCH +
                          (uint32_t)((i4 >> 1) * 8) * 2;
  const uint32_t kb_row = (uint32_t)((i4 >> 1) * 8 + j8);
  const uint32_t kb_koff = (uint32_t)((i4 & 1) * 8) * 2;
  const uint32_t v_kv = (uint32_t)((i4 & 1) * 8 + j8);
  const uint32_t v_d = (uint32_t)((i4 >> 1) * 8);

  const int krow = tid >> 2, kqtr = tid & 3;

  const int nkv = 2 * qt + 2;
  for (int kvi = 0; kvi < nkv; kvi++) {
    const int kvb = kvi * 64;
    uint4 rk[4], rv[4];
    {
      const size_t gb = (size_t)(b * Ss_ + kvb + krow) * (NKV_ * HD_) +
                        kvh * HD_ + kqtr * 32;
#pragma unroll
      for (int q = 0; q < 4; q++) {
        rk[q] = ((const uint4*)(g_k16 + gb))[q];
        rv[q] = ((const uint4*)(g_v16 + gb))[q];
      }
    }
    __syncthreads();
    {
      char* kd = sm + FK + krow * FPITCH + kqtr * 64;
      char* vd = sm + FV + krow * FPITCH + kqtr * 64;
#pragma unroll
      for (int q = 0; q < 4; q++) {
        *(uint4*)(kd + q * 16) = rk[q];
        *(uint4*)(vd + q * 16) = rv[q];
      }
    }
    __syncthreads();

    if (kvb > qwb + 15) continue;

    float s4[8][4];
#pragma unroll
    for (int j = 0; j < 8; j++)
#pragma unroll
      for (int q = 0; q < 4; q++) s4[j][q] = 0.f;

#pragma unroll
    for (int kt = 0; kt < 8; kt++) {
      uint32_t aH[4], aL[4];
      ldsm4(smb + FQHI + qa_off + kt * 32, aH);
      ldsm4(smb + FQLO + qa_off + kt * 32, aL);
#pragma unroll
      for (int p = 0; p < 4; p++) {
        uint32_t rK[4];
        uint32_t ka = (uint32_t)(p * 16) * FPITCH + kb_row * FPITCH + kb_koff +
                      (uint32_t)(kt * 32);
        ldsm4(smb + FK + ka, rK);
        mmaf16(s4[2 * p],     aH, rK[0], rK[1]);
        mmaf16(s4[2 * p],     aL, rK[0], rK[1]);
        mmaf16(s4[2 * p + 1], aH, rK[2], rK[3]);
        mmaf16(s4[2 * p + 1], aL, rK[2], rK[3]);
      }
    }

    if (kvb + 63 > qwb) {
      const int qr0 = qwb + (lane >> 2), qr1 = qr0 + 8;
      const int kc0 = kvb + (lane & 3) * 2;
#pragma unroll
      for (int j = 0; j < 8; j++) {
        int kv0 = kc0 + j * 8, kv1 = kv0 + 1;
        if (kv0 > qr0) s4[j][0] = -1e30f;
        if (kv1 > qr0) s4[j][1] = -1e30f;
        if (kv0 > qr1) s4[j][2] = -1e30f;
        if (kv1 > qr1) s4[j][3] = -1e30f;
      }
    }

    float mx0 = -1e30f, mx1 = -1e30f;
#pragma unroll
    for (int j = 0; j < 8; j++) {
      mx0 = fmaxf(mx0, fmaxf(s4[j][0], s4[j][1]));
      mx1 = fmaxf(mx1, fmaxf(s4[j][2], s4[j][3]));
    }
    mx0 = fmaxf(mx0, __shfl_xor_sync(0xffffffffu, mx0, 1));
    mx0 = fmaxf(mx0, __shfl_xor_sync(0xffffffffu, mx0, 2));
    mx1 = fmaxf(mx1, __shfl_xor_sync(0xffffffffu, mx1, 1));
    mx1 = fmaxf(mx1, __shfl_xor_sync(0xffffffffu, mx1, 2));
    float mn0 = fmaxf(m0, mx0), mn1 = fmaxf(m1, mx1);
    float al0 = __expf(m0 - mn0), al1 = __expf(m1 - mn1);
    m0 = mn0; m1 = mn1;
    float sum0 = 0.f, sum1 = 0.f;
#pragma unroll
    for (int j = 0; j < 8; j++) {
      s4[j][0] = __expf(s4[j][0] - mn0);
      s4[j][1] = __expf(s4[j][1] - mn0);
      s4[j][2] = __expf(s4[j][2] - mn1);
      s4[j][3] = __expf(s4[j][3] - mn1);
      sum0 += s4[j][0] + s4[j][1];
      sum1 += s4[j][2] + s4[j][3];
    }
    sum0 += __shfl_xor_sync(0xffffffffu, sum0, 1);
    sum0 += __shfl_xor_sync(0xffffffffu, sum0, 2);
    sum1 += __shfl_xor_sync(0xffffffffu, sum1, 1);
    sum1 += __shfl_xor_sync(0xffffffffu, sum1, 2);
    l0 = l0 * al0 + sum0;
    l1 = l1 * al1 + sum1;
#pragma unroll
    for (int nt = 0; nt < 16; nt++) {
      oa[nt][0] *= al0; oa[nt][1] *= al0;
      oa[nt][2] *= al1; oa[nt][3] *= al1;
    }

    // P split (exact fp16 hi/lo), V single
#pragma unroll
    for (int kt = 0; kt < 4; kt++) {
      uint32_t aPh[4], aPl[4];
      pack_h2(s4[2 * kt][0], s4[2 * kt][1], aPh[0], aPl[0]);
      pack_h2(s4[2 * kt][2], s4[2 * kt][3], aPh[1], aPl[1]);
      pack_h2(s4[2 * kt + 1][0], s4[2 * kt + 1][1], aPh[2], aPl[2]);
      pack_h2(s4[2 * kt + 1][2], s4[2 * kt + 1][3], aPh[3], aPl[3]);
#pragma unroll
      for (int p = 0; p < 8; p++) {
        uint32_t rV[4];
        uint32_t va = (uint32_t)(kt * 16 + v_kv) * FPITCH +
                      (uint32_t)(p * 16 + v_d) * 2;
        ldsm4t(smb + FV + va, rV);
        mmaf16(oa[2 * p],     aPh, rV[0], rV[1]);
        mmaf16(oa[2 * p],     aPl, rV[0], rV[1]);
        mmaf16(oa[2 * p + 1], aPh, rV[2], rV[3]);
        mmaf16(oa[2 * p + 1], aPl, rV[2], rV[3]);
      }
    }
  }

  // epilogue: attention output as single fp16
  const float inv0 = 1.0f / l0, inv1 = 1.0f / l1;
  const int r0 = qwb + (lane >> 2);
#pragma unroll
  for (int nt = 0; nt < 16; nt++) {
    int col = h * HD_ + nt * 8 + (lane & 3) * 2;
    size_t idx0 = (size_t)(b * Ss_ + r0) * (NH_ * HD_) + col;
    size_t idx1 = (size_t)(b * Ss_ + r0 + 8) * (NH_ * HD_) + col;
    __half2 o0 = __float22half2_rn(make_float2(oa[nt][0] * inv0,
                                               oa[nt][1] * inv0));
    __half2 o1 = __float22half2_rn(make_float2(oa[nt][2] * inv1,
                                               oa[nt][3] * inv1));
    *(__half2*)(g_a16 + idx0) = o0;
    *(__half2*)(g_a16 + idx1) = o1;
  }
}

// ============================ launch ========================================
extern "C" void kernel_launch(void* const* d_in, const int* in_sizes, int n_in,
                              void* d_out, int out_size) {
  const float* hs = (const float*)d_in[0];
  const float* wq = (const float*)d_in[1];
  const float* wk = (const float*)d_in[2];
  const float* wv = (const float*)d_in[3];
  const float* wo = (const float*)d_in[4];
  const float* qw = (const float*)d_in[5];
  const float* kw = (const float*)d_in[6];
  float* out = (float*)d_out;

  void *pq, *pk, *pqh, *pql, *pk16;
  void *phs, *pwq, *pwk, *pwv, *pwo;
  cudaGetSymbolAddress(&pq, g_q);
  cudaGetSymbolAddress(&pk, g_k);
  cudaGetSymbolAddress(&pqh, g_q16h);
  cudaGetSymbolAddress(&pql, g_q16l);
  cudaGetSymbolAddress(&pk16, g_k16);
  cudaGetSymbolAddress(&phs, g_hs16);
  cudaGetSymbolAddress(&pwq, g_wq16);
  cudaGetSymbolAddress(&pwk, g_wk16);
  cudaGetSymbolAddress(&pwv, g_wv16);
  cudaGetSymbolAddress(&pwo, g_wo16);

  cudaFuncSetAttribute(gemm_f16, cudaFuncAttributeMaxDynamicSharedMemorySize,
                       GSM);
  cudaFuncSetAttribute(flash_attn_f16,
                       cudaFuncAttributeMaxDynamicSharedMemorySize, FA2_SMEM);

  // prep: single fp16 rounding of hs + weights
  {
    int n4;
    n4 = MTOK * Hh_ / 4;
    round_fp16<<<(n4 + 255) / 256, 256>>>(hs, (__half*)phs, n4);
    n4 = NH_ * HD_ * Hh_ / 4;
    round_fp16<<<(n4 + 255) / 256, 256>>>(wq, (__half*)pwq, n4);
    n4 = NKV_ * HD_ * Hh_ / 4;
    round_fp16<<<(n4 + 255) / 256, 256>>>(wk, (__half*)pwk, n4);
    round_fp16<<<(n4 + 255) / 256, 256>>>(wv, (__half*)pwv, n4);
    n4 = Hh_ * NH_ * HD_ / 4;
    round_fp16<<<(n4 + 255) / 256, 256>>>(wo, (__half*)pwo, n4);
  }

  // Fused Q+K+V projections (fp16 1-pass)
  gemm_f16<<<dim3(12, MTOK / 128), 512, GSM>>>(0, nullptr);

  // RoPE + RMSNorm (q: exact fp16 split, pre-scaled; k: single fp16)
  rope_rms_f16<<<(MTOK * NH_) / 8, 256>>>(
      (const float*)pq, qw, (__half*)pqh, (__half*)pql, NH_, MTOK * NH_,
      0.08838834764831845f, 1);
  rope_rms_f16<<<(MTOK * NKV_) / 8, 256>>>(
      (const float*)pk, kw, (__half*)pk16, nullptr, NKV_, MTOK * NKV_, 1.0f, 0);

  flash_attn_f16<<<dim3(Ss_ / 128, NH_, Bb_), 256, FA2_SMEM>>>();

  // Output projection (fp16 1-pass) -> d_out
  gemm_f16<<<dim3(Hh_ / 256, MTOK / 128), 512, GSM>>>(1, out);
}

// round 10
// speedup vs baseline: 6.1205x; 1.1697x over previous
#include <cuda_runtime.h>
#include <cuda_fp16.h>
#include <math.h>
#include <stdint.h>

#define Bb_ 2
#define Ss_ 2048
#define Hh_ 2048
#define NH_ 16
#define NKV_ 4
#define HD_ 128
#define MTOK (Bb_ * Ss_)   // 4096 tokens

// Scratch (allocation-free rule: __device__ globals)
__device__ float g_q[(size_t)MTOK * NH_ * HD_];    // fp32 pre-rope Q
__device__ float g_k[(size_t)MTOK * NKV_ * HD_];   // fp32 pre-rope K
// fp16 GEMM operands (single-rounded)
__device__ __half g_hs16[(size_t)MTOK * Hh_];
__device__ __half g_wq16[(size_t)NH_ * HD_ * Hh_];
__device__ __half g_wk16[(size_t)NKV_ * HD_ * Hh_];
__device__ __half g_wv16[(size_t)NKV_ * HD_ * Hh_];
// attention inputs (fp16, single)
__device__ __half g_q16[(size_t)MTOK * NH_ * HD_];
__device__ __half g_k16[(size_t)MTOK * NKV_ * HD_];
__device__ __half g_v16[(size_t)MTOK * NKV_ * HD_];
// O-proj operands (fp16 1-pass)
__device__ __half g_wo16[(size_t)Hh_ * NH_ * HD_];
__device__ __half g_a16[(size_t)MTOK * NH_ * HD_];

// ============================ helpers =======================================
__device__ __forceinline__ uint32_t smem_u32(const void* p) {
  uint32_t a;
  asm("{ .reg .u64 t; cvta.to.shared.u64 t, %1; cvt.u32.u64 %0, t; }"
      : "=r"(a) : "l"(p));
  return a;
}
__device__ __forceinline__ void cp16(uint32_t dst, const void* src) {
  asm volatile("cp.async.cg.shared.global [%0], [%1], 16;"
               :: "r"(dst), "l"(src));
}
__device__ __forceinline__ void cp_commit() {
  asm volatile("cp.async.commit_group;" ::: "memory");
}
__device__ __forceinline__ void cp_wait1() {
  asm volatile("cp.async.wait_group 1;" ::: "memory");
}
__device__ __forceinline__ void ldsm4(uint32_t addr, uint32_t r[4]) {
  asm volatile("ldmatrix.sync.aligned.m8n8.x4.shared.b16 {%0,%1,%2,%3}, [%4];"
               : "=r"(r[0]), "=r"(r[1]), "=r"(r[2]), "=r"(r[3]) : "r"(addr));
}
__device__ __forceinline__ void ldsm4t(uint32_t addr, uint32_t r[4]) {
  asm volatile(
      "ldmatrix.sync.aligned.m8n8.x4.trans.shared.b16 {%0,%1,%2,%3}, [%4];"
      : "=r"(r[0]), "=r"(r[1]), "=r"(r[2]), "=r"(r[3]) : "r"(addr));
}
__device__ __forceinline__ void mmaf16(float c[4], const uint32_t a[4],
                                       uint32_t b0, uint32_t b1) {
  asm volatile(
      "mma.sync.aligned.m16n8k16.row.col.f32.f16.f16.f32 "
      "{%0,%1,%2,%3}, {%4,%5,%6,%7}, {%8,%9}, {%0,%1,%2,%3};"
      : "+f"(c[0]), "+f"(c[1]), "+f"(c[2]), "+f"(c[3])
      : "r"(a[0]), "r"(a[1]), "r"(a[2]), "r"(a[3]), "r"(b0), "r"(b1));
}

// ============================ prep kernel (merged) ==========================
// Segments: hs, wq, wk, wv, wo (float4 groups)
#define N4_HS (MTOK * Hh_ / 4)            // 2M
#define N4_WQ (NH_ * HD_ * Hh_ / 4)       // 1M
#define N4_WKV (NKV_ * HD_ * Hh_ / 4)     // 256K
#define N4_TOT (N4_HS + N4_WQ + 2 * N4_WKV + N4_WQ)

__global__ __launch_bounds__(256) void round_all(
    const float* __restrict__ hs, const float* __restrict__ wq,
    const float* __restrict__ wk, const float* __restrict__ wv,
    const float* __restrict__ wo) {
  int i = blockIdx.x * blockDim.x + threadIdx.x;
  if (i >= N4_TOT) return;
  const float* src;
  __half* dst;
  int off;
  if (i < N4_HS) {
    src = hs; dst = g_hs16; off = i;
  } else if (i < N4_HS + N4_WQ) {
    src = wq; dst = g_wq16; off = i - N4_HS;
  } else if (i < N4_HS + N4_WQ + N4_WKV) {
    src = wk; dst = g_wk16; off = i - N4_HS - N4_WQ;
  } else if (i < N4_HS + N4_WQ + 2 * N4_WKV) {
    src = wv; dst = g_wv16; off = i - N4_HS - N4_WQ - N4_WKV;
  } else {
    src = wo; dst = g_wo16; off = i - N4_HS - N4_WQ - 2 * N4_WKV;
  }
  float4 v = ((const float4*)src)[off];
  __half2 a = __float22half2_rn(make_float2(v.x, v.y));
  __half2 b = __float22half2_rn(make_float2(v.z, v.w));
  ((uint2*)dst)[off] = make_uint2(*reinterpret_cast<uint32_t*>(&a),
                                  *reinterpret_cast<uint32_t*>(&b));
}

// ============ fp16 1-pass GEMM, cp.async 3-stage, 512 threads ===============
#define A_MAT (128 * 80)            // 10240 B
#define B_MAT (256 * 80)            // 20480 B
#define STG (A_MAT + B_MAT)         // 30720 B
#define GSM (3 * STG)               // 92160 B
#define KDIM 2048

// mode 0: fused QKV (bn<8 Q fp32, 8..9 K fp32, 10..11 V fp16)
// mode 1: O proj (A = g_a16, B = g_wo16, C = outC fp32)
__global__ __launch_bounds__(512, 1) void gemm_f16(int mode, float* outC) {
  extern __shared__ char sm[];
  const uint32_t smb = smem_u32(sm);
  const int tid = threadIdx.x, wid = tid >> 5, lane = tid & 31;
  const int wm = wid & 1, wn = wid >> 1;
  const int bn = blockIdx.x, bm = blockIdx.y;
  const int i4 = lane >> 3, j8 = lane & 7;

  const __half *Ab, *Bb;
  int colbase, dest;  // 0=Q fp32, 1=K fp32, 2=V fp16, 3=out fp32
  if (mode == 0) {
    Ab = g_hs16 + (size_t)(bm * 128) * KDIM;
    if (bn < 8) {
      Bb = g_wq16 + (size_t)(bn * 256) * KDIM;
      colbase = bn * 256; dest = 0;
    } else if (bn < 10) {
      Bb = g_wk16 + (size_t)((bn - 8) * 256) * KDIM;
      colbase = (bn - 8) * 256; dest = 1;
    } else {
      Bb = g_wv16 + (size_t)((bn - 10) * 256) * KDIM;
      colbase = (bn - 10) * 256; dest = 2;
    }
  } else {
    Ab = g_a16 + (size_t)(bm * 128) * KDIM;
    Bb = g_wo16 + (size_t)(bn * 256) * KDIM;
    colbase = bn * 256; dest = 3;
  }

  float ac[4][4][4];
#pragma unroll
  for (int mt = 0; mt < 4; mt++)
#pragma unroll
    for (int nt = 0; nt < 4; nt++)
#pragma unroll
      for (int q = 0; q < 4; q++) ac[mt][nt][q] = 0.f;

  auto issue = [&](int s, int k0) {
    const uint32_t st = smb + s * STG;
    {
      int r = tid >> 2, c = tid & 3;
      size_t go = (size_t)r * KDIM + k0 + c * 8;
      uint32_t so = (uint32_t)(r * 80 + c * 16);
      cp16(st + so, Ab + go);
    }
#pragma unroll
    for (int i = 0; i < 2; i++) {
      int e = i * 512 + tid;
      int r = e >> 2, c = e & 3;
      size_t go = (size_t)r * KDIM + k0 + c * 8;
      uint32_t so = (uint32_t)(r * 80 + c * 16);
      cp16(st + A_MAT + so, Bb + go);
    }
  };

  auto compute = [&](int s) {
    const uint32_t base = smb + s * STG;
#pragma unroll
    for (int ks = 0; ks < 2; ks++) {
      uint32_t af[4][4];
#pragma unroll
      for (int mt = 0; mt < 4; mt++) {
        uint32_t addr = base +
                        (uint32_t)(wm * 64 + mt * 16 + (i4 & 1) * 8 + j8) * 80 +
                        (uint32_t)((i4 >> 1) * 8 + ks * 16) * 2;
        ldsm4(addr, af[mt]);
      }
      uint32_t bf[4][2];
#pragma unroll
      for (int p = 0; p < 2; p++) {
        uint32_t r[4];
        uint32_t addr = base + A_MAT +
                        (uint32_t)(wn * 32 + p * 16 + (i4 >> 1) * 8 + j8) * 80 +
                        (uint32_t)((i4 & 1) * 8 + ks * 16) * 2;
        ldsm4(addr, r);
        bf[2 * p][0] = r[0]; bf[2 * p][1] = r[1];
        bf[2 * p + 1][0] = r[2]; bf[2 * p + 1][1] = r[3];
      }
#pragma unroll
      for (int mt = 0; mt < 4; mt++)
#pragma unroll
        for (int nt = 0; nt < 4; nt++)
          mmaf16(ac[mt][nt], af[mt], bf[nt][0], bf[nt][1]);
    }
  };

  const int KS = KDIM >> 5;  // 64
  issue(0, 0); cp_commit();
  issue(1, 32); cp_commit();

  for (int it = 0; it < KS; it++) {
    const int s = it % 3;
    cp_wait1();
    __syncthreads();
    if (it + 2 < KS) issue((it + 2) % 3, (it + 2) * 32);
    cp_commit();
    compute(s);
  }

  // epilogue
#pragma unroll
  for (int mt = 0; mt < 4; mt++)
#pragma unroll
    for (int nt = 0; nt < 4; nt++) {
      int row = bm * 128 + wm * 64 + mt * 16 + (lane >> 2);
      int col = colbase + wn * 32 + nt * 8 + (lane & 3) * 2;
      if (dest == 0) {
        float* c0 = g_q + (size_t)row * 2048 + col;
        *(float2*)c0 = make_float2(ac[mt][nt][0], ac[mt][nt][1]);
        *(float2*)(c0 + 8 * 2048) = make_float2(ac[mt][nt][2], ac[mt][nt][3]);
      } else if (dest == 1) {
        float* c0 = g_k + (size_t)row * 512 + col;
        *(float2*)c0 = make_float2(ac[mt][nt][0], ac[mt][nt][1]);
        *(float2*)(c0 + 8 * 512) = make_float2(ac[mt][nt][2], ac[mt][nt][3]);
      } else if (dest == 2) {
        size_t i0 = (size_t)row * 512 + col;
        size_t i1 = i0 + 8 * 512;
        __half2 v0 = __float22half2_rn(make_float2(ac[mt][nt][0], ac[mt][nt][1]));
        __half2 v1 = __float22half2_rn(make_float2(ac[mt][nt][2], ac[mt][nt][3]));
        *(__half2*)(g_v16 + i0) = v0;
        *(__half2*)(g_v16 + i1) = v1;
      } else {
        float* c0 = outC + (size_t)row * 2048 + col;
        *(float2*)c0 = make_float2(ac[mt][nt][0], ac[mt][nt][1]);
        *(float2*)(c0 + 8 * 2048) = make_float2(ac[mt][nt][2], ac[mt][nt][3]);
      }
    }
}

// =================== RoPE + RMSNorm -> single fp16 ==========================
__global__ __launch_bounds__(256) void rope_rms_f16(
    const float* __restrict__ x, const float* __restrict__ w,
    __half* __restrict__ y, int nh, int total_warps, float osc) {
  int gw = (blockIdx.x * blockDim.x + threadIdx.x) >> 5;
  if (gw >= total_warps) return;
  int lane = threadIdx.x & 31;
  int token = gw / nh;
  int s = token & (Ss_ - 1);
  const float* p = x + (size_t)gw * HD_;

  const float neg_l2theta_over_half = -13.287712379549449f / 64.f;
  float vals[4];
  float ss = 0.f;
#pragma unroll
  for (int hh = 0; hh < 2; hh++) {
    int d = lane + hh * 32;
    float x1 = p[d];
    float x2 = p[d + 64];
    float invf = exp2f((float)d * neg_l2theta_over_half);
    float ang = (float)s * invf;
    float c, sn;
    sincosf(ang, &sn, &c);
    float o1 = x1 * c - x2 * sn;
    float o2 = x2 * c + x1 * sn;
    vals[hh * 2] = o1;
    vals[hh * 2 + 1] = o2;
    ss += o1 * o1 + o2 * o2;
  }
#pragma unroll
  for (int o = 16; o >= 1; o >>= 1) ss += __shfl_xor_sync(0xffffffffu, ss, o);
  float r = rsqrtf(ss * (1.f / 128.f) + 1e-6f) * osc;
#pragma unroll
  for (int hh = 0; hh < 2; hh++) {
    int d = lane + hh * 32;
    size_t base = (size_t)gw * HD_;
    y[base + d] = __float2half_rn(vals[hh * 2] * r * w[d]);
    y[base + d + 64] = __float2half_rn(vals[hh * 2 + 1] * r * w[d + 64]);
  }
}

// ================ Flash attention (fp16 1-pass mma) =========================
// smem: Q[128], K[64], V[64] rows, pitch 272 -> 69632 B (2 CTAs/SM fit)
#define FPITCH 272
#define FQ 0
#define FK (128 * FPITCH)                 // 34816
#define FV (FK + 64 * FPITCH)             // 52224
#define FA2_SMEM (FV + 64 * FPITCH)       // 69632

__global__ __launch_bounds__(256, 2) void flash_attn_f16() {
  extern __shared__ char sm[];
  const uint32_t smb = smem_u32(sm);
  const int qt = blockIdx.x, h = blockIdx.y, b = blockIdx.z;
  const int kvh = h >> 2;
  const int tid = threadIdx.x, wid = tid >> 5, lane = tid & 31;
  const int i4 = lane >> 3, j8 = lane & 7;
  const int qb = qt * 128;
  const int qwb = qb + wid * 16;

  // ---- prologue: Q (single fp16, pre-scaled) -> smem ----
  {
    const int row = tid >> 1, half = tid & 1;
    const size_t gof = (size_t)(b * Ss_ + qb + row) * (NH_ * HD_) + h * HD_ +
                       half * 64;
    const uint4* sq = (const uint4*)(g_q16 + gof);
    char* dq = sm + FQ + row * FPITCH + half * 128;
#pragma unroll
    for (int q = 0; q < 8; q++) *(uint4*)(dq + q * 16) = sq[q];
  }

  float oa[16][4];
#pragma unroll
  for (int nt = 0; nt < 16; nt++)
#pragma unroll
    for (int q = 0; q < 4; q++) oa[nt][q] = 0.f;
  float m0 = -INFINITY, m1 = -INFINITY, l0 = 0.f, l1 = 0.f;

  const uint32_t qa_off = (uint32_t)(wid * 16 + (i4 & 1) * 8 + j8) * FPITCH +
                          (uint32_t)((i4 >> 1) * 8) * 2;
  const uint32_t kb_row = (uint32_t)((i4 >> 1) * 8 + j8);
  const uint32_t kb_koff = (uint32_t)((i4 & 1) * 8) * 2;
  const uint32_t v_kv = (uint32_t)((i4 & 1) * 8 + j8);
  const uint32_t v_d = (uint32_t)((i4 >> 1) * 8);

  const int krow = tid >> 2, kqtr = tid & 3;

  const int nkv = 2 * qt + 2;
  for (int kvi = 0; kvi < nkv; kvi++) {
    const int kvb = kvi * 64;
    uint4 rk[4], rv[4];
    {
      const size_t gb = (size_t)(b * Ss_ + kvb + krow) * (NKV_ * HD_) +
                        kvh * HD_ + kqtr * 32;
#pragma unroll
      for (int q = 0; q < 4; q++) {
        rk[q] = ((const uint4*)(g_k16 + gb))[q];
        rv[q] = ((const uint4*)(g_v16 + gb))[q];
      }
    }
    __syncthreads();
    {
      char* kd = sm + FK + krow * FPITCH + kqtr * 64;
      char* vd = sm + FV + krow * FPITCH + kqtr * 64;
#pragma unroll
      for (int q = 0; q < 4; q++) {
        *(uint4*)(kd + q * 16) = rk[q];
        *(uint4*)(vd + q * 16) = rv[q];
      }
    }
    __syncthreads();

    if (kvb > qwb + 15) continue;

    float s4[8][4];
#pragma unroll
    for (int j = 0; j < 8; j++)
#pragma unroll
      for (int q = 0; q < 4; q++) s4[j][q] = 0.f;

#pragma unroll
    for (int kt = 0; kt < 8; kt++) {
      uint32_t aQ[4];
      ldsm4(smb + FQ + qa_off + kt * 32, aQ);
#pragma unroll
      for (int p = 0; p < 4; p++) {
        uint32_t rK[4];
        uint32_t ka = (uint32_t)(p * 16) * FPITCH + kb_row * FPITCH + kb_koff +
                      (uint32_t)(kt * 32);
        ldsm4(smb + FK + ka, rK);
        mmaf16(s4[2 * p],     aQ, rK[0], rK[1]);
        mmaf16(s4[2 * p + 1], aQ, rK[2], rK[3]);
      }
    }

    if (kvb + 63 > qwb) {
      const int qr0 = qwb + (lane >> 2), qr1 = qr0 + 8;
      const int kc0 = kvb + (lane & 3) * 2;
#pragma unroll
      for (int j = 0; j < 8; j++) {
        int kv0 = kc0 + j * 8, kv1 = kv0 + 1;
        if (kv0 > qr0) s4[j][0] = -1e30f;
        if (kv1 > qr0) s4[j][1] = -1e30f;
        if (kv0 > qr1) s4[j][2] = -1e30f;
        if (kv1 > qr1) s4[j][3] = -1e30f;
      }
    }

    float mx0 = -1e30f, mx1 = -1e30f;
#pragma unroll
    for (int j = 0; j < 8; j++) {
      mx0 = fmaxf(mx0, fmaxf(s4[j][0], s4[j][1]));
      mx1 = fmaxf(mx1, fmaxf(s4[j][2], s4[j][3]));
    }
    mx0 = fmaxf(mx0, __shfl_xor_sync(0xffffffffu, mx0, 1));
    mx0 = fmaxf(mx0, __shfl_xor_sync(0xffffffffu, mx0, 2));
    mx1 = fmaxf(mx1, __shfl_xor_sync(0xffffffffu, mx1, 1));
    mx1 = fmaxf(mx1, __shfl_xor_sync(0xffffffffu, mx1, 2));
    float mn0 = fmaxf(m0, mx0), mn1 = fmaxf(m1, mx1);
    float al0 = __expf(m0 - mn0), al1 = __expf(m1 - mn1);
    m0 = mn0; m1 = mn1;
    float sum0 = 0.f, sum1 = 0.f;
#pragma unroll
    for (int j = 0; j < 8; j++) {
      s4[j][0] = __expf(s4[j][0] - mn0);
      s4[j][1] = __expf(s4[j][1] - mn0);
      s4[j][2] = __expf(s4[j][2] - mn1);
      s4[j][3] = __expf(s4[j][3] - mn1);
      sum0 += s4[j][0] + s4[j][1];
      sum1 += s4[j][2] + s4[j][3];
    }
    sum0 += __shfl_xor_sync(0xffffffffu, sum0, 1);
    sum0 += __shfl_xor_sync(0xffffffffu, sum0, 2);
    sum1 += __shfl_xor_sync(0xffffffffu, sum1, 1);
    sum1 += __shfl_xor_sync(0xffffffffu, sum1, 2);
    l0 = l0 * al0 + sum0;
    l1 = l1 * al1 + sum1;
#pragma unroll
    for (int nt = 0; nt < 16; nt++) {
      oa[nt][0] *= al0; oa[nt][1] *= al0;
      oa[nt][2] *= al1; oa[nt][3] *= al1;
    }

    // P single fp16, V single
#pragma unroll
    for (int kt = 0; kt < 4; kt++) {
      uint32_t aP[4];
      {
        __half2 p0 = __float22half2_rn(make_float2(s4[2 * kt][0], s4[2 * kt][1]));
        __half2 p1 = __float22half2_rn(make_float2(s4[2 * kt][2], s4[2 * kt][3]));
        __half2 p2 = __float22half2_rn(
            make_float2(s4[2 * kt + 1][0], s4[2 * kt + 1][1]));
        __half2 p3 = __float22half2_rn(
            make_float2(s4[2 * kt + 1][2], s4[2 * kt + 1][3]));
        aP[0] = *reinterpret_cast<uint32_t*>(&p0);
        aP[1] = *reinterpret_cast<uint32_t*>(&p1);
        aP[2] = *reinterpret_cast<uint32_t*>(&p2);
        aP[3] = *reinterpret_cast<uint32_t*>(&p3);
      }
#pragma unroll
      for (int p = 0; p < 8; p++) {
        uint32_t rV[4];
        uint32_t va = (uint32_t)(kt * 16 + v_kv) * FPITCH +
                      (uint32_t)(p * 16 + v_d) * 2;
        ldsm4t(smb + FV + va, rV);
        mmaf16(oa[2 * p],     aP, rV[0], rV[1]);
        mmaf16(oa[2 * p + 1], aP, rV[2], rV[3]);
      }
    }
  }

  // epilogue: attention output as single fp16
  const float inv0 = 1.0f / l0, inv1 = 1.0f / l1;
  const int r0 = qwb + (lane >> 2);
#pragma unroll
  for (int nt = 0; nt < 16; nt++) {
    int col = h * HD_ + nt * 8 + (lane & 3) * 2;
    size_t idx0 = (size_t)(b * Ss_ + r0) * (NH_ * HD_) + col;
    size_t idx1 = (size_t)(b * Ss_ + r0 + 8) * (NH_ * HD_) + col;
    __half2 o0 = __float22half2_rn(make_float2(oa[nt][0] * inv0,
                                               oa[nt][1] * inv0));
    __half2 o1 = __float22half2_rn(make_float2(oa[nt][2] * inv1,
                                               oa[nt][3] * inv1));
    *(__half2*)(g_a16 + idx0) = o0;
    *(__half2*)(g_a16 + idx1) = o1;
  }
}

// ============================ launch ========================================
extern "C" void kernel_launch(void* const* d_in, const int* in_sizes, int n_in,
                              void* d_out, int out_size) {
  const float* hs = (const float*)d_in[0];
  const float* wq = (const float*)d_in[1];
  const float* wk = (const float*)d_in[2];
  const float* wv = (const float*)d_in[3];
  const float* wo = (const float*)d_in[4];
  const float* qw = (const float*)d_in[5];
  const float* kw = (const float*)d_in[6];
  float* out = (float*)d_out;

  void *pq, *pk, *pq16, *pk16;
  cudaGetSymbolAddress(&pq, g_q);
  cudaGetSymbolAddress(&pk, g_k);
  cudaGetSymbolAddress(&pq16, g_q16);
  cudaGetSymbolAddress(&pk16, g_k16);

  cudaFuncSetAttribute(gemm_f16, cudaFuncAttributeMaxDynamicSharedMemorySize,
                       GSM);
  cudaFuncSetAttribute(flash_attn_f16,
                       cudaFuncAttributeMaxDynamicSharedMemorySize, FA2_SMEM);

  // merged prep: fp16 rounding of hs + all weights
  round_all<<<(N4_TOT + 255) / 256, 256>>>(hs, wq, wk, wv, wo);

  // Fused Q+K+V projections (fp16 1-pass)
  gemm_f16<<<dim3(12, MTOK / 128), 512, GSM>>>(0, nullptr);

  // RoPE + RMSNorm (q pre-scaled by 1/sqrt(HD); single fp16 out)
  rope_rms_f16<<<(MTOK * NH_) / 8, 256>>>(
      (const float*)pq, qw, (__half*)pq16, NH_, MTOK * NH_,
      0.08838834764831845f);
  rope_rms_f16<<<(MTOK * NKV_) / 8, 256>>>(
      (const float*)pk, kw, (__half*)pk16, NKV_, MTOK * NKV_, 1.0f);

  flash_attn_f16<<<dim3(Ss_ / 128, NH_, Bb_), 256, FA2_SMEM>>>();

  // Output projection (fp16 1-pass) -> d_out
  gemm_f16<<<dim3(Hh_ / 256, MTOK / 128), 512, GSM>>>(1, out);
}

// round 11
// speedup vs baseline: 6.7253x; 1.0988x over previous
#include <cuda_runtime.h>
#include <cuda_fp16.h>
#include <math.h>
#include <stdint.h>

#define Bb_ 2
#define Ss_ 2048
#define Hh_ 2048
#define NH_ 16
#define NKV_ 4
#define HD_ 128
#define MTOK (Bb_ * Ss_)   // 4096 tokens

// Scratch (allocation-free rule: __device__ globals)
__device__ float g_q[(size_t)MTOK * NH_ * HD_];    // fp32 pre-rope Q
__device__ float g_k[(size_t)MTOK * NKV_ * HD_];   // fp32 pre-rope K
// fp16 GEMM operands (single-rounded)
__device__ __half g_hs16[(size_t)MTOK * Hh_];
__device__ __half g_wq16[(size_t)NH_ * HD_ * Hh_];
__device__ __half g_wk16[(size_t)NKV_ * HD_ * Hh_];
__device__ __half g_wv16[(size_t)NKV_ * HD_ * Hh_];
// attention inputs (fp16, single)
__device__ __half g_q16[(size_t)MTOK * NH_ * HD_];
__device__ __half g_k16[(size_t)MTOK * NKV_ * HD_];
__device__ __half g_v16[(size_t)MTOK * NKV_ * HD_];
// O-proj operands (fp16 1-pass)
__device__ __half g_wo16[(size_t)Hh_ * NH_ * HD_];
__device__ __half g_a16[(size_t)MTOK * NH_ * HD_];

// ============================ helpers =======================================
__device__ __forceinline__ uint32_t smem_u32(const void* p) {
  uint32_t a;
  asm("{ .reg .u64 t; cvta.to.shared.u64 t, %1; cvt.u32.u64 %0, t; }"
      : "=r"(a) : "l"(p));
  return a;
}
__device__ __forceinline__ void cp16(uint32_t dst, const void* src) {
  asm volatile("cp.async.cg.shared.global [%0], [%1], 16;"
               :: "r"(dst), "l"(src));
}
__device__ __forceinline__ void cp_commit() {
  asm volatile("cp.async.commit_group;" ::: "memory");
}
__device__ __forceinline__ void cp_wait1() {
  asm volatile("cp.async.wait_group 1;" ::: "memory");
}
__device__ __forceinline__ void ldsm4(uint32_t addr, uint32_t r[4]) {
  asm volatile("ldmatrix.sync.aligned.m8n8.x4.shared.b16 {%0,%1,%2,%3}, [%4];"
               : "=r"(r[0]), "=r"(r[1]), "=r"(r[2]), "=r"(r[3]) : "r"(addr));
}
__device__ __forceinline__ void ldsm4t(uint32_t addr, uint32_t r[4]) {
  asm volatile(
      "ldmatrix.sync.aligned.m8n8.x4.trans.shared.b16 {%0,%1,%2,%3}, [%4];"
      : "=r"(r[0]), "=r"(r[1]), "=r"(r[2]), "=r"(r[3]) : "r"(addr));
}
__device__ __forceinline__ void mmaf16(float c[4], const uint32_t a[4],
                                       uint32_t b0, uint32_t b1) {
  asm volatile(
      "mma.sync.aligned.m16n8k16.row.col.f32.f16.f16.f32 "
      "{%0,%1,%2,%3}, {%4,%5,%6,%7}, {%8,%9}, {%0,%1,%2,%3};"
      : "+f"(c[0]), "+f"(c[1]), "+f"(c[2]), "+f"(c[3])
      : "r"(a[0]), "r"(a[1]), "r"(a[2]), "r"(a[3]), "r"(b0), "r"(b1));
}

// ============================ prep kernel (merged) ==========================
#define N4_HS (MTOK * Hh_ / 4)            // 2M
#define N4_WQ (NH_ * HD_ * Hh_ / 4)       // 1M
#define N4_WKV (NKV_ * HD_ * Hh_ / 4)     // 256K
#define N4_TOT (N4_HS + N4_WQ + 2 * N4_WKV + N4_WQ)

__global__ __launch_bounds__(256) void round_all(
    const float* __restrict__ hs, const float* __restrict__ wq,
    const float* __restrict__ wk, const float* __restrict__ wv,
    const float* __restrict__ wo) {
  int i = blockIdx.x * blockDim.x + threadIdx.x;
  if (i >= N4_TOT) return;
  const float* src;
  __half* dst;
  int off;
  if (i < N4_HS) {
    src = hs; dst = g_hs16; off = i;
  } else if (i < N4_HS + N4_WQ) {
    src = wq; dst = g_wq16; off = i - N4_HS;
  } else if (i < N4_HS + N4_WQ + N4_WKV) {
    src = wk; dst = g_wk16; off = i - N4_HS - N4_WQ;
  } else if (i < N4_HS + N4_WQ + 2 * N4_WKV) {
    src = wv; dst = g_wv16; off = i - N4_HS - N4_WQ - N4_WKV;
  } else {
    src = wo; dst = g_wo16; off = i - N4_HS - N4_WQ - 2 * N4_WKV;
  }
  float4 v = ((const float4*)src)[off];
  __half2 a = __float22half2_rn(make_float2(v.x, v.y));
  __half2 b = __float22half2_rn(make_float2(v.z, v.w));
  ((uint2*)dst)[off] = make_uint2(*reinterpret_cast<uint32_t*>(&a),
                                  *reinterpret_cast<uint32_t*>(&b));
}

// ============ fp16 1-pass GEMM, cp.async 3-stage, 512 threads ===============
#define A_MAT (128 * 80)            // 10240 B
#define B_MAT (256 * 80)            // 20480 B
#define STG (A_MAT + B_MAT)         // 30720 B
#define GSM (3 * STG)               // 92160 B
#define KDIM 2048

// mode 0: fused QKV (bn<8 Q fp32, 8..9 K fp32, 10..11 V fp16)
// mode 1: O proj (A = g_a16, B = g_wo16, C = outC fp32)
__global__ __launch_bounds__(512, 1) void gemm_f16(int mode, float* outC) {
  extern __shared__ char sm[];
  const uint32_t smb = smem_u32(sm);
  const int tid = threadIdx.x, wid = tid >> 5, lane = tid & 31;
  const int wm = wid & 1, wn = wid >> 1;
  const int bn = blockIdx.x, bm = blockIdx.y;
  const int i4 = lane >> 3, j8 = lane & 7;

  const __half *Ab, *Bb;
  int colbase, dest;  // 0=Q fp32, 1=K fp32, 2=V fp16, 3=out fp32
  if (mode == 0) {
    Ab = g_hs16 + (size_t)(bm * 128) * KDIM;
    if (bn < 8) {
      Bb = g_wq16 + (size_t)(bn * 256) * KDIM;
      colbase = bn * 256; dest = 0;
    } else if (bn < 10) {
      Bb = g_wk16 + (size_t)((bn - 8) * 256) * KDIM;
      colbase = (bn - 8) * 256; dest = 1;
    } else {
      Bb = g_wv16 + (size_t)((bn - 10) * 256) * KDIM;
      colbase = (bn - 10) * 256; dest = 2;
    }
  } else {
    Ab = g_a16 + (size_t)(bm * 128) * KDIM;
    Bb = g_wo16 + (size_t)(bn * 256) * KDIM;
    colbase = bn * 256; dest = 3;
  }

  float ac[4][4][4];
#pragma unroll
  for (int mt = 0; mt < 4; mt++)
#pragma unroll
    for (int nt = 0; nt < 4; nt++)
#pragma unroll
      for (int q = 0; q < 4; q++) ac[mt][nt][q] = 0.f;

  auto issue = [&](int s, int k0) {
    const uint32_t st = smb + s * STG;
    {
      int r = tid >> 2, c = tid & 3;
      size_t go = (size_t)r * KDIM + k0 + c * 8;
      uint32_t so = (uint32_t)(r * 80 + c * 16);
      cp16(st + so, Ab + go);
    }
#pragma unroll
    for (int i = 0; i < 2; i++) {
      int e = i * 512 + tid;
      int r = e >> 2, c = e & 3;
      size_t go = (size_t)r * KDIM + k0 + c * 8;
      uint32_t so = (uint32_t)(r * 80 + c * 16);
      cp16(st + A_MAT + so, Bb + go);
    }
  };

  auto compute = [&](int s) {
    const uint32_t base = smb + s * STG;
#pragma unroll
    for (int ks = 0; ks < 2; ks++) {
      uint32_t af[4][4];
#pragma unroll
      for (int mt = 0; mt < 4; mt++) {
        uint32_t addr = base +
                        (uint32_t)(wm * 64 + mt * 16 + (i4 & 1) * 8 + j8) * 80 +
                        (uint32_t)((i4 >> 1) * 8 + ks * 16) * 2;
        ldsm4(addr, af[mt]);
      }
      uint32_t bf[4][2];
#pragma unroll
      for (int p = 0; p < 2; p++) {
        uint32_t r[4];
        uint32_t addr = base + A_MAT +
                        (uint32_t)(wn * 32 + p * 16 + (i4 >> 1) * 8 + j8) * 80 +
                        (uint32_t)((i4 & 1) * 8 + ks * 16) * 2;
        ldsm4(addr, r);
        bf[2 * p][0] = r[0]; bf[2 * p][1] = r[1];
        bf[2 * p + 1][0] = r[2]; bf[2 * p + 1][1] = r[3];
      }
#pragma unroll
      for (int mt = 0; mt < 4; mt++)
#pragma unroll
        for (int nt = 0; nt < 4; nt++)
          mmaf16(ac[mt][nt], af[mt], bf[nt][0], bf[nt][1]);
    }
  };

  const int KS = KDIM >> 5;  // 64
  issue(0, 0); cp_commit();
  issue(1, 32); cp_commit();

  for (int it = 0; it < KS; it++) {
    const int s = it % 3;
    cp_wait1();
    __syncthreads();
    if (it + 2 < KS) issue((it + 2) % 3, (it + 2) * 32);
    cp_commit();
    compute(s);
  }

  // epilogue
#pragma unroll
  for (int mt = 0; mt < 4; mt++)
#pragma unroll
    for (int nt = 0; nt < 4; nt++) {
      int row = bm * 128 + wm * 64 + mt * 16 + (lane >> 2);
      int col = colbase + wn * 32 + nt * 8 + (lane & 3) * 2;
      if (dest == 0) {
        float* c0 = g_q + (size_t)row * 2048 + col;
        *(float2*)c0 = make_float2(ac[mt][nt][0], ac[mt][nt][1]);
        *(float2*)(c0 + 8 * 2048) = make_float2(ac[mt][nt][2], ac[mt][nt][3]);
      } else if (dest == 1) {
        float* c0 = g_k + (size_t)row * 512 + col;
        *(float2*)c0 = make_float2(ac[mt][nt][0], ac[mt][nt][1]);
        *(float2*)(c0 + 8 * 512) = make_float2(ac[mt][nt][2], ac[mt][nt][3]);
      } else if (dest == 2) {
        size_t i0 = (size_t)row * 512 + col;
        size_t i1 = i0 + 8 * 512;
        __half2 v0 = __float22half2_rn(make_float2(ac[mt][nt][0], ac[mt][nt][1]));
        __half2 v1 = __float22half2_rn(make_float2(ac[mt][nt][2], ac[mt][nt][3]));
        *(__half2*)(g_v16 + i0) = v0;
        *(__half2*)(g_v16 + i1) = v1;
      } else {
        float* c0 = outC + (size_t)row * 2048 + col;
        *(float2*)c0 = make_float2(ac[mt][nt][0], ac[mt][nt][1]);
        *(float2*)(c0 + 8 * 2048) = make_float2(ac[mt][nt][2], ac[mt][nt][3]);
      }
    }
}

// =============== RoPE + RMSNorm -> single fp16 (merged q+k) =================
#define QW_TOT (MTOK * NH_)
#define KW_TOT (MTOK * NKV_)

__global__ __launch_bounds__(256) void rope_rms_f16(
    const float* __restrict__ qw, const float* __restrict__ kw) {
  int gw = (blockIdx.x * blockDim.x + threadIdx.x) >> 5;
  if (gw >= QW_TOT + KW_TOT) return;
  int lane = threadIdx.x & 31;
  const float* x;
  const float* w;
  __half* y;
  float osc;
  int lw, nh;
  if (gw < QW_TOT) {
    lw = gw; nh = NH_; x = g_q; w = qw; y = g_q16;
    osc = 0.08838834764831845f;  // 1/sqrt(128)
  } else {
    lw = gw - QW_TOT; nh = NKV_; x = g_k; w = kw; y = g_k16;
    osc = 1.0f;
  }
  int token = lw / nh;
  int s = token & (Ss_ - 1);
  const float* p = x + (size_t)lw * HD_;

  const float neg_l2theta_over_half = -13.287712379549449f / 64.f;
  float vals[4];
  float ss = 0.f;
#pragma unroll
  for (int hh = 0; hh < 2; hh++) {
    int d = lane + hh * 32;
    float x1 = p[d];
    float x2 = p[d + 64];
    float invf = exp2f((float)d * neg_l2theta_over_half);
    float ang = (float)s * invf;
    float c, sn;
    sincosf(ang, &sn, &c);
    float o1 = x1 * c - x2 * sn;
    float o2 = x2 * c + x1 * sn;
    vals[hh * 2] = o1;
    vals[hh * 2 + 1] = o2;
    ss += o1 * o1 + o2 * o2;
  }
#pragma unroll
  for (int o = 16; o >= 1; o >>= 1) ss += __shfl_xor_sync(0xffffffffu, ss, o);
  float r = rsqrtf(ss * (1.f / 128.f) + 1e-6f) * osc;
#pragma unroll
  for (int hh = 0; hh < 2; hh++) {
    int d = lane + hh * 32;
    size_t base = (size_t)lw * HD_;
    y[base + d] = __float2half_rn(vals[hh * 2] * r * w[d]);
    y[base + d + 64] = __float2half_rn(vals[hh * 2 + 1] * r * w[d + 64]);
  }
}

// ====== Flash attention (fp16 1-pass, paired q-tiles, max-free softmax) =====
// smem: Q[128], K[64], V[64] rows, pitch 272 -> 69632 B (2 CTAs/SM fit)
#define FPITCH 272
#define FQ 0
#define FK (128 * FPITCH)                 // 34816
#define FV (FK + 64 * FPITCH)             // 52224
#define FA2_SMEM (FV + 64 * FPITCH)       // 69632
#define SM_OFF 4.0f                       // softmax exponent offset

__global__ __launch_bounds__(256, 2) void flash_attn_f16() {
  extern __shared__ char sm[];
  const uint32_t smb = smem_u32(sm);
  const int bx = blockIdx.x, h = blockIdx.y, b = blockIdx.z;
  const int kvh = h >> 2;
  const int tid = threadIdx.x, wid = tid >> 5, lane = tid & 31;
  const int i4 = lane >> 3, j8 = lane & 7;

  const uint32_t qa_off = (uint32_t)(wid * 16 + (i4 & 1) * 8 + j8) * FPITCH +
                          (uint32_t)((i4 >> 1) * 8) * 2;
  const uint32_t kb_row = (uint32_t)((i4 >> 1) * 8 + j8);
  const uint32_t kb_koff = (uint32_t)((i4 & 1) * 8) * 2;
  const uint32_t v_kv = (uint32_t)((i4 & 1) * 8 + j8);
  const uint32_t v_d = (uint32_t)((i4 >> 1) * 8);
  const int krow = tid >> 2, kqtr = tid & 3;

#pragma unroll
  for (int ti = 0; ti < 2; ti++) {
    const int qt = ti ? 15 - bx : bx;   // paired tiles: uniform 34 chunks/CTA
    const int qb = qt * 128;
    const int qwb = qb + wid * 16;

    __syncthreads();  // all warps done with previous tile's smem

    // ---- Q (single fp16, pre-scaled) -> smem ----
    {
      const int row = tid >> 1, half = tid & 1;
      const size_t gof = (size_t)(b * Ss_ + qb + row) * (NH_ * HD_) + h * HD_ +
                         half * 64;
      const uint4* sq = (const uint4*)(g_q16 + gof);
      char* dq = sm + FQ + row * FPITCH + half * 128;
#pragma unroll
      for (int q = 0; q < 8; q++) *(uint4*)(dq + q * 16) = sq[q];
    }

    float oa[16][4];
#pragma unroll
    for (int nt = 0; nt < 16; nt++)
#pragma unroll
      for (int q = 0; q < 4; q++) oa[nt][q] = 0.f;
    float l0 = 0.f, l1 = 0.f;

    const int nkv = 2 * qt + 2;
    for (int kvi = 0; kvi < nkv; kvi++) {
      const int kvb = kvi * 64;
      uint4 rk[4], rv[4];
      {
        const size_t gb = (size_t)(b * Ss_ + kvb + krow) * (NKV_ * HD_) +
                          kvh * HD_ + kqtr * 32;
#pragma unroll
        for (int q = 0; q < 4; q++) {
          rk[q] = ((const uint4*)(g_k16 + gb))[q];
          rv[q] = ((const uint4*)(g_v16 + gb))[q];
        }
      }
      __syncthreads();
      {
        char* kd = sm + FK + krow * FPITCH + kqtr * 64;
        char* vd = sm + FV + krow * FPITCH + kqtr * 64;
#pragma unroll
        for (int q = 0; q < 4; q++) {
          *(uint4*)(kd + q * 16) = rk[q];
          *(uint4*)(vd + q * 16) = rv[q];
        }
      }
      __syncthreads();

      if (kvb > qwb + 15) continue;

      float s4[8][4];
#pragma unroll
      for (int j = 0; j < 8; j++)
#pragma unroll
        for (int q = 0; q < 4; q++) s4[j][q] = 0.f;

#pragma unroll
      for (int kt = 0; kt < 8; kt++) {
        uint32_t aQ[4];
        ldsm4(smb + FQ + qa_off + kt * 32, aQ);
#pragma unroll
        for (int p = 0; p < 4; p++) {
          uint32_t rK[4];
          uint32_t ka = (uint32_t)(p * 16) * FPITCH + kb_row * FPITCH +
                        kb_koff + (uint32_t)(kt * 32);
          ldsm4(smb + FK + ka, rK);
          mmaf16(s4[2 * p],     aQ, rK[0], rK[1]);
          mmaf16(s4[2 * p + 1], aQ, rK[2], rK[3]);
        }
      }

      if (kvb + 63 > qwb) {
        const int qr0 = qwb + (lane >> 2), qr1 = qr0 + 8;
        const int kc0 = kvb + (lane & 3) * 2;
#pragma unroll
        for (int j = 0; j < 8; j++) {
          int kv0 = kc0 + j * 8, kv1 = kv0 + 1;
          if (kv0 > qr0) s4[j][0] = -1e30f;
          if (kv1 > qr0) s4[j][1] = -1e30f;
          if (kv0 > qr1) s4[j][2] = -1e30f;
          if (kv1 > qr1) s4[j][3] = -1e30f;
        }
      }

      // max-free softmax: p = exp(s - 4); |s| <= sqrt(128) by Cauchy-Schwarz
      float sum0 = 0.f, sum1 = 0.f;
#pragma unroll
      for (int j = 0; j < 8; j++) {
        s4[j][0] = __expf(s4[j][0] - SM_OFF);
        s4[j][1] = __expf(s4[j][1] - SM_OFF);
        s4[j][2] = __expf(s4[j][2] - SM_OFF);
        s4[j][3] = __expf(s4[j][3] - SM_OFF);
        sum0 += s4[j][0] + s4[j][1];
        sum1 += s4[j][2] + s4[j][3];
      }
      sum0 += __shfl_xor_sync(0xffffffffu, sum0, 1);
      sum0 += __shfl_xor_sync(0xffffffffu, sum0, 2);
      sum1 += __shfl_xor_sync(0xffffffffu, sum1, 1);
      sum1 += __shfl_xor_sync(0xffffffffu, sum1, 2);
      l0 += sum0;
      l1 += sum1;

      // P single fp16, V single
#pragma unroll
      for (int kt = 0; kt < 4; kt++) {
        uint32_t aP[4];
        {
          __half2 p0 = __float22half2_rn(
              make_float2(s4[2 * kt][0], s4[2 * kt][1]));
          __half2 p1 = __float22half2_rn(
              make_float2(s4[2 * kt][2], s4[2 * kt][3]));
          __half2 p2 = __float22half2_rn(
              make_float2(s4[2 * kt + 1][0], s4[2 * kt + 1][1]));
          __half2 p3 = __float22half2_rn(
              make_float2(s4[2 * kt + 1][2], s4[2 * kt + 1][3]));
          aP[0] = *reinterpret_cast<uint32_t*>(&p0);
          aP[1] = *reinterpret_cast<uint32_t*>(&p1);
          aP[2] = *reinterpret_cast<uint32_t*>(&p2);
          aP[3] = *reinterpret_cast<uint32_t*>(&p3);
        }
#pragma unroll
        for (int p = 0; p < 8; p++) {
          uint32_t rV[4];
          uint32_t va = (uint32_t)(kt * 16 + v_kv) * FPITCH +
                        (uint32_t)(p * 16 + v_d) * 2;
          ldsm4t(smb + FV + va, rV);
          mmaf16(oa[2 * p],     aP, rV[0], rV[1]);
          mmaf16(oa[2 * p + 1], aP, rV[2], rV[3]);
        }
      }
    }

    // epilogue: attention output as single fp16
    const float inv0 = 1.0f / l0, inv1 = 1.0f / l1;
    const int r0 = qwb + (lane >> 2);
#pragma unroll
    for (int nt = 0; nt < 16; nt++) {
      int col = h * HD_ + nt * 8 + (lane & 3) * 2;
      size_t idx0 = (size_t)(b * Ss_ + r0) * (NH_ * HD_) + col;
      size_t idx1 = (size_t)(b * Ss_ + r0 + 8) * (NH_ * HD_) + col;
      __half2 o0 = __float22half2_rn(make_float2(oa[nt][0] * inv0,
                                                 oa[nt][1] * inv0));
      __half2 o1 = __float22half2_rn(make_float2(oa[nt][2] * inv1,
                                                 oa[nt][3] * inv1));
      *(__half2*)(g_a16 + idx0) = o0;
      *(__half2*)(g_a16 + idx1) = o1;
    }
  }
}

// ============================ launch ========================================
extern "C" void kernel_launch(void* const* d_in, const int* in_sizes, int n_in,
                              void* d_out, int out_size) {
  const float* hs = (const float*)d_in[0];
  const float* wq = (const float*)d_in[1];
  const float* wk = (const float*)d_in[2];
  const float* wv = (const float*)d_in[3];
  const float* wo = (const float*)d_in[4];
  const float* qw = (const float*)d_in[5];
  const float* kw = (const float*)d_in[6];
  float* out = (float*)d_out;

  cudaFuncSetAttribute(gemm_f16, cudaFuncAttributeMaxDynamicSharedMemorySize,
                       GSM);
  cudaFuncSetAttribute(flash_attn_f16,
                       cudaFuncAttributeMaxDynamicSharedMemorySize, FA2_SMEM);

  // merged prep: fp16 rounding of hs + all weights
  round_all<<<(N4_TOT + 255) / 256, 256>>>(hs, wq, wk, wv, wo);

  // Fused Q+K+V projections (fp16 1-pass)
  gemm_f16<<<dim3(12, MTOK / 128), 512, GSM>>>(0, nullptr);

  // RoPE + RMSNorm (merged q+k; q pre-scaled by 1/sqrt(HD))
  rope_rms_f16<<<((QW_TOT + KW_TOT) * 32 + 255) / 256, 256>>>(qw, kw);

  // Flash attention, paired q-tiles (uniform 34 chunks/CTA, 1 balanced wave)
  flash_attn_f16<<<dim3(8, NH_, Bb_), 256, FA2_SMEM>>>();

  // Output projection (fp16 1-pass) -> d_out
  gemm_f16<<<dim3(Hh_ / 256, MTOK / 128), 512, GSM>>>(1, out);
}